// round 4
// baseline (speedup 1.0000x reference)
#include <cuda_runtime.h>
#include <math.h>
#include <stdint.h>

// Problem constants (fixed by the reference generator)
#define NN   20000
#define DD   512
#define HH   8
#define DHH  64
#define FF   2048
#define LLAY 2
#define EE   320000
#define QKVW 1536   // packed q|k|v row width

// ---------------------------------------------------------------------------
// Scratch (device globals: alloc-free rule)
// ---------------------------------------------------------------------------
__device__ float g_qkv [NN * QKVW];  // packed q|k|v activations
__device__ float g_agg [NN * DD];
__device__ float g_t   [NN * DD];    // attn-out / ff2-out
__device__ float g_x   [NN * DD];    // running activations
__device__ float g_ff  [NN * FF];
__device__ float g_sums[2 * DD];     // batchnorm column sums (sum, sumsq)
__device__ float g_mu  [DD];
__device__ float g_rs  [DD];
__device__ float g_wqkv[LLAY * QKVW * DD];  // packed weights (Wq pre-scaled)
__device__ float g_bqkv[LLAY * QKVW];       // packed bias
// CSR
__device__ int g_cnt [NN + 1];
__device__ int g_off [NN + 1];
__device__ int g_pos [NN];
__device__ int g_esrc[EE];

// ---------------------------------------------------------------------------
// Utility kernels
// ---------------------------------------------------------------------------
__global__ void fill_f(float* __restrict__ p, float v, int n) {
    int i = blockIdx.x * blockDim.x + threadIdx.x;
    if (i < n) p[i] = v;
}
__global__ void fill_i(int* __restrict__ p, int v, int n) {
    int i = blockIdx.x * blockDim.x + threadIdx.x;
    if (i < n) p[i] = v;
}

// ---------------------------------------------------------------------------
// Weight packing:  wout[l][r][c], r<512: Wq*0.125 | r<1024: Wk | else Wv
// ---------------------------------------------------------------------------
__global__ void pack_qkv_w(const float* __restrict__ Wq, const float* __restrict__ Wk,
                           const float* __restrict__ Wv, float* __restrict__ wout)
{
    int idx = blockIdx.x * blockDim.x + threadIdx.x;
    const int total = LLAY * QKVW * DD;
    if (idx >= total) return;
    int l = idx / (QKVW * DD);
    int rem = idx % (QKVW * DD);
    int r = rem / DD, c = rem % DD;
    float val;
    if (r < 512)       val = Wq[(size_t)l * DD * DD + (size_t)r * DD + c] * 0.125f;
    else if (r < 1024) val = Wk[(size_t)l * DD * DD + (size_t)(r - 512) * DD + c];
    else               val = Wv[(size_t)l * DD * DD + (size_t)(r - 1024) * DD + c];
    wout[idx] = val;
}
__global__ void pack_qkv_b(const float* __restrict__ bq, float* __restrict__ bout)
{
    int idx = blockIdx.x * blockDim.x + threadIdx.x;
    if (idx >= LLAY * QKVW) return;
    int l = idx / QKVW, r = idx % QKVW;
    bout[idx] = (r < 512) ? bq[l * DD + r] * 0.125f : 0.f;
}

// ---------------------------------------------------------------------------
// CSR build
// ---------------------------------------------------------------------------
__global__ void csr_hist(const int* __restrict__ tgtI, int* __restrict__ cnt, int E)
{
    int e = blockIdx.x * blockDim.x + threadIdx.x;
    if (e < E) atomicAdd(&cnt[tgtI[e]], 1);
}

// single block, 1024 threads; n <= 32768
__global__ void __launch_bounds__(1024)
csr_scan(const int* __restrict__ cnt, int* __restrict__ off, int* __restrict__ pos, int n)
{
    __shared__ int part[1024];
    const int t = threadIdx.x;
    const int CH = (n + 1023) / 1024;   // 20 for n=20000
    int vals[32];
    int base = t * CH;
    int local = 0;
    for (int i = 0; i < CH; i++) {
        int e = base + i;
        int v = (e < n) ? cnt[e] : 0;
        vals[i] = v;
        local += v;
    }
    part[t] = local;
    __syncthreads();
    for (int d = 1; d < 1024; d <<= 1) {
        int v = (t >= d) ? part[t - d] : 0;
        __syncthreads();
        part[t] += v;
        __syncthreads();
    }
    int run = (t > 0) ? part[t - 1] : 0;
    for (int i = 0; i < CH; i++) {
        int e = base + i;
        if (e < n) { off[e] = run; pos[e] = run; run += vals[i]; }
    }
    if (t == 1023) off[n] = part[1023];
}

__global__ void csr_scatter(const int* __restrict__ srcI, const int* __restrict__ tgtI,
                            int* __restrict__ pos, int* __restrict__ esrc, int E)
{
    int e = blockIdx.x * blockDim.x + threadIdx.x;
    if (e >= E) return;
    int slot = atomicAdd(&pos[tgtI[e]], 1);
    esrc[slot] = srcI[e];
}

// ---------------------------------------------------------------------------
// Attention over CSR: one warp per target node, single-pass online softmax.
// qkv row layout: [q(512) | k(512) | v(512)], lane owns 16 contiguous dims,
// lane's head = lane>>2 (16 dims always within one 64-dim head).
// ---------------------------------------------------------------------------
__global__ void __launch_bounds__(256)
attn_csr(const float* __restrict__ qkv, const int* __restrict__ off,
         const int* __restrict__ esrc, float* __restrict__ agg, int n)
{
    int node = (blockIdx.x * blockDim.x + threadIdx.x) >> 5;
    int lane = threadIdx.x & 31;
    if (node >= n) return;
    const int start = off[node];
    const int end   = off[node + 1];

    const float4* qr = (const float4*)(qkv + (size_t)node * QKVW) + lane * 4;
    float4 q0 = qr[0], q1 = qr[1], q2 = qr[2], q3 = qr[3];

    float hmax = -INFINITY, hsum = 0.f;
    float acc[16];
#pragma unroll
    for (int i = 0; i < 16; i++) acc[i] = 0.f;

    for (int base = start; base < end; base += 32) {
        int idx = base + lane;
        int myE = (idx < end) ? esrc[idx] : 0;
        int cnt = min(32, end - base);
        for (int i = 0; i < cnt; i++) {
            int sn = __shfl_sync(0xffffffffu, myE, i);
            const float4* kr = (const float4*)(qkv + (size_t)sn * QKVW + 512)  + lane * 4;
            const float4* vr = (const float4*)(qkv + (size_t)sn * QKVW + 1024) + lane * 4;
            float4 k0 = kr[0], k1 = kr[1], k2 = kr[2], k3 = kr[3];
            float4 v0 = vr[0], v1 = vr[1], v2 = vr[2], v3 = vr[3];

            float d = q0.x*k0.x + q0.y*k0.y + q0.z*k0.z + q0.w*k0.w;
            d += q1.x*k1.x + q1.y*k1.y + q1.z*k1.z + q1.w*k1.w;
            d += q2.x*k2.x + q2.y*k2.y + q2.z*k2.z + q2.w*k2.w;
            d += q3.x*k3.x + q3.y*k3.y + q3.z*k3.z + q3.w*k3.w;
            d += __shfl_xor_sync(0xffffffffu, d, 1);
            d += __shfl_xor_sync(0xffffffffu, d, 2);

            float nm = fmaxf(hmax, d);
            float sc = expf(hmax - nm);   // 1 if max unchanged; 0 on first edge
            float w  = expf(d - nm);
            hmax = nm;
            hsum = hsum * sc + w;
            acc[0]  = acc[0] *sc + w*v0.x; acc[1]  = acc[1] *sc + w*v0.y;
            acc[2]  = acc[2] *sc + w*v0.z; acc[3]  = acc[3] *sc + w*v0.w;
            acc[4]  = acc[4] *sc + w*v1.x; acc[5]  = acc[5] *sc + w*v1.y;
            acc[6]  = acc[6] *sc + w*v1.z; acc[7]  = acc[7] *sc + w*v1.w;
            acc[8]  = acc[8] *sc + w*v2.x; acc[9]  = acc[9] *sc + w*v2.y;
            acc[10] = acc[10]*sc + w*v2.z; acc[11] = acc[11]*sc + w*v2.w;
            acc[12] = acc[12]*sc + w*v3.x; acc[13] = acc[13]*sc + w*v3.y;
            acc[14] = acc[14]*sc + w*v3.z; acc[15] = acc[15]*sc + w*v3.w;
        }
    }

    float inv = 1.f / (hsum + 1e-16f);
    float4* ag = (float4*)(agg + (size_t)node * DD) + lane * 4;
#pragma unroll
    for (int i = 0; i < 4; i++)
        ag[i] = make_float4(acc[i*4+0]*inv, acc[i*4+1]*inv, acc[i*4+2]*inv, acc[i*4+3]*inv);
}

// ---------------------------------------------------------------------------
// TF32 tensor-core GEMM: C[M,Nout] = act((A[M,K] @ W[Nout,K]^T + bias)*scale)
// Block tile 128x128, BK=32, 256 threads (8 warps, 2x4), warp tile 64x32.
// Double-buffered smem (dynamic, 73.7 KB), one __syncthreads per k-tile.
// ---------------------------------------------------------------------------
__device__ __forceinline__ uint32_t f2tf(float x) {
    uint32_t r;
    asm("cvt.rna.tf32.f32 %0, %1;" : "=r"(r) : "f"(x));
    return r;
}

#define STAGE_F (128 * 36)

template <bool RELU>
__global__ void __launch_bounds__(256)
gemm_tf32(const float* __restrict__ A, const float* __restrict__ W,
          const float* __restrict__ bias, float* __restrict__ C,
          int M, int K, int Nout, float scale)
{
    extern __shared__ float smem[];
    float* AsBase = smem;                  // [2][128][36]
    float* BsBase = smem + 2 * STAGE_F;    // [2][128][36]

    const int tid  = threadIdx.x;
    const int lane = tid & 31;
    const int warp = tid >> 5;
    const int wm   = warp >> 2;     // 0..1
    const int wn   = warp & 3;      // 0..3
    const int g    = lane >> 2;     // 0..7
    const int c    = lane & 3;      // 0..3
    const int rowBase = blockIdx.y * 128;
    const int colBase = blockIdx.x * 128;

    float acc[4][4][4];
#pragma unroll
    for (int mt = 0; mt < 4; mt++)
#pragma unroll
        for (int nt = 0; nt < 4; nt++)
#pragma unroll
            for (int i = 0; i < 4; i++) acc[mt][nt][i] = 0.f;

    float4 aR[4], bR[4];

    auto loadTiles = [&](int k0) {
#pragma unroll
        for (int i = 0; i < 4; i++) {
            int li = tid + i * 256;       // 0..1023 float4 slots
            int r  = li >> 3;             // 0..127
            int q  = li & 7;              // 0..7 (quad of 4 k's)
            int ar = rowBase + r;
            aR[i] = (ar < M) ? *(const float4*)(A + (size_t)ar * K + k0 + q * 4)
                             : make_float4(0.f, 0.f, 0.f, 0.f);
            bR[i] = *(const float4*)(W + (size_t)(colBase + r) * K + k0 + q * 4);
        }
    };

    auto storeTiles = [&](int st) {
        float* As = AsBase + st * STAGE_F;
        float* Bs = BsBase + st * STAGE_F;
#pragma unroll
        for (int i = 0; i < 4; i++) {
            int li = tid + i * 256;
            int r  = li >> 3;
            int q  = li & 7;
            float4 av, bv;
            av.x = __uint_as_float(f2tf(aR[i].x));
            av.y = __uint_as_float(f2tf(aR[i].y));
            av.z = __uint_as_float(f2tf(aR[i].z));
            av.w = __uint_as_float(f2tf(aR[i].w));
            bv.x = __uint_as_float(f2tf(bR[i].x));
            bv.y = __uint_as_float(f2tf(bR[i].y));
            bv.z = __uint_as_float(f2tf(bR[i].z));
            bv.w = __uint_as_float(f2tf(bR[i].w));
            *(float4*)&As[r * 36 + q * 4] = av;
            *(float4*)&Bs[r * 36 + q * 4] = bv;
        }
    };

    loadTiles(0);
    storeTiles(0);
    __syncthreads();

    const int nIter = K >> 5;

    for (int kt = 0; kt < nIter; kt++) {
        if (kt + 1 < nIter) loadTiles((kt + 1) << 5);

        const float* As = AsBase + (kt & 1) * STAGE_F;
        const float* Bs = BsBase + (kt & 1) * STAGE_F;

#pragma unroll
        for (int ks = 0; ks < 4; ks++) {
            uint32_t af[4][4];
            uint32_t bf[4][2];
#pragma unroll
            for (int mt = 0; mt < 4; mt++) {
                int r0 = wm * 64 + mt * 16 + g;
                af[mt][0] = __float_as_uint(As[(r0    ) * 36 + ks * 8 + c    ]);
                af[mt][1] = __float_as_uint(As[(r0 + 8) * 36 + ks * 8 + c    ]);
                af[mt][2] = __float_as_uint(As[(r0    ) * 36 + ks * 8 + c + 4]);
                af[mt][3] = __float_as_uint(As[(r0 + 8) * 36 + ks * 8 + c + 4]);
            }
#pragma unroll
            for (int nt = 0; nt < 4; nt++) {
                int n0 = wn * 32 + nt * 8 + g;
                bf[nt][0] = __float_as_uint(Bs[n0 * 36 + ks * 8 + c    ]);
                bf[nt][1] = __float_as_uint(Bs[n0 * 36 + ks * 8 + c + 4]);
            }
#pragma unroll
            for (int mt = 0; mt < 4; mt++)
#pragma unroll
                for (int nt = 0; nt < 4; nt++)
                    asm volatile(
                        "mma.sync.aligned.m16n8k8.row.col.f32.tf32.tf32.f32 "
                        "{%0,%1,%2,%3}, {%4,%5,%6,%7}, {%8,%9}, {%0,%1,%2,%3};"
                        : "+f"(acc[mt][nt][0]), "+f"(acc[mt][nt][1]),
                          "+f"(acc[mt][nt][2]), "+f"(acc[mt][nt][3])
                        : "r"(af[mt][0]), "r"(af[mt][1]),
                          "r"(af[mt][2]), "r"(af[mt][3]),
                          "r"(bf[nt][0]), "r"(bf[nt][1]));
        }

        if (kt + 1 < nIter) {
            storeTiles((kt + 1) & 1);
            __syncthreads();
        }
    }

    // Epilogue: bias, scale, relu, guarded float2 stores
#pragma unroll
    for (int mt = 0; mt < 4; mt++) {
        int r0 = rowBase + wm * 64 + mt * 16 + g;
        int r1 = r0 + 8;
#pragma unroll
        for (int nt = 0; nt < 4; nt++) {
            int col = colBase + wn * 32 + nt * 8 + c * 2;
            float bx = 0.f, by = 0.f;
            if (bias) { float2 bb = *(const float2*)(bias + col); bx = bb.x; by = bb.y; }
            float v0 = (acc[mt][nt][0] + bx) * scale;
            float v1 = (acc[mt][nt][1] + by) * scale;
            float v2 = (acc[mt][nt][2] + bx) * scale;
            float v3 = (acc[mt][nt][3] + by) * scale;
            if (RELU) {
                v0 = fmaxf(v0, 0.f); v1 = fmaxf(v1, 0.f);
                v2 = fmaxf(v2, 0.f); v3 = fmaxf(v3, 0.f);
            }
            if (r0 < M) *(float2*)(C + (size_t)r0 * Nout + col) = make_float2(v0, v1);
            if (r1 < M) *(float2*)(C + (size_t)r1 * Nout + col) = make_float2(v2, v3);
        }
    }
}

#define GEMM_SMEM (4 * STAGE_F * (int)sizeof(float))   // 73728 bytes

// ---------------------------------------------------------------------------
// BatchNorm over node dimension on z = a + b (residual fused)
// ---------------------------------------------------------------------------
__global__ void bn_stats(const float* __restrict__ a, const float* __restrict__ b,
                         float* __restrict__ sums, int n)
{
    int j = threadIdx.x;   // 512 threads = one per feature
    float sum = 0.f, sq = 0.f;
    for (int i = blockIdx.x; i < n; i += gridDim.x) {
        float z = a[(size_t)i * DD + j] + b[(size_t)i * DD + j];
        sum += z; sq += z * z;
    }
    atomicAdd(&sums[j], sum);
    atomicAdd(&sums[DD + j], sq);
}

__global__ void bn_finalize(const float* __restrict__ sums,
                            float* __restrict__ mu, float* __restrict__ rs, float invn)
{
    int j = threadIdx.x;
    float m = sums[j] * invn;
    float var = sums[DD + j] * invn - m * m;
    mu[j] = m;
    rs[j] = rsqrtf(var + 1e-5f);
}

__global__ void bn_apply(const float* __restrict__ a, const float* __restrict__ b,
                         const float* __restrict__ mu, const float* __restrict__ rs,
                         const float* __restrict__ g, const float* __restrict__ beta,
                         float* __restrict__ out, int n)
{
    int idx = blockIdx.x * blockDim.x + threadIdx.x;
    if (idx >= n * DD) return;
    int j = idx & (DD - 1);
    float z = a[idx] + b[idx];
    out[idx] = (z - mu[j]) * rs[j] * g[j] + beta[j];
}

// ---------------------------------------------------------------------------
// Final per-row LayerNorm  (128 threads/row, 4 floats each)
// ---------------------------------------------------------------------------
__global__ void layernorm_k(const float* __restrict__ x, const float* __restrict__ g,
                            const float* __restrict__ b, float* __restrict__ out)
{
    int row = blockIdx.x;
    int t = threadIdx.x;
    const float4* xr = (const float4*)(x + (size_t)row * DD);
    float4 v = xr[t];
    float sum = v.x + v.y + v.z + v.w;
    float sq  = v.x * v.x + v.y * v.y + v.z * v.z + v.w * v.w;

#pragma unroll
    for (int o = 16; o > 0; o >>= 1) {
        sum += __shfl_xor_sync(0xffffffffu, sum, o);
        sq  += __shfl_xor_sync(0xffffffffu, sq, o);
    }
    __shared__ float sa[4], sb[4];
    int w = t >> 5, l = t & 31;
    if (l == 0) { sa[w] = sum; sb[w] = sq; }
    __syncthreads();
    sum = sa[0] + sa[1] + sa[2] + sa[3];
    sq  = sb[0] + sb[1] + sb[2] + sb[3];

    float mu = sum * (1.f / DD);
    float var = sq * (1.f / DD) - mu * mu;
    float rs = rsqrtf(var + 1e-5f);

    const float4* g4 = (const float4*)g;
    const float4* b4 = (const float4*)b;
    float4 gg = g4[t], bb = b4[t];
    float4 o;
    o.x = (v.x - mu) * rs * gg.x + bb.x;
    o.y = (v.y - mu) * rs * gg.y + bb.y;
    o.z = (v.z - mu) * rs * gg.z + bb.z;
    o.w = (v.w - mu) * rs * gg.w + bb.w;
    *(float4*)(out + (size_t)row * DD + t * 4) = o;
}

// ---------------------------------------------------------------------------
// Orchestration
// ---------------------------------------------------------------------------
extern "C" void kernel_launch(void* const* d_in, const int* in_sizes, int n_in,
                              void* d_out, int out_size)
{
    const float* src = (const float*)d_in[0];
    const int*   ei  = (const int*)  d_in[1];
    const float* Wq  = (const float*)d_in[2];
    const float* bq  = (const float*)d_in[3];
    const float* Wk  = (const float*)d_in[4];
    const float* Wv  = (const float*)d_in[5];
    const float* Wo  = (const float*)d_in[6];
    const float* bo  = (const float*)d_in[7];
    const float* W1  = (const float*)d_in[8];
    const float* b1  = (const float*)d_in[9];
    const float* W2  = (const float*)d_in[10];
    const float* b2  = (const float*)d_in[11];
    const float* g1  = (const float*)d_in[12];
    const float* be1 = (const float*)d_in[13];
    const float* g2  = (const float*)d_in[14];
    const float* be2 = (const float*)d_in[15];
    const float* lng = (const float*)d_in[16];
    const float* lnb = (const float*)d_in[17];
    float* outp = (float*)d_out;

    const int n = in_sizes[0] / DD;
    const int E = in_sizes[1] / 2;
    const int* srcI = ei;
    const int* tgtI = ei + E;

    float *qkv, *agg, *tb, *x, *ff, *sums, *mu, *rs, *wqkv, *bqkv;
    int *cnt, *off, *pos, *esrc;
    cudaGetSymbolAddress((void**)&qkv,  g_qkv);
    cudaGetSymbolAddress((void**)&agg,  g_agg);
    cudaGetSymbolAddress((void**)&tb,   g_t);
    cudaGetSymbolAddress((void**)&x,    g_x);
    cudaGetSymbolAddress((void**)&ff,   g_ff);
    cudaGetSymbolAddress((void**)&sums, g_sums);
    cudaGetSymbolAddress((void**)&mu,   g_mu);
    cudaGetSymbolAddress((void**)&rs,   g_rs);
    cudaGetSymbolAddress((void**)&wqkv, g_wqkv);
    cudaGetSymbolAddress((void**)&bqkv, g_bqkv);
    cudaGetSymbolAddress((void**)&cnt,  g_cnt);
    cudaGetSymbolAddress((void**)&off,  g_off);
    cudaGetSymbolAddress((void**)&pos,  g_pos);
    cudaGetSymbolAddress((void**)&esrc, g_esrc);

    // raise dynamic smem limit for the GEMM (idempotent host calls)
    cudaFuncSetAttribute((const void*)gemm_tf32<false>,
                         cudaFuncAttributeMaxDynamicSharedMemorySize, GEMM_SMEM);
    cudaFuncSetAttribute((const void*)gemm_tf32<true>,
                         cudaFuncAttributeMaxDynamicSharedMemorySize, GEMM_SMEM);

    const dim3 gQKV(QKVW / 128, (n + 127) / 128);
    const dim3 gD(DD / 128, (n + 127) / 128);
    const dim3 gF(FF / 128, (n + 127) / 128);
    const int nDblocks = (n * DD + 255) / 256;

    // ---- weight packing (per launch, deterministic) ----
    pack_qkv_w<<<(LLAY * QKVW * DD + 255) / 256, 256>>>(Wq, Wk, Wv, wqkv);
    pack_qkv_b<<<(LLAY * QKVW + 255) / 256, 256>>>(bq, bqkv);

    // ---- CSR build (edge structure shared by both layers) ----
    fill_i<<<(n + 1 + 255) / 256, 256>>>(cnt, 0, n + 1);
    csr_hist<<<(E + 255) / 256, 256>>>(tgtI, cnt, E);
    csr_scan<<<1, 1024>>>(cnt, off, pos, n);
    csr_scatter<<<(E + 255) / 256, 256>>>(srcI, tgtI, pos, esrc, E);

    const float* xin = src;

    for (int l = 0; l < LLAY; l++) {
        const float* Wol = Wo + (size_t)l * DD * DD;
        const float* W1l = W1 + (size_t)l * FF * DD;
        const float* W2l = W2 + (size_t)l * DD * FF;

        // fused q|k|v projection (q already pre-scaled in packed weights)
        gemm_tf32<false><<<gQKV, 256, GEMM_SMEM>>>(xin, wqkv + (size_t)l * QKVW * DD,
                                                   bqkv + l * QKVW, qkv, n, DD, QKVW, 1.f);

        // attention over CSR (single pass, no atomics)
        attn_csr<<<(n * 32 + 255) / 256, 256>>>(qkv, off, esrc, agg, n);

        // output projection
        gemm_tf32<false><<<gD, 256, GEMM_SMEM>>>(agg, Wol, bo + l * DD, tb, n, DD, DD, 1.f);

        // batchnorm 1 (residual xin + tb)
        fill_f<<<(2 * DD + 255) / 256, 256>>>(sums, 0.f, 2 * DD);
        bn_stats<<<256, DD>>>(xin, tb, sums, n);
        bn_finalize<<<1, DD>>>(sums, mu, rs, 1.f / (float)n);
        bn_apply<<<nDblocks, 256>>>(xin, tb, mu, rs, g1 + l * DD, be1 + l * DD, x, n);

        // feedforward
        gemm_tf32<true ><<<gF, 256, GEMM_SMEM>>>(x, W1l, b1 + l * FF, ff, n, DD, FF, 1.f);
        gemm_tf32<false><<<gD, 256, GEMM_SMEM>>>(ff, W2l, b2 + l * DD, tb, n, FF, DD, 1.f);

        // batchnorm 2 (residual x + tb), in-place on x
        fill_f<<<(2 * DD + 255) / 256, 256>>>(sums, 0.f, 2 * DD);
        bn_stats<<<256, DD>>>(x, tb, sums, n);
        bn_finalize<<<1, DD>>>(sums, mu, rs, 1.f / (float)n);
        bn_apply<<<nDblocks, 256>>>(x, tb, mu, rs, g2 + l * DD, be2 + l * DD, x, n);

        xin = x;
    }

    // final layernorm -> output
    layernorm_k<<<n, 128>>>(x, lng, lnb, outp);
}

// round 6
// speedup vs baseline: 1.0388x; 1.0388x over previous
#include <cuda_runtime.h>
#include <math.h>
#include <stdint.h>

// Problem constants (fixed by the reference generator)
#define NN   20000
#define DD   512
#define HH   8
#define DHH  64
#define FF   2048
#define LLAY 2
#define EE   320000
#define QKVW 1536   // packed q|k|v projection width

// ---------------------------------------------------------------------------
// Scratch (device globals: alloc-free rule)
// ---------------------------------------------------------------------------
__device__ float g_qb  [NN * DD];        // q rows (read once per node)
__device__ float g_kv  [NN * 2 * DD];    // compact k|v rows (gather working set)
__device__ float g_agg [NN * DD];
__device__ float g_t   [NN * DD];
__device__ float g_x   [NN * DD];
__device__ float g_ff  [NN * FF];
__device__ float g_p   [EE * HH];
__device__ float g_sums[2 * DD];
__device__ float g_mu  [DD];
__device__ float g_rs  [DD];
__device__ float g_wqkv[LLAY * QKVW * DD];
__device__ float g_bqkv[LLAY * QKVW];
__device__ int g_cnt [NN + 1];
__device__ int g_off [NN + 1];
__device__ int g_pos [NN];
__device__ int g_esrc[EE];

// ---------------------------------------------------------------------------
// Utility kernels
// ---------------------------------------------------------------------------
__global__ void fill_f(float* __restrict__ p, float v, int n) {
    int i = blockIdx.x * blockDim.x + threadIdx.x;
    if (i < n) p[i] = v;
}
__global__ void fill_i(int* __restrict__ p, int v, int n) {
    int i = blockIdx.x * blockDim.x + threadIdx.x;
    if (i < n) p[i] = v;
}

// ---------------------------------------------------------------------------
// Weight packing:  wout[l][r][c], r<512: Wq*0.125 | r<1024: Wk | else Wv
// ---------------------------------------------------------------------------
__global__ void pack_qkv_w(const float* __restrict__ Wq, const float* __restrict__ Wk,
                           const float* __restrict__ Wv, float* __restrict__ wout)
{
    int idx = blockIdx.x * blockDim.x + threadIdx.x;
    const int total = LLAY * QKVW * DD;
    if (idx >= total) return;
    int l = idx / (QKVW * DD);
    int rem = idx % (QKVW * DD);
    int r = rem / DD, c = rem % DD;
    float val;
    if (r < 512)       val = Wq[(size_t)l * DD * DD + (size_t)r * DD + c] * 0.125f;
    else if (r < 1024) val = Wk[(size_t)l * DD * DD + (size_t)(r - 512) * DD + c];
    else               val = Wv[(size_t)l * DD * DD + (size_t)(r - 1024) * DD + c];
    wout[idx] = val;
}
__global__ void pack_qkv_b(const float* __restrict__ bq, float* __restrict__ bout)
{
    int idx = blockIdx.x * blockDim.x + threadIdx.x;
    if (idx >= LLAY * QKVW) return;
    int l = idx / QKVW, r = idx % QKVW;
    bout[idx] = (r < 512) ? bq[l * DD + r] * 0.125f : 0.f;
}

// ---------------------------------------------------------------------------
// TF32 tensor-core GEMM (mma.sync HMMA path — tcgen05 PTX is gated off in
// this toolchain's .target sm_103).
// C = act(A[M,K] @ W[Nout,K]^T + bias). If split>0, output columns
// [0,split) go to Cq (row stride split) and [split,Nout) to Ckv
// (row stride Nout-split). Block tile 128x128, BK=32, 8 warps.
// ---------------------------------------------------------------------------
__device__ __forceinline__ uint32_t f2tf(float x) {
    uint32_t r;
    asm("cvt.rna.tf32.f32 %0, %1;" : "=r"(r) : "f"(x));
    return r;
}

template <bool RELU>
__global__ void __launch_bounds__(256, 1)
gemm_tf32(const float* __restrict__ A, const float* __restrict__ W,
          const float* __restrict__ bias, float* __restrict__ Cq,
          float* __restrict__ Ckv, int M, int K, int Nout, int split)
{
    __shared__ float As[128][36];   // [m][k] padded: frag loads conflict-free
    __shared__ float Bs[128][36];   // [n][k]

    const int tid  = threadIdx.x;
    const int lane = tid & 31;
    const int warp = tid >> 5;
    const int wm   = warp >> 2;     // 0..1
    const int wn   = warp & 3;      // 0..3
    const int g    = lane >> 2;     // 0..7
    const int c    = lane & 3;      // 0..3
    const int rowBase = blockIdx.y * 128;
    const int colBase = blockIdx.x * 128;

    // output routing (whole 128-col block lands in one buffer: split%128==0)
    float* Cb;
    int NoutB, colB;
    if (split > 0 && colBase >= split) {
        Cb = Ckv; NoutB = Nout - split; colB = colBase - split;
    } else if (split > 0) {
        Cb = Cq;  NoutB = split;        colB = colBase;
    } else {
        Cb = Cq;  NoutB = Nout;         colB = colBase;
    }

    float acc[4][4][4];
#pragma unroll
    for (int mt = 0; mt < 4; mt++)
#pragma unroll
        for (int nt = 0; nt < 4; nt++)
#pragma unroll
            for (int i = 0; i < 4; i++) acc[mt][nt][i] = 0.f;

    float4 aR[4], bR[4];

    auto loadTiles = [&](int k0) {
#pragma unroll
        for (int i = 0; i < 4; i++) {
            int li = tid + i * 256;       // 0..1023 float4 slots
            int r  = li >> 3;             // 0..127
            int q  = li & 7;              // 0..7 (quad of 4 k's)
            int ar = rowBase + r;
            aR[i] = (ar < M) ? *(const float4*)(A + (size_t)ar * K + k0 + q * 4)
                             : make_float4(0.f, 0.f, 0.f, 0.f);
            bR[i] = *(const float4*)(W + (size_t)(colBase + r) * K + k0 + q * 4);
        }
    };

    auto storeTiles = [&]() {
#pragma unroll
        for (int i = 0; i < 4; i++) {
            int li = tid + i * 256;
            int r  = li >> 3;
            int q  = li & 7;
            float4 av, bv;
            av.x = __uint_as_float(f2tf(aR[i].x));
            av.y = __uint_as_float(f2tf(aR[i].y));
            av.z = __uint_as_float(f2tf(aR[i].z));
            av.w = __uint_as_float(f2tf(aR[i].w));
            bv.x = __uint_as_float(f2tf(bR[i].x));
            bv.y = __uint_as_float(f2tf(bR[i].y));
            bv.z = __uint_as_float(f2tf(bR[i].z));
            bv.w = __uint_as_float(f2tf(bR[i].w));
            *(float4*)&As[r][q * 4] = av;
            *(float4*)&Bs[r][q * 4] = bv;
        }
    };

    loadTiles(0);
    const int nIter = K >> 5;

    for (int kt = 0; kt < nIter; kt++) {
        __syncthreads();
        storeTiles();
        __syncthreads();
        if (kt + 1 < nIter) loadTiles((kt + 1) << 5);

#pragma unroll
        for (int ks = 0; ks < 4; ks++) {
            uint32_t af[4][4];
            uint32_t bf[4][2];
#pragma unroll
            for (int mt = 0; mt < 4; mt++) {
                int r0 = wm * 64 + mt * 16 + g;
                af[mt][0] = __float_as_uint(As[r0    ][ks * 8 + c    ]);
                af[mt][1] = __float_as_uint(As[r0 + 8][ks * 8 + c    ]);
                af[mt][2] = __float_as_uint(As[r0    ][ks * 8 + c + 4]);
                af[mt][3] = __float_as_uint(As[r0 + 8][ks * 8 + c + 4]);
            }
#pragma unroll
            for (int nt = 0; nt < 4; nt++) {
                int n0 = wn * 32 + nt * 8 + g;
                bf[nt][0] = __float_as_uint(Bs[n0][ks * 8 + c    ]);
                bf[nt][1] = __float_as_uint(Bs[n0][ks * 8 + c + 4]);
            }
#pragma unroll
            for (int mt = 0; mt < 4; mt++)
#pragma unroll
                for (int nt = 0; nt < 4; nt++)
                    asm volatile(
                        "mma.sync.aligned.m16n8k8.row.col.f32.tf32.tf32.f32 "
                        "{%0,%1,%2,%3}, {%4,%5,%6,%7}, {%8,%9}, {%0,%1,%2,%3};"
                        : "+f"(acc[mt][nt][0]), "+f"(acc[mt][nt][1]),
                          "+f"(acc[mt][nt][2]), "+f"(acc[mt][nt][3])
                        : "r"(af[mt][0]), "r"(af[mt][1]),
                          "r"(af[mt][2]), "r"(af[mt][3]),
                          "r"(bf[nt][0]), "r"(bf[nt][1]));
        }
    }

    // Epilogue: bias, relu, guarded float2 stores with split routing
#pragma unroll
    for (int mt = 0; mt < 4; mt++) {
        int r0 = rowBase + wm * 64 + mt * 16 + g;
        int r1 = r0 + 8;
#pragma unroll
        for (int nt = 0; nt < 4; nt++) {
            int colRel = wn * 32 + nt * 8 + c * 2;
            float2 bb = *(const float2*)(bias + colBase + colRel);
            float v0 = acc[mt][nt][0] + bb.x;
            float v1 = acc[mt][nt][1] + bb.y;
            float v2 = acc[mt][nt][2] + bb.x;
            float v3 = acc[mt][nt][3] + bb.y;
            if (RELU) {
                v0 = fmaxf(v0, 0.f); v1 = fmaxf(v1, 0.f);
                v2 = fmaxf(v2, 0.f); v3 = fmaxf(v3, 0.f);
            }
            int col = colB + colRel;
            if (r0 < M) *(float2*)(Cb + (size_t)r0 * NoutB + col) = make_float2(v0, v1);
            if (r1 < M) *(float2*)(Cb + (size_t)r1 * NoutB + col) = make_float2(v2, v3);
        }
    }
}

// ---------------------------------------------------------------------------
// CSR build
// ---------------------------------------------------------------------------
__global__ void csr_hist(const int* __restrict__ tgtI, int* __restrict__ cnt, int E)
{
    int e = blockIdx.x * blockDim.x + threadIdx.x;
    if (e < E) atomicAdd(&cnt[tgtI[e]], 1);
}

__global__ void __launch_bounds__(1024)
csr_scan(const int* __restrict__ cnt, int* __restrict__ off, int* __restrict__ pos, int n)
{
    __shared__ int part[1024];
    const int t = threadIdx.x;
    const int CH = (n + 1023) / 1024;
    int vals[32];
    int base = t * CH;
    int local = 0;
    for (int i = 0; i < CH; i++) {
        int e = base + i;
        int v = (e < n) ? cnt[e] : 0;
        vals[i] = v;
        local += v;
    }
    part[t] = local;
    __syncthreads();
    for (int d = 1; d < 1024; d <<= 1) {
        int v = (t >= d) ? part[t - d] : 0;
        __syncthreads();
        part[t] += v;
        __syncthreads();
    }
    int run = (t > 0) ? part[t - 1] : 0;
    for (int i = 0; i < CH; i++) {
        int e = base + i;
        if (e < n) { off[e] = run; pos[e] = run; run += vals[i]; }
    }
    if (t == 1023) off[n] = part[1023];
}

__global__ void csr_scatter(const int* __restrict__ srcI, const int* __restrict__ tgtI,
                            int* __restrict__ pos, int* __restrict__ esrc, int E)
{
    int e = blockIdx.x * blockDim.x + threadIdx.x;
    if (e >= E) return;
    int slot = atomicAdd(&pos[tgtI[e]], 1);
    esrc[slot] = srcI[e];
}

// ---------------------------------------------------------------------------
// Attention over CSR: one warp per target node, two-pass, no atomics.
// q from qb (stride 512); k,v from compact kv buffer (stride 1024).
// ---------------------------------------------------------------------------
__global__ void __launch_bounds__(256)
attn_csr(const float* __restrict__ qb, const float* __restrict__ kv,
         const int* __restrict__ off, const int* __restrict__ esrc,
         float* __restrict__ p, float* __restrict__ agg, int n)
{
    int node = (blockIdx.x * blockDim.x + threadIdx.x) >> 5;
    int lane = threadIdx.x & 31;
    if (node >= n) return;
    const int start = off[node];
    const int end   = off[node + 1];
    const int h     = lane >> 2;

    const float4* qr = (const float4*)(qb + (size_t)node * DD) + lane * 4;
    float4 q0 = qr[0], q1 = qr[1], q2 = qr[2], q3 = qr[3];

    float hmax = -INFINITY;
    for (int s = start; s < end; s++) {
        int sn = esrc[s];
        const float4* kr = (const float4*)(kv + (size_t)sn * 1024) + lane * 4;
        float4 k0 = kr[0], k1 = kr[1], k2 = kr[2], k3 = kr[3];
        float d = q0.x*k0.x + q0.y*k0.y + q0.z*k0.z + q0.w*k0.w;
        d += q1.x*k1.x + q1.y*k1.y + q1.z*k1.z + q1.w*k1.w;
        d += q2.x*k2.x + q2.y*k2.y + q2.z*k2.z + q2.w*k2.w;
        d += q3.x*k3.x + q3.y*k3.y + q3.z*k3.z + q3.w*k3.w;
        d += __shfl_xor_sync(0xffffffffu, d, 1);
        d += __shfl_xor_sync(0xffffffffu, d, 2);
        if ((lane & 3) == 0) p[(size_t)s * HH + h] = d;
        hmax = fmaxf(hmax, d);
    }

    float acc[16];
#pragma unroll
    for (int i = 0; i < 16; i++) acc[i] = 0.f;
    float hsum = 0.f;

    for (int s = start; s < end; s++) {
        int sn = esrc[s];
        float d = p[(size_t)s * HH + h];
        float w = expf(d - hmax);
        hsum += w;
        const float4* vr = (const float4*)(kv + (size_t)sn * 1024 + 512) + lane * 4;
        float4 v0 = vr[0], v1 = vr[1], v2 = vr[2], v3 = vr[3];
        acc[0]  += w * v0.x; acc[1]  += w * v0.y; acc[2]  += w * v0.z; acc[3]  += w * v0.w;
        acc[4]  += w * v1.x; acc[5]  += w * v1.y; acc[6]  += w * v1.z; acc[7]  += w * v1.w;
        acc[8]  += w * v2.x; acc[9]  += w * v2.y; acc[10] += w * v2.z; acc[11] += w * v2.w;
        acc[12] += w * v3.x; acc[13] += w * v3.y; acc[14] += w * v3.z; acc[15] += w * v3.w;
    }

    float inv = 1.f / (hsum + 1e-16f);
    float4* ag = (float4*)(agg + (size_t)node * DD) + lane * 4;
#pragma unroll
    for (int i = 0; i < 4; i++)
        ag[i] = make_float4(acc[i*4+0]*inv, acc[i*4+1]*inv, acc[i*4+2]*inv, acc[i*4+3]*inv);
}

// ---------------------------------------------------------------------------
// BatchNorm over node dimension on z = a + b (residual fused)
// ---------------------------------------------------------------------------
__global__ void bn_stats(const float* __restrict__ a, const float* __restrict__ b,
                         float* __restrict__ sums, int n)
{
    int j = threadIdx.x;
    float sum = 0.f, sq = 0.f;
    for (int i = blockIdx.x; i < n; i += gridDim.x) {
        float z = a[(size_t)i * DD + j] + b[(size_t)i * DD + j];
        sum += z; sq += z * z;
    }
    atomicAdd(&sums[j], sum);
    atomicAdd(&sums[DD + j], sq);
}

__global__ void bn_finalize(const float* __restrict__ sums,
                            float* __restrict__ mu, float* __restrict__ rs, float invn)
{
    int j = threadIdx.x;
    float m = sums[j] * invn;
    float var = sums[DD + j] * invn - m * m;
    mu[j] = m;
    rs[j] = rsqrtf(var + 1e-5f);
}

__global__ void bn_apply(const float* __restrict__ a, const float* __restrict__ b,
                         const float* __restrict__ mu, const float* __restrict__ rs,
                         const float* __restrict__ g, const float* __restrict__ beta,
                         float* __restrict__ out, int n)
{
    int idx = blockIdx.x * blockDim.x + threadIdx.x;
    if (idx >= n * DD) return;
    int j = idx & (DD - 1);
    float z = a[idx] + b[idx];
    out[idx] = (z - mu[j]) * rs[j] * g[j] + beta[j];
}

// ---------------------------------------------------------------------------
// Final per-row LayerNorm  (128 threads/row, 4 floats each)
// ---------------------------------------------------------------------------
__global__ void layernorm_k(const float* __restrict__ x, const float* __restrict__ g,
                            const float* __restrict__ b, float* __restrict__ out)
{
    int row = blockIdx.x;
    int t = threadIdx.x;
    const float4* xr = (const float4*)(x + (size_t)row * DD);
    float4 v = xr[t];
    float sum = v.x + v.y + v.z + v.w;
    float sq  = v.x * v.x + v.y * v.y + v.z * v.z + v.w * v.w;

#pragma unroll
    for (int o = 16; o > 0; o >>= 1) {
        sum += __shfl_xor_sync(0xffffffffu, sum, o);
        sq  += __shfl_xor_sync(0xffffffffu, sq, o);
    }
    __shared__ float sa[4], sb[4];
    int w = t >> 5, l = t & 31;
    if (l == 0) { sa[w] = sum; sb[w] = sq; }
    __syncthreads();
    sum = sa[0] + sa[1] + sa[2] + sa[3];
    sq  = sb[0] + sb[1] + sb[2] + sb[3];

    float mu = sum * (1.f / DD);
    float var = sq * (1.f / DD) - mu * mu;
    float rs = rsqrtf(var + 1e-5f);

    const float4* g4 = (const float4*)g;
    const float4* b4 = (const float4*)b;
    float4 gg = g4[t], bb = b4[t];
    float4 o;
    o.x = (v.x - mu) * rs * gg.x + bb.x;
    o.y = (v.y - mu) * rs * gg.y + bb.y;
    o.z = (v.z - mu) * rs * gg.z + bb.z;
    o.w = (v.w - mu) * rs * gg.w + bb.w;
    *(float4*)(out + (size_t)row * DD + t * 4) = o;
}

// ---------------------------------------------------------------------------
// Orchestration
// ---------------------------------------------------------------------------
extern "C" void kernel_launch(void* const* d_in, const int* in_sizes, int n_in,
                              void* d_out, int out_size)
{
    const float* src = (const float*)d_in[0];
    const int*   ei  = (const int*)  d_in[1];
    const float* Wq  = (const float*)d_in[2];
    const float* bq  = (const float*)d_in[3];
    const float* Wk  = (const float*)d_in[4];
    const float* Wv  = (const float*)d_in[5];
    const float* Wo  = (const float*)d_in[6];
    const float* bo  = (const float*)d_in[7];
    const float* W1  = (const float*)d_in[8];
    const float* b1  = (const float*)d_in[9];
    const float* W2  = (const float*)d_in[10];
    const float* b2  = (const float*)d_in[11];
    const float* g1  = (const float*)d_in[12];
    const float* be1 = (const float*)d_in[13];
    const float* g2  = (const float*)d_in[14];
    const float* be2 = (const float*)d_in[15];
    const float* lng = (const float*)d_in[16];
    const float* lnb = (const float*)d_in[17];
    float* outp = (float*)d_out;

    const int n = in_sizes[0] / DD;
    const int E = in_sizes[1] / 2;
    const int* srcI = ei;
    const int* tgtI = ei + E;

    float *qb, *kv, *agg, *tb, *x, *ff, *p, *sums, *mu, *rs, *wqkv, *bqkv;
    int *cnt, *off, *pos, *esrc;
    cudaGetSymbolAddress((void**)&qb,   g_qb);
    cudaGetSymbolAddress((void**)&kv,   g_kv);
    cudaGetSymbolAddress((void**)&agg,  g_agg);
    cudaGetSymbolAddress((void**)&tb,   g_t);
    cudaGetSymbolAddress((void**)&x,    g_x);
    cudaGetSymbolAddress((void**)&ff,   g_ff);
    cudaGetSymbolAddress((void**)&p,    g_p);
    cudaGetSymbolAddress((void**)&sums, g_sums);
    cudaGetSymbolAddress((void**)&mu,   g_mu);
    cudaGetSymbolAddress((void**)&rs,   g_rs);
    cudaGetSymbolAddress((void**)&wqkv, g_wqkv);
    cudaGetSymbolAddress((void**)&bqkv, g_bqkv);
    cudaGetSymbolAddress((void**)&cnt,  g_cnt);
    cudaGetSymbolAddress((void**)&off,  g_off);
    cudaGetSymbolAddress((void**)&pos,  g_pos);
    cudaGetSymbolAddress((void**)&esrc, g_esrc);

    const dim3 gQKV(QKVW / 128, (n + 127) / 128);
    const dim3 gD(DD / 128, (n + 127) / 128);
    const dim3 gF(FF / 128, (n + 127) / 128);
    const int nDblocks = (n * DD + 255) / 256;

    // ---- packing; layer-0 QKV gemm hoisted to launch index 3 (ncu sample) --
    pack_qkv_w<<<(LLAY * QKVW * DD + 255) / 256, 256>>>(Wq, Wk, Wv, wqkv);
    pack_qkv_b<<<(LLAY * QKVW + 255) / 256, 256>>>(bq, bqkv);
    fill_i<<<(n + 1 + 255) / 256, 256>>>(cnt, 0, n + 1);
    gemm_tf32<false><<<gQKV, 256>>>(src, wqkv, bqkv, qb, kv, n, DD, QKVW, DD);

    // ---- CSR build (edge structure shared by both layers) ----
    csr_hist<<<(E + 255) / 256, 256>>>(tgtI, cnt, E);
    csr_scan<<<1, 1024>>>(cnt, off, pos, n);
    csr_scatter<<<(E + 255) / 256, 256>>>(srcI, tgtI, pos, esrc, E);

    const float* xin = src;

    for (int l = 0; l < LLAY; l++) {
        const float* Wol = Wo + (size_t)l * DD * DD;
        const float* W1l = W1 + (size_t)l * FF * DD;
        const float* W2l = W2 + (size_t)l * DD * FF;

        // fused q|k|v projection, split-routed into qb / kv buffers
        if (l > 0)
            gemm_tf32<false><<<gQKV, 256>>>(xin, wqkv + (size_t)l * QKVW * DD,
                                            bqkv + l * QKVW, qb, kv, n, DD, QKVW, DD);

        // attention over CSR (two-pass, no atomics, compact kv gathers)
        attn_csr<<<(n * 32 + 255) / 256, 256>>>(qb, kv, off, esrc, p, agg, n);

        // output projection
        gemm_tf32<false><<<gD, 256>>>(agg, Wol, bo + l * DD, tb, nullptr, n, DD, DD, 0);

        // batchnorm 1 (residual xin + tb)
        fill_f<<<(2 * DD + 255) / 256, 256>>>(sums, 0.f, 2 * DD);
        bn_stats<<<256, DD>>>(xin, tb, sums, n);
        bn_finalize<<<1, DD>>>(sums, mu, rs, 1.f / (float)n);
        bn_apply<<<nDblocks, 256>>>(xin, tb, mu, rs, g1 + l * DD, be1 + l * DD, x, n);

        // feedforward
        gemm_tf32<true ><<<gF, 256>>>(x, W1l, b1 + l * FF, ff, nullptr, n, DD, FF, 0);
        gemm_tf32<false><<<gD, 256>>>(ff, W2l, b2 + l * DD, tb, nullptr, n, FF, DD, 0);

        // batchnorm 2 (residual x + tb), in-place on x
        fill_f<<<(2 * DD + 255) / 256, 256>>>(sums, 0.f, 2 * DD);
        bn_stats<<<256, DD>>>(x, tb, sums, n);
        bn_finalize<<<1, DD>>>(sums, mu, rs, 1.f / (float)n);
        bn_apply<<<nDblocks, 256>>>(x, tb, mu, rs, g2 + l * DD, be2 + l * DD, x, n);

        xin = x;
    }

    // final layernorm -> output
    layernorm_k<<<n, 128>>>(x, lng, lnb, outp);
}

// round 8
// speedup vs baseline: 1.0606x; 1.0210x over previous
#include <cuda_runtime.h>
#include <math.h>
#include <stdint.h>

// Problem constants (fixed by the reference generator)
#define NN   20000
#define DD   512
#define HH   8
#define DHH  64
#define FF   2048
#define LLAY 2
#define EE   320000
#define QKVW 1536   // packed q|k|v projection width

// ---------------------------------------------------------------------------
// Scratch (device globals: alloc-free rule)
// ---------------------------------------------------------------------------
__device__ float g_qb  [NN * DD];        // q rows (read once per node)
__device__ float g_kv  [NN * 2 * DD];    // compact k|v rows (gather working set)
__device__ float g_agg [NN * DD];
__device__ float g_t   [NN * DD];
__device__ float g_x   [NN * DD];
__device__ float g_ff  [NN * FF];
__device__ float g_p   [EE * HH];
__device__ float g_sums[2 * DD];
__device__ float g_mu  [DD];
__device__ float g_rs  [DD];
__device__ float g_wqkv[LLAY * QKVW * DD];
__device__ float g_bqkv[LLAY * QKVW];
__device__ int g_cnt [NN + 1];
__device__ int g_off [NN + 1];
__device__ int g_pos [NN];
__device__ int g_esrc[EE];

// ---------------------------------------------------------------------------
// Utility kernels
// ---------------------------------------------------------------------------
__global__ void fill_f(float* __restrict__ p, float v, int n) {
    int i = blockIdx.x * blockDim.x + threadIdx.x;
    if (i < n) p[i] = v;
}
__global__ void fill_i(int* __restrict__ p, int v, int n) {
    int i = blockIdx.x * blockDim.x + threadIdx.x;
    if (i < n) p[i] = v;
}

// ---------------------------------------------------------------------------
// Weight packing:  wout[l][r][c], r<512: Wq*0.125 | r<1024: Wk | else Wv
// ---------------------------------------------------------------------------
__global__ void pack_qkv_w(const float* __restrict__ Wq, const float* __restrict__ Wk,
                           const float* __restrict__ Wv, float* __restrict__ wout)
{
    int idx = blockIdx.x * blockDim.x + threadIdx.x;
    const int total = LLAY * QKVW * DD;
    if (idx >= total) return;
    int l = idx / (QKVW * DD);
    int rem = idx % (QKVW * DD);
    int r = rem / DD, c = rem % DD;
    float val;
    if (r < 512)       val = Wq[(size_t)l * DD * DD + (size_t)r * DD + c] * 0.125f;
    else if (r < 1024) val = Wk[(size_t)l * DD * DD + (size_t)(r - 512) * DD + c];
    else               val = Wv[(size_t)l * DD * DD + (size_t)(r - 1024) * DD + c];
    wout[idx] = val;
}
__global__ void pack_qkv_b(const float* __restrict__ bq, float* __restrict__ bout)
{
    int idx = blockIdx.x * blockDim.x + threadIdx.x;
    if (idx >= LLAY * QKVW) return;
    int l = idx / QKVW, r = idx % QKVW;
    bout[idx] = (r < 512) ? bq[l * DD + r] * 0.125f : 0.f;
}

// ---------------------------------------------------------------------------
// cp.async helpers
// ---------------------------------------------------------------------------
__device__ __forceinline__ uint32_t smem_u32(const void* p) {
    uint32_t a;
    asm("{ .reg .u64 t; cvta.to.shared.u64 t, %1; cvt.u32.u64 %0, t; }"
        : "=r"(a) : "l"(p));
    return a;
}
__device__ __forceinline__ void cp16(uint32_t dst, const void* src, int szbytes) {
    asm volatile("cp.async.cg.shared.global [%0], [%1], 16, %2;"
                 :: "r"(dst), "l"(src), "r"(szbytes) : "memory");
}
#define CP_COMMIT() asm volatile("cp.async.commit_group;" ::: "memory")
#define CP_WAIT(n)  asm volatile("cp.async.wait_group %0;" :: "n"(n) : "memory")

__device__ __forceinline__ uint32_t f2tf(float x) {
    uint32_t r;
    asm("cvt.rna.tf32.f32 %0, %1;" : "=r"(r) : "f"(x));
    return r;
}

// ---------------------------------------------------------------------------
// TF32 tensor-core GEMM (mma.sync HMMA path), cp.async 3-stage pipeline.
// Raw f32 staged in smem; cvt.rna.tf32 applied at fragment-load time, so
// numerics match the reference rna path exactly.
// C = act(A[M,K] @ W[Nout,K]^T + bias). If split>0, output columns
// [0,split) -> Cq (stride split), [split,Nout) -> Ckv (stride Nout-split).
// Block tile 128x128, BK=32, 8 warps (2x4), warp tile 64x32, 2 CTAs/SM.
// ---------------------------------------------------------------------------
#define TILE_F (128 * 36)                        // floats per matrix stage
#define GEMM_SMEM (6 * TILE_F * (int)sizeof(float))  // 3 stages x (A+B) = 110592 B

template <bool RELU>
__global__ void __launch_bounds__(256, 2)
gemm_tf32(const float* __restrict__ A, const float* __restrict__ W,
          const float* __restrict__ bias, float* __restrict__ Cq,
          float* __restrict__ Ckv, int M, int K, int Nout, int split)
{
    extern __shared__ float smemf[];
    float* AsB = smemf;                 // [3][128][36]
    float* BsB = smemf + 3 * TILE_F;    // [3][128][36]
    const uint32_t AsAddr = smem_u32(AsB);
    const uint32_t BsAddr = smem_u32(BsB);

    const int tid  = threadIdx.x;
    const int lane = tid & 31;
    const int warp = tid >> 5;
    const int wm   = warp >> 2;     // 0..1
    const int wn   = warp & 3;      // 0..3
    const int g    = lane >> 2;     // 0..7
    const int c    = lane & 3;      // 0..3
    const int rowBase = blockIdx.y * 128;
    const int colBase = blockIdx.x * 128;

    // output routing (whole 128-col block lands in one buffer: split%128==0)
    float* Cb;
    int NoutB, colB;
    if (split > 0 && colBase >= split) {
        Cb = Ckv; NoutB = Nout - split; colB = colBase - split;
    } else if (split > 0) {
        Cb = Cq;  NoutB = split;        colB = colBase;
    } else {
        Cb = Cq;  NoutB = Nout;         colB = colBase;
    }

    float acc[4][4][4];
#pragma unroll
    for (int mt = 0; mt < 4; mt++)
#pragma unroll
        for (int nt = 0; nt < 4; nt++)
#pragma unroll
            for (int i = 0; i < 4; i++) acc[mt][nt][i] = 0.f;

    // async tile loader: 256 threads x 4 slots cover 128 rows x 8 quads (16B)
    auto issue = [&](int kt) {
        const int k0 = kt << 5;
        const int st = kt % 3;
        const uint32_t Ad = AsAddr + (uint32_t)(st * TILE_F) * 4u;
        const uint32_t Bd = BsAddr + (uint32_t)(st * TILE_F) * 4u;
#pragma unroll
        for (int i = 0; i < 4; i++) {
            int li = tid + i * 256;
            int r  = li >> 3;
            int q  = li & 7;
            int ar = rowBase + r;
            int sz = (ar < M) ? 16 : 0;
            int arc = (ar < M) ? ar : (M - 1);
            cp16(Ad + (uint32_t)(r * 36 + q * 4) * 4u,
                 A + (size_t)arc * K + k0 + q * 4, sz);
            cp16(Bd + (uint32_t)(r * 36 + q * 4) * 4u,
                 W + (size_t)(colBase + r) * K + k0 + q * 4, 16);
        }
        CP_COMMIT();
    };

    const int NT = K >> 5;   // >= 16 always
    issue(0);
    issue(1);

    for (int kt = 0; kt < NT; kt++) {
        if (kt + 1 < NT) { CP_WAIT(1); } else { CP_WAIT(0); }
        __syncthreads();
        if (kt + 2 < NT) issue(kt + 2);

        const float* As = AsB + (kt % 3) * TILE_F;
        const float* Bs = BsB + (kt % 3) * TILE_F;

#pragma unroll
        for (int ks = 0; ks < 4; ks++) {
            uint32_t af[4][4];
            uint32_t bf[4][2];
#pragma unroll
            for (int mt = 0; mt < 4; mt++) {
                int r0 = wm * 64 + mt * 16 + g;
                af[mt][0] = f2tf(As[(r0    ) * 36 + ks * 8 + c    ]);
                af[mt][1] = f2tf(As[(r0 + 8) * 36 + ks * 8 + c    ]);
                af[mt][2] = f2tf(As[(r0    ) * 36 + ks * 8 + c + 4]);
                af[mt][3] = f2tf(As[(r0 + 8) * 36 + ks * 8 + c + 4]);
            }
#pragma unroll
            for (int nt = 0; nt < 4; nt++) {
                int n0 = wn * 32 + nt * 8 + g;
                bf[nt][0] = f2tf(Bs[n0 * 36 + ks * 8 + c    ]);
                bf[nt][1] = f2tf(Bs[n0 * 36 + ks * 8 + c + 4]);
            }
#pragma unroll
            for (int mt = 0; mt < 4; mt++)
#pragma unroll
                for (int nt = 0; nt < 4; nt++)
                    asm volatile(
                        "mma.sync.aligned.m16n8k8.row.col.f32.tf32.tf32.f32 "
                        "{%0,%1,%2,%3}, {%4,%5,%6,%7}, {%8,%9}, {%0,%1,%2,%3};"
                        : "+f"(acc[mt][nt][0]), "+f"(acc[mt][nt][1]),
                          "+f"(acc[mt][nt][2]), "+f"(acc[mt][nt][3])
                        : "r"(af[mt][0]), "r"(af[mt][1]),
                          "r"(af[mt][2]), "r"(af[mt][3]),
                          "r"(bf[nt][0]), "r"(bf[nt][1]));
        }
        __syncthreads();
    }

    // Epilogue: bias, relu, guarded float2 stores with split routing
#pragma unroll
    for (int mt = 0; mt < 4; mt++) {
        int r0 = rowBase + wm * 64 + mt * 16 + g;
        int r1 = r0 + 8;
#pragma unroll
        for (int nt = 0; nt < 4; nt++) {
            int colRel = wn * 32 + nt * 8 + c * 2;
            float2 bb = *(const float2*)(bias + colBase + colRel);
            float v0 = acc[mt][nt][0] + bb.x;
            float v1 = acc[mt][nt][1] + bb.y;
            float v2 = acc[mt][nt][2] + bb.x;
            float v3 = acc[mt][nt][3] + bb.y;
            if (RELU) {
                v0 = fmaxf(v0, 0.f); v1 = fmaxf(v1, 0.f);
                v2 = fmaxf(v2, 0.f); v3 = fmaxf(v3, 0.f);
            }
            int col = colB + colRel;
            if (r0 < M) *(float2*)(Cb + (size_t)r0 * NoutB + col) = make_float2(v0, v1);
            if (r1 < M) *(float2*)(Cb + (size_t)r1 * NoutB + col) = make_float2(v2, v3);
        }
    }
}

// ---------------------------------------------------------------------------
// CSR build
// ---------------------------------------------------------------------------
__global__ void csr_hist(const int* __restrict__ tgtI, int* __restrict__ cnt, int E)
{
    int e = blockIdx.x * blockDim.x + threadIdx.x;
    if (e < E) atomicAdd(&cnt[tgtI[e]], 1);
}

__global__ void __launch_bounds__(1024)
csr_scan(const int* __restrict__ cnt, int* __restrict__ off, int* __restrict__ pos, int n)
{
    __shared__ int part[1024];
    const int t = threadIdx.x;
    const int CH = (n + 1023) / 1024;
    int vals[32];
    int base = t * CH;
    int local = 0;
    for (int i = 0; i < CH; i++) {
        int e = base + i;
        int v = (e < n) ? cnt[e] : 0;
        vals[i] = v;
        local += v;
    }
    part[t] = local;
    __syncthreads();
    for (int d = 1; d < 1024; d <<= 1) {
        int v = (t >= d) ? part[t - d] : 0;
        __syncthreads();
        part[t] += v;
        __syncthreads();
    }
    int run = (t > 0) ? part[t - 1] : 0;
    for (int i = 0; i < CH; i++) {
        int e = base + i;
        if (e < n) { off[e] = run; pos[e] = run; run += vals[i]; }
    }
    if (t == 1023) off[n] = part[1023];
}

__global__ void csr_scatter(const int* __restrict__ srcI, const int* __restrict__ tgtI,
                            int* __restrict__ pos, int* __restrict__ esrc, int E)
{
    int e = blockIdx.x * blockDim.x + threadIdx.x;
    if (e >= E) return;
    int slot = atomicAdd(&pos[tgtI[e]], 1);
    esrc[slot] = srcI[e];
}

// ---------------------------------------------------------------------------
// Attention over CSR: one warp per target node, two-pass, no atomics.
// q from qb (stride 512); k,v from compact kv buffer (stride 1024).
// ---------------------------------------------------------------------------
__global__ void __launch_bounds__(256)
attn_csr(const float* __restrict__ qb, const float* __restrict__ kv,
         const int* __restrict__ off, const int* __restrict__ esrc,
         float* __restrict__ p, float* __restrict__ agg, int n)
{
    int node = (blockIdx.x * blockDim.x + threadIdx.x) >> 5;
    int lane = threadIdx.x & 31;
    if (node >= n) return;
    const int start = off[node];
    const int end   = off[node + 1];
    const int h     = lane >> 2;

    const float4* qr = (const float4*)(qb + (size_t)node * DD) + lane * 4;
    float4 q0 = qr[0], q1 = qr[1], q2 = qr[2], q3 = qr[3];

    float hmax = -INFINITY;
    for (int s = start; s < end; s++) {
        int sn = esrc[s];
        const float4* kr = (const float4*)(kv + (size_t)sn * 1024) + lane * 4;
        float4 k0 = kr[0], k1 = kr[1], k2 = kr[2], k3 = kr[3];
        float d = q0.x*k0.x + q0.y*k0.y + q0.z*k0.z + q0.w*k0.w;
        d += q1.x*k1.x + q1.y*k1.y + q1.z*k1.z + q1.w*k1.w;
        d += q2.x*k2.x + q2.y*k2.y + q2.z*k2.z + q2.w*k2.w;
        d += q3.x*k3.x + q3.y*k3.y + q3.z*k3.z + q3.w*k3.w;
        d += __shfl_xor_sync(0xffffffffu, d, 1);
        d += __shfl_xor_sync(0xffffffffu, d, 2);
        if ((lane & 3) == 0) p[(size_t)s * HH + h] = d;
        hmax = fmaxf(hmax, d);
    }

    float acc[16];
#pragma unroll
    for (int i = 0; i < 16; i++) acc[i] = 0.f;
    float hsum = 0.f;

    for (int s = start; s < end; s++) {
        int sn = esrc[s];
        float d = p[(size_t)s * HH + h];
        float w = expf(d - hmax);
        hsum += w;
        const float4* vr = (const float4*)(kv + (size_t)sn * 1024 + 512) + lane * 4;
        float4 v0 = vr[0], v1 = vr[1], v2 = vr[2], v3 = vr[3];
        acc[0]  += w * v0.x; acc[1]  += w * v0.y; acc[2]  += w * v0.z; acc[3]  += w * v0.w;
        acc[4]  += w * v1.x; acc[5]  += w * v1.y; acc[6]  += w * v1.z; acc[7]  += w * v1.w;
        acc[8]  += w * v2.x; acc[9]  += w * v2.y; acc[10] += w * v2.z; acc[11] += w * v2.w;
        acc[12] += w * v3.x; acc[13] += w * v3.y; acc[14] += w * v3.z; acc[15] += w * v3.w;
    }

    float inv = 1.f / (hsum + 1e-16f);
    float4* ag = (float4*)(agg + (size_t)node * DD) + lane * 4;
#pragma unroll
    for (int i = 0; i < 4; i++)
        ag[i] = make_float4(acc[i*4+0]*inv, acc[i*4+1]*inv, acc[i*4+2]*inv, acc[i*4+3]*inv);
}

// ---------------------------------------------------------------------------
// BatchNorm over node dimension on z = a + b (residual fused)
// ---------------------------------------------------------------------------
__global__ void bn_stats(const float* __restrict__ a, const float* __restrict__ b,
                         float* __restrict__ sums, int n)
{
    int j = threadIdx.x;
    float sum = 0.f, sq = 0.f;
    for (int i = blockIdx.x; i < n; i += gridDim.x) {
        float z = a[(size_t)i * DD + j] + b[(size_t)i * DD + j];
        sum += z; sq += z * z;
    }
    atomicAdd(&sums[j], sum);
    atomicAdd(&sums[DD + j], sq);
}

__global__ void bn_finalize(const float* __restrict__ sums,
                            float* __restrict__ mu, float* __restrict__ rs, float invn)
{
    int j = threadIdx.x;
    float m = sums[j] * invn;
    float var = sums[DD + j] * invn - m * m;
    mu[j] = m;
    rs[j] = rsqrtf(var + 1e-5f);
}

__global__ void bn_apply(const float* __restrict__ a, const float* __restrict__ b,
                         const float* __restrict__ mu, const float* __restrict__ rs,
                         const float* __restrict__ g, const float* __restrict__ beta,
                         float* __restrict__ out, int n)
{
    int idx = blockIdx.x * blockDim.x + threadIdx.x;
    if (idx >= n * DD) return;
    int j = idx & (DD - 1);
    float z = a[idx] + b[idx];
    out[idx] = (z - mu[j]) * rs[j] * g[j] + beta[j];
}

// ---------------------------------------------------------------------------
// Final per-row LayerNorm  (128 threads/row, 4 floats each)
// ---------------------------------------------------------------------------
__global__ void layernorm_k(const float* __restrict__ x, const float* __restrict__ g,
                            const float* __restrict__ b, float* __restrict__ out)
{
    int row = blockIdx.x;
    int t = threadIdx.x;
    const float4* xr = (const float4*)(x + (size_t)row * DD);
    float4 v = xr[t];
    float sum = v.x + v.y + v.z + v.w;
    float sq  = v.x * v.x + v.y * v.y + v.z * v.z + v.w * v.w;

#pragma unroll
    for (int o = 16; o > 0; o >>= 1) {
        sum += __shfl_xor_sync(0xffffffffu, sum, o);
        sq  += __shfl_xor_sync(0xffffffffu, sq, o);
    }
    __shared__ float sa[4], sb[4];
    int w = t >> 5, l = t & 31;
    if (l == 0) { sa[w] = sum; sb[w] = sq; }
    __syncthreads();
    sum = sa[0] + sa[1] + sa[2] + sa[3];
    sq  = sb[0] + sb[1] + sb[2] + sb[3];

    float mu = sum * (1.f / DD);
    float var = sq * (1.f / DD) - mu * mu;
    float rs = rsqrtf(var + 1e-5f);

    const float4* g4 = (const float4*)g;
    const float4* b4 = (const float4*)b;
    float4 gg = g4[t], bb = b4[t];
    float4 o;
    o.x = (v.x - mu) * rs * gg.x + bb.x;
    o.y = (v.y - mu) * rs * gg.y + bb.y;
    o.z = (v.z - mu) * rs * gg.z + bb.z;
    o.w = (v.w - mu) * rs * gg.w + bb.w;
    *(float4*)(out + (size_t)row * DD + t * 4) = o;
}

// ---------------------------------------------------------------------------
// Orchestration
// ---------------------------------------------------------------------------
extern "C" void kernel_launch(void* const* d_in, const int* in_sizes, int n_in,
                              void* d_out, int out_size)
{
    const float* src = (const float*)d_in[0];
    const int*   ei  = (const int*)  d_in[1];
    const float* Wq  = (const float*)d_in[2];
    const float* bq  = (const float*)d_in[3];
    const float* Wk  = (const float*)d_in[4];
    const float* Wv  = (const float*)d_in[5];
    const float* Wo  = (const float*)d_in[6];
    const float* bo  = (const float*)d_in[7];
    const float* W1  = (const float*)d_in[8];
    const float* b1  = (const float*)d_in[9];
    const float* W2  = (const float*)d_in[10];
    const float* b2  = (const float*)d_in[11];
    const float* g1  = (const float*)d_in[12];
    const float* be1 = (const float*)d_in[13];
    const float* g2  = (const float*)d_in[14];
    const float* be2 = (const float*)d_in[15];
    const float* lng = (const float*)d_in[16];
    const float* lnb = (const float*)d_in[17];
    float* outp = (float*)d_out;

    const int n = in_sizes[0] / DD;
    const int E = in_sizes[1] / 2;
    const int* srcI = ei;
    const int* tgtI = ei + E;

    float *qb, *kv, *agg, *tb, *x, *ff, *p, *sums, *mu, *rs, *wqkv, *bqkv;
    int *cnt, *off, *pos, *esrc;
    cudaGetSymbolAddress((void**)&qb,   g_qb);
    cudaGetSymbolAddress((void**)&kv,   g_kv);
    cudaGetSymbolAddress((void**)&agg,  g_agg);
    cudaGetSymbolAddress((void**)&tb,   g_t);
    cudaGetSymbolAddress((void**)&x,    g_x);
    cudaGetSymbolAddress((void**)&ff,   g_ff);
    cudaGetSymbolAddress((void**)&p,    g_p);
    cudaGetSymbolAddress((void**)&sums, g_sums);
    cudaGetSymbolAddress((void**)&mu,   g_mu);
    cudaGetSymbolAddress((void**)&rs,   g_rs);
    cudaGetSymbolAddress((void**)&wqkv, g_wqkv);
    cudaGetSymbolAddress((void**)&bqkv, g_bqkv);
    cudaGetSymbolAddress((void**)&cnt,  g_cnt);
    cudaGetSymbolAddress((void**)&off,  g_off);
    cudaGetSymbolAddress((void**)&pos,  g_pos);
    cudaGetSymbolAddress((void**)&esrc, g_esrc);

    // raise dynamic smem limit for the GEMM (idempotent host calls)
    cudaFuncSetAttribute((const void*)gemm_tf32<false>,
                         cudaFuncAttributeMaxDynamicSharedMemorySize, GEMM_SMEM);
    cudaFuncSetAttribute((const void*)gemm_tf32<true>,
                         cudaFuncAttributeMaxDynamicSharedMemorySize, GEMM_SMEM);

    const dim3 gQKV(QKVW / 128, (n + 127) / 128);
    const dim3 gD(DD / 128, (n + 127) / 128);
    const dim3 gF(FF / 128, (n + 127) / 128);
    const int nDblocks = (n * DD + 255) / 256;

    // ---- packing; layer-0 QKV gemm hoisted to launch index 3 (ncu sample) --
    pack_qkv_w<<<(LLAY * QKVW * DD + 255) / 256, 256>>>(Wq, Wk, Wv, wqkv);
    pack_qkv_b<<<(LLAY * QKVW + 255) / 256, 256>>>(bq, bqkv);
    fill_i<<<(n + 1 + 255) / 256, 256>>>(cnt, 0, n + 1);
    gemm_tf32<false><<<gQKV, 256, GEMM_SMEM>>>(src, wqkv, bqkv, qb, kv, n, DD, QKVW, DD);

    // ---- CSR build (edge structure shared by both layers) ----
    csr_hist<<<(E + 255) / 256, 256>>>(tgtI, cnt, E);
    csr_scan<<<1, 1024>>>(cnt, off, pos, n);
    csr_scatter<<<(E + 255) / 256, 256>>>(srcI, tgtI, pos, esrc, E);

    const float* xin = src;

    for (int l = 0; l < LLAY; l++) {
        const float* Wol = Wo + (size_t)l * DD * DD;
        const float* W1l = W1 + (size_t)l * FF * DD;
        const float* W2l = W2 + (size_t)l * DD * FF;

        // fused q|k|v projection, split-routed into qb / kv buffers
        if (l > 0)
            gemm_tf32<false><<<gQKV, 256, GEMM_SMEM>>>(xin, wqkv + (size_t)l * QKVW * DD,
                                                       bqkv + l * QKVW, qb, kv, n, DD, QKVW, DD);

        // attention over CSR (two-pass, no atomics, compact kv gathers)
        attn_csr<<<(n * 32 + 255) / 256, 256>>>(qb, kv, off, esrc, p, agg, n);

        // output projection
        gemm_tf32<false><<<gD, 256, GEMM_SMEM>>>(agg, Wol, bo + l * DD, tb, nullptr, n, DD, DD, 0);

        // batchnorm 1 (residual xin + tb)
        fill_f<<<(2 * DD + 255) / 256, 256>>>(sums, 0.f, 2 * DD);
        bn_stats<<<256, DD>>>(xin, tb, sums, n);
        bn_finalize<<<1, DD>>>(sums, mu, rs, 1.f / (float)n);
        bn_apply<<<nDblocks, 256>>>(xin, tb, mu, rs, g1 + l * DD, be1 + l * DD, x, n);

        // feedforward
        gemm_tf32<true ><<<gF, 256, GEMM_SMEM>>>(x, W1l, b1 + l * FF, ff, nullptr, n, DD, FF, 0);
        gemm_tf32<false><<<gD, 256, GEMM_SMEM>>>(ff, W2l, b2 + l * DD, tb, nullptr, n, FF, DD, 0);

        // batchnorm 2 (residual x + tb), in-place on x
        fill_f<<<(2 * DD + 255) / 256, 256>>>(sums, 0.f, 2 * DD);
        bn_stats<<<256, DD>>>(x, tb, sums, n);
        bn_finalize<<<1, DD>>>(sums, mu, rs, 1.f / (float)n);
        bn_apply<<<nDblocks, 256>>>(x, tb, mu, rs, g2 + l * DD, be2 + l * DD, x, n);

        xin = x;
    }

    // final layernorm -> output
    layernorm_k<<<n, 128>>>(x, lng, lnb, outp);
}

// round 9
// speedup vs baseline: 1.1745x; 1.1074x over previous
#include <cuda_runtime.h>
#include <math.h>
#include <stdint.h>

// Problem constants (fixed by the reference generator)
#define NN   20000
#define DD   512
#define HH   8
#define DHH  64
#define FF   2048
#define LLAY 2
#define EE   320000
#define QKVW 1536   // packed q|k|v projection width

// ---------------------------------------------------------------------------
// Scratch (device globals: alloc-free rule)
// ---------------------------------------------------------------------------
__device__ float g_qb  [NN * DD];        // q rows (read once per node)
__device__ float g_kv  [NN * 2 * DD];    // compact k|v rows (gather working set)
__device__ float g_agg [NN * DD];        // attn output (tf32-rounded)
__device__ float g_t   [NN * DD];
__device__ float g_x   [NN * DD];        // exact activations (residual/LN path)
__device__ float g_xr  [NN * DD];        // tf32-rounded activations (GEMM path)
__device__ float g_srctf[NN * DD];       // tf32-rounded src
__device__ float g_ff  [NN * FF];        // FF1 output (tf32-rounded)
__device__ float g_p   [EE * HH];
__device__ float g_sums[2 * DD];
__device__ float g_mu  [DD];
__device__ float g_rs  [DD];
__device__ float g_wqkv[LLAY * QKVW * DD];   // packed+rounded
__device__ float g_bqkv[LLAY * QKVW];
__device__ float g_woR [LLAY * DD * DD];     // rounded weight copies
__device__ float g_w1R [LLAY * FF * DD];
__device__ float g_w2R [LLAY * DD * FF];
__device__ int g_cnt [NN + 1];
__device__ int g_off [NN + 1];
__device__ int g_pos [NN];
__device__ int g_esrc[EE];

// ---------------------------------------------------------------------------
// helpers
// ---------------------------------------------------------------------------
__device__ __forceinline__ uint32_t smem_u32(const void* p) {
    uint32_t a;
    asm("{ .reg .u64 t; cvta.to.shared.u64 t, %1; cvt.u32.u64 %0, t; }"
        : "=r"(a) : "l"(p));
    return a;
}
__device__ __forceinline__ void cp16(uint32_t dst, const void* src, int szbytes) {
    asm volatile("cp.async.cg.shared.global [%0], [%1], 16, %2;"
                 :: "r"(dst), "l"(src), "r"(szbytes) : "memory");
}
#define CP_COMMIT() asm volatile("cp.async.commit_group;" ::: "memory")
#define CP_WAIT(n)  asm volatile("cp.async.wait_group %0;" :: "n"(n) : "memory")

__device__ __forceinline__ float rnd_tf(float x) {
    uint32_t r;
    asm("cvt.rna.tf32.f32 %0, %1;" : "=r"(r) : "f"(x));
    return __uint_as_float(r);
}

// ---------------------------------------------------------------------------
// Utility kernels
// ---------------------------------------------------------------------------
__global__ void fill_f(float* __restrict__ p, float v, int n) {
    int i = blockIdx.x * blockDim.x + threadIdx.x;
    if (i < n) p[i] = v;
}
__global__ void fill_i(int* __restrict__ p, int v, int n) {
    int i = blockIdx.x * blockDim.x + threadIdx.x;
    if (i < n) p[i] = v;
}
__global__ void round_copy(const float* __restrict__ in, float* __restrict__ out, int n)
{
    int i = blockIdx.x * blockDim.x + threadIdx.x;
    if (i < n) out[i] = rnd_tf(in[i]);
}

// ---------------------------------------------------------------------------
// Weight packing (rounded): r<512: Wq*0.125 | r<1024: Wk | else Wv
// ---------------------------------------------------------------------------
__global__ void pack_qkv_w(const float* __restrict__ Wq, const float* __restrict__ Wk,
                           const float* __restrict__ Wv, float* __restrict__ wout)
{
    int idx = blockIdx.x * blockDim.x + threadIdx.x;
    const int total = LLAY * QKVW * DD;
    if (idx >= total) return;
    int l = idx / (QKVW * DD);
    int rem = idx % (QKVW * DD);
    int r = rem / DD, c = rem % DD;
    float val;
    if (r < 512)       val = Wq[(size_t)l * DD * DD + (size_t)r * DD + c] * 0.125f;
    else if (r < 1024) val = Wk[(size_t)l * DD * DD + (size_t)(r - 512) * DD + c];
    else               val = Wv[(size_t)l * DD * DD + (size_t)(r - 1024) * DD + c];
    wout[idx] = rnd_tf(val);
}
__global__ void pack_qkv_b(const float* __restrict__ bq, float* __restrict__ bout)
{
    int idx = blockIdx.x * blockDim.x + threadIdx.x;
    if (idx >= LLAY * QKVW) return;
    int l = idx / QKVW, r = idx % QKVW;
    bout[idx] = (r < 512) ? bq[l * DD + r] * 0.125f : 0.f;
}

// ---------------------------------------------------------------------------
// TF32 tensor-core GEMM (mma.sync), cp.async 3-stage pipeline.
// ALL operands are pre-rounded to tf32 values in gmem, so raw-bit fragment
// feeds are numerically identical to cvt.rna at load (idempotent rounding).
// C = act(A @ W^T + bias); ROUND rounds outputs (for chained GEMM inputs).
// split>0: cols [0,split)->Cq, [split,Nout)->Ckv.
// ---------------------------------------------------------------------------
#define TILE_F (128 * 36)
#define GEMM_SMEM (6 * TILE_F * (int)sizeof(float))  // 110592 B

template <bool RELU, bool ROUND>
__global__ void __launch_bounds__(256, 2)
gemm_tf32(const float* __restrict__ A, const float* __restrict__ W,
          const float* __restrict__ bias, float* __restrict__ Cq,
          float* __restrict__ Ckv, int M, int K, int Nout, int split)
{
    extern __shared__ float smemf[];
    float* AsB = smemf;                 // [3][128][36]
    float* BsB = smemf + 3 * TILE_F;    // [3][128][36]
    const uint32_t AsAddr = smem_u32(AsB);
    const uint32_t BsAddr = smem_u32(BsB);

    const int tid  = threadIdx.x;
    const int lane = tid & 31;
    const int warp = tid >> 5;
    const int wm   = warp >> 2;     // 0..1
    const int wn   = warp & 3;      // 0..3
    const int g    = lane >> 2;     // 0..7
    const int c    = lane & 3;      // 0..3
    const int rowBase = blockIdx.y * 128;
    const int colBase = blockIdx.x * 128;

    float* Cb;
    int NoutB, colB;
    if (split > 0 && colBase >= split) {
        Cb = Ckv; NoutB = Nout - split; colB = colBase - split;
    } else if (split > 0) {
        Cb = Cq;  NoutB = split;        colB = colBase;
    } else {
        Cb = Cq;  NoutB = Nout;         colB = colBase;
    }

    float acc[4][4][4];
#pragma unroll
    for (int mt = 0; mt < 4; mt++)
#pragma unroll
        for (int nt = 0; nt < 4; nt++)
#pragma unroll
            for (int i = 0; i < 4; i++) acc[mt][nt][i] = 0.f;

    auto issue = [&](int kt) {
        const int k0 = kt << 5;
        const int st = kt % 3;
        const uint32_t Ad = AsAddr + (uint32_t)(st * TILE_F) * 4u;
        const uint32_t Bd = BsAddr + (uint32_t)(st * TILE_F) * 4u;
#pragma unroll
        for (int i = 0; i < 4; i++) {
            int li = tid + i * 256;
            int r  = li >> 3;
            int q  = li & 7;
            int ar = rowBase + r;
            int sz = (ar < M) ? 16 : 0;
            int arc = (ar < M) ? ar : (M - 1);
            cp16(Ad + (uint32_t)(r * 36 + q * 4) * 4u,
                 A + (size_t)arc * K + k0 + q * 4, sz);
            cp16(Bd + (uint32_t)(r * 36 + q * 4) * 4u,
                 W + (size_t)(colBase + r) * K + k0 + q * 4, 16);
        }
        CP_COMMIT();
    };

    const int NT = K >> 5;
    issue(0);
    issue(1);

    for (int kt = 0; kt < NT; kt++) {
        if (kt + 1 < NT) { CP_WAIT(1); } else { CP_WAIT(0); }
        __syncthreads();
        if (kt + 2 < NT) issue(kt + 2);

        const float* As = AsB + (kt % 3) * TILE_F;
        const float* Bs = BsB + (kt % 3) * TILE_F;

#pragma unroll
        for (int ks = 0; ks < 4; ks++) {
            uint32_t af[4][4];
            uint32_t bf[4][2];
#pragma unroll
            for (int mt = 0; mt < 4; mt++) {
                int r0 = wm * 64 + mt * 16 + g;
                af[mt][0] = __float_as_uint(As[(r0    ) * 36 + ks * 8 + c    ]);
                af[mt][1] = __float_as_uint(As[(r0 + 8) * 36 + ks * 8 + c    ]);
                af[mt][2] = __float_as_uint(As[(r0    ) * 36 + ks * 8 + c + 4]);
                af[mt][3] = __float_as_uint(As[(r0 + 8) * 36 + ks * 8 + c + 4]);
            }
#pragma unroll
            for (int nt = 0; nt < 4; nt++) {
                int n0 = wn * 32 + nt * 8 + g;
                bf[nt][0] = __float_as_uint(Bs[n0 * 36 + ks * 8 + c    ]);
                bf[nt][1] = __float_as_uint(Bs[n0 * 36 + ks * 8 + c + 4]);
            }
#pragma unroll
            for (int mt = 0; mt < 4; mt++)
#pragma unroll
                for (int nt = 0; nt < 4; nt++)
                    asm volatile(
                        "mma.sync.aligned.m16n8k8.row.col.f32.tf32.tf32.f32 "
                        "{%0,%1,%2,%3}, {%4,%5,%6,%7}, {%8,%9}, {%0,%1,%2,%3};"
                        : "+f"(acc[mt][nt][0]), "+f"(acc[mt][nt][1]),
                          "+f"(acc[mt][nt][2]), "+f"(acc[mt][nt][3])
                        : "r"(af[mt][0]), "r"(af[mt][1]),
                          "r"(af[mt][2]), "r"(af[mt][3]),
                          "r"(bf[nt][0]), "r"(bf[nt][1]));
        }
        __syncthreads();
    }

    // Epilogue: bias, relu, optional tf32 rounding, split-routed stores
#pragma unroll
    for (int mt = 0; mt < 4; mt++) {
        int r0 = rowBase + wm * 64 + mt * 16 + g;
        int r1 = r0 + 8;
#pragma unroll
        for (int nt = 0; nt < 4; nt++) {
            int colRel = wn * 32 + nt * 8 + c * 2;
            float2 bb = *(const float2*)(bias + colBase + colRel);
            float v0 = acc[mt][nt][0] + bb.x;
            float v1 = acc[mt][nt][1] + bb.y;
            float v2 = acc[mt][nt][2] + bb.x;
            float v3 = acc[mt][nt][3] + bb.y;
            if (RELU) {
                v0 = fmaxf(v0, 0.f); v1 = fmaxf(v1, 0.f);
                v2 = fmaxf(v2, 0.f); v3 = fmaxf(v3, 0.f);
            }
            if (ROUND) {
                v0 = rnd_tf(v0); v1 = rnd_tf(v1);
                v2 = rnd_tf(v2); v3 = rnd_tf(v3);
            }
            int col = colB + colRel;
            if (r0 < M) *(float2*)(Cb + (size_t)r0 * NoutB + col) = make_float2(v0, v1);
            if (r1 < M) *(float2*)(Cb + (size_t)r1 * NoutB + col) = make_float2(v2, v3);
        }
    }
}

// ---------------------------------------------------------------------------
// CSR build
// ---------------------------------------------------------------------------
__global__ void csr_hist(const int* __restrict__ tgtI, int* __restrict__ cnt, int E)
{
    int e = blockIdx.x * blockDim.x + threadIdx.x;
    if (e < E) atomicAdd(&cnt[tgtI[e]], 1);
}

__global__ void __launch_bounds__(1024)
csr_scan(const int* __restrict__ cnt, int* __restrict__ off, int* __restrict__ pos, int n)
{
    __shared__ int part[1024];
    const int t = threadIdx.x;
    const int CH = (n + 1023) / 1024;
    int vals[32];
    int base = t * CH;
    int local = 0;
    for (int i = 0; i < CH; i++) {
        int e = base + i;
        int v = (e < n) ? cnt[e] : 0;
        vals[i] = v;
        local += v;
    }
    part[t] = local;
    __syncthreads();
    for (int d = 1; d < 1024; d <<= 1) {
        int v = (t >= d) ? part[t - d] : 0;
        __syncthreads();
        part[t] += v;
        __syncthreads();
    }
    int run = (t > 0) ? part[t - 1] : 0;
    for (int i = 0; i < CH; i++) {
        int e = base + i;
        if (e < n) { off[e] = run; pos[e] = run; run += vals[i]; }
    }
    if (t == 1023) off[n] = part[1023];
}

__global__ void csr_scatter(const int* __restrict__ srcI, const int* __restrict__ tgtI,
                            int* __restrict__ pos, int* __restrict__ esrc, int E)
{
    int e = blockIdx.x * blockDim.x + threadIdx.x;
    if (e >= E) return;
    int slot = atomicAdd(&pos[tgtI[e]], 1);
    esrc[slot] = srcI[e];
}

// ---------------------------------------------------------------------------
// Attention over CSR: one warp per target node, two-pass, no atomics.
// Output agg is tf32-rounded (it feeds the Wo GEMM only).
// ---------------------------------------------------------------------------
__global__ void __launch_bounds__(256)
attn_csr(const float* __restrict__ qb, const float* __restrict__ kv,
         const int* __restrict__ off, const int* __restrict__ esrc,
         float* __restrict__ p, float* __restrict__ agg, int n)
{
    int node = (blockIdx.x * blockDim.x + threadIdx.x) >> 5;
    int lane = threadIdx.x & 31;
    if (node >= n) return;
    const int start = off[node];
    const int end   = off[node + 1];
    const int h     = lane >> 2;

    const float4* qr = (const float4*)(qb + (size_t)node * DD) + lane * 4;
    float4 q0 = qr[0], q1 = qr[1], q2 = qr[2], q3 = qr[3];

    float hmax = -INFINITY;
    for (int s = start; s < end; s++) {
        int sn = esrc[s];
        const float4* kr = (const float4*)(kv + (size_t)sn * 1024) + lane * 4;
        float4 k0 = kr[0], k1 = kr[1], k2 = kr[2], k3 = kr[3];
        float d = q0.x*k0.x + q0.y*k0.y + q0.z*k0.z + q0.w*k0.w;
        d += q1.x*k1.x + q1.y*k1.y + q1.z*k1.z + q1.w*k1.w;
        d += q2.x*k2.x + q2.y*k2.y + q2.z*k2.z + q2.w*k2.w;
        d += q3.x*k3.x + q3.y*k3.y + q3.z*k3.z + q3.w*k3.w;
        d += __shfl_xor_sync(0xffffffffu, d, 1);
        d += __shfl_xor_sync(0xffffffffu, d, 2);
        if ((lane & 3) == 0) p[(size_t)s * HH + h] = d;
        hmax = fmaxf(hmax, d);
    }

    float acc[16];
#pragma unroll
    for (int i = 0; i < 16; i++) acc[i] = 0.f;
    float hsum = 0.f;

    for (int s = start; s < end; s++) {
        int sn = esrc[s];
        float d = p[(size_t)s * HH + h];
        float w = expf(d - hmax);
        hsum += w;
        const float4* vr = (const float4*)(kv + (size_t)sn * 1024 + 512) + lane * 4;
        float4 v0 = vr[0], v1 = vr[1], v2 = vr[2], v3 = vr[3];
        acc[0]  += w * v0.x; acc[1]  += w * v0.y; acc[2]  += w * v0.z; acc[3]  += w * v0.w;
        acc[4]  += w * v1.x; acc[5]  += w * v1.y; acc[6]  += w * v1.z; acc[7]  += w * v1.w;
        acc[8]  += w * v2.x; acc[9]  += w * v2.y; acc[10] += w * v2.z; acc[11] += w * v2.w;
        acc[12] += w * v3.x; acc[13] += w * v3.y; acc[14] += w * v3.z; acc[15] += w * v3.w;
    }

    float inv = 1.f / (hsum + 1e-16f);
    float4* ag = (float4*)(agg + (size_t)node * DD) + lane * 4;
#pragma unroll
    for (int i = 0; i < 4; i++)
        ag[i] = make_float4(rnd_tf(acc[i*4+0]*inv), rnd_tf(acc[i*4+1]*inv),
                            rnd_tf(acc[i*4+2]*inv), rnd_tf(acc[i*4+3]*inv));
}

// ---------------------------------------------------------------------------
// BatchNorm over node dimension on z = a + b (residual fused)
// ---------------------------------------------------------------------------
__global__ void bn_stats(const float* __restrict__ a, const float* __restrict__ b,
                         float* __restrict__ sums, int n)
{
    int j = threadIdx.x;
    float sum = 0.f, sq = 0.f;
    for (int i = blockIdx.x; i < n; i += gridDim.x) {
        float z = a[(size_t)i * DD + j] + b[(size_t)i * DD + j];
        sum += z; sq += z * z;
    }
    atomicAdd(&sums[j], sum);
    atomicAdd(&sums[DD + j], sq);
}

__global__ void bn_finalize(const float* __restrict__ sums,
                            float* __restrict__ mu, float* __restrict__ rs, float invn)
{
    int j = threadIdx.x;
    float m = sums[j] * invn;
    float var = sums[DD + j] * invn - m * m;
    mu[j] = m;
    rs[j] = rsqrtf(var + 1e-5f);
}

// writes exact out (residual/LN path) and tf32-rounded outr (GEMM path)
__global__ void bn_apply(const float* __restrict__ a, const float* __restrict__ b,
                         const float* __restrict__ mu, const float* __restrict__ rs,
                         const float* __restrict__ g, const float* __restrict__ beta,
                         float* __restrict__ out, float* __restrict__ outr, int n)
{
    int idx = blockIdx.x * blockDim.x + threadIdx.x;
    if (idx >= n * DD) return;
    int j = idx & (DD - 1);
    float z = a[idx] + b[idx];
    float o = (z - mu[j]) * rs[j] * g[j] + beta[j];
    out[idx]  = o;
    outr[idx] = rnd_tf(o);
}

// ---------------------------------------------------------------------------
// Final per-row LayerNorm  (128 threads/row, 4 floats each)
// ---------------------------------------------------------------------------
__global__ void layernorm_k(const float* __restrict__ x, const float* __restrict__ g,
                            const float* __restrict__ b, float* __restrict__ out)
{
    int row = blockIdx.x;
    int t = threadIdx.x;
    const float4* xr = (const float4*)(x + (size_t)row * DD);
    float4 v = xr[t];
    float sum = v.x + v.y + v.z + v.w;
    float sq  = v.x * v.x + v.y * v.y + v.z * v.z + v.w * v.w;

#pragma unroll
    for (int o = 16; o > 0; o >>= 1) {
        sum += __shfl_xor_sync(0xffffffffu, sum, o);
        sq  += __shfl_xor_sync(0xffffffffu, sq, o);
    }
    __shared__ float sa[4], sb[4];
    int w = t >> 5, l = t & 31;
    if (l == 0) { sa[w] = sum; sb[w] = sq; }
    __syncthreads();
    sum = sa[0] + sa[1] + sa[2] + sa[3];
    sq  = sb[0] + sb[1] + sb[2] + sb[3];

    float mu = sum * (1.f / DD);
    float var = sq * (1.f / DD) - mu * mu;
    float rs = rsqrtf(var + 1e-5f);

    const float4* g4 = (const float4*)g;
    const float4* b4 = (const float4*)b;
    float4 gg = g4[t], bb = b4[t];
    float4 o;
    o.x = (v.x - mu) * rs * gg.x + bb.x;
    o.y = (v.y - mu) * rs * gg.y + bb.y;
    o.z = (v.z - mu) * rs * gg.z + bb.z;
    o.w = (v.w - mu) * rs * gg.w + bb.w;
    *(float4*)(out + (size_t)row * DD + t * 4) = o;
}

// ---------------------------------------------------------------------------
// Orchestration
// ---------------------------------------------------------------------------
extern "C" void kernel_launch(void* const* d_in, const int* in_sizes, int n_in,
                              void* d_out, int out_size)
{
    const float* src = (const float*)d_in[0];
    const int*   ei  = (const int*)  d_in[1];
    const float* Wq  = (const float*)d_in[2];
    const float* bq  = (const float*)d_in[3];
    const float* Wk  = (const float*)d_in[4];
    const float* Wv  = (const float*)d_in[5];
    const float* Wo  = (const float*)d_in[6];
    const float* bo  = (const float*)d_in[7];
    const float* W1  = (const float*)d_in[8];
    const float* b1  = (const float*)d_in[9];
    const float* W2  = (const float*)d_in[10];
    const float* b2  = (const float*)d_in[11];
    const float* g1  = (const float*)d_in[12];
    const float* be1 = (const float*)d_in[13];
    const float* g2  = (const float*)d_in[14];
    const float* be2 = (const float*)d_in[15];
    const float* lng = (const float*)d_in[16];
    const float* lnb = (const float*)d_in[17];
    float* outp = (float*)d_out;

    const int n = in_sizes[0] / DD;
    const int E = in_sizes[1] / 2;
    const int* srcI = ei;
    const int* tgtI = ei + E;

    float *qb, *kv, *agg, *tb, *x, *xr, *srctf, *ff, *p, *sums, *mu, *rs;
    float *wqkv, *bqkv, *woR, *w1R, *w2R;
    int *cnt, *off, *pos, *esrc;
    cudaGetSymbolAddress((void**)&qb,    g_qb);
    cudaGetSymbolAddress((void**)&kv,    g_kv);
    cudaGetSymbolAddress((void**)&agg,   g_agg);
    cudaGetSymbolAddress((void**)&tb,    g_t);
    cudaGetSymbolAddress((void**)&x,     g_x);
    cudaGetSymbolAddress((void**)&xr,    g_xr);
    cudaGetSymbolAddress((void**)&srctf, g_srctf);
    cudaGetSymbolAddress((void**)&ff,    g_ff);
    cudaGetSymbolAddress((void**)&p,     g_p);
    cudaGetSymbolAddress((void**)&sums,  g_sums);
    cudaGetSymbolAddress((void**)&mu,    g_mu);
    cudaGetSymbolAddress((void**)&rs,    g_rs);
    cudaGetSymbolAddress((void**)&wqkv,  g_wqkv);
    cudaGetSymbolAddress((void**)&bqkv,  g_bqkv);
    cudaGetSymbolAddress((void**)&woR,   g_woR);
    cudaGetSymbolAddress((void**)&w1R,   g_w1R);
    cudaGetSymbolAddress((void**)&w2R,   g_w2R);
    cudaGetSymbolAddress((void**)&cnt,   g_cnt);
    cudaGetSymbolAddress((void**)&off,   g_off);
    cudaGetSymbolAddress((void**)&pos,   g_pos);
    cudaGetSymbolAddress((void**)&esrc,  g_esrc);

    cudaFuncSetAttribute((const void*)gemm_tf32<false, false>,
                         cudaFuncAttributeMaxDynamicSharedMemorySize, GEMM_SMEM);
    cudaFuncSetAttribute((const void*)gemm_tf32<true, true>,
                         cudaFuncAttributeMaxDynamicSharedMemorySize, GEMM_SMEM);

    const dim3 gQKV(QKVW / 128, (n + 127) / 128);
    const dim3 gD(DD / 128, (n + 127) / 128);
    const dim3 gF(FF / 128, (n + 127) / 128);
    const int nDblocks = (n * DD + 255) / 256;

    // launches 0-2: packing + src rounding; launch 3: QKV GEMM (ncu samples #3)
    pack_qkv_w<<<(LLAY * QKVW * DD + 255) / 256, 256>>>(Wq, Wk, Wv, wqkv);
    pack_qkv_b<<<(LLAY * QKVW + 255) / 256, 256>>>(bq, bqkv);
    round_copy<<<nDblocks, 256>>>(src, srctf, n * DD);
    gemm_tf32<false, false><<<gQKV, 256, GEMM_SMEM>>>(srctf, wqkv, bqkv, qb, kv,
                                                      n, DD, QKVW, DD);

    // rounded weight copies + CSR build
    round_copy<<<(LLAY * DD * DD + 255) / 256, 256>>>(Wo, woR, LLAY * DD * DD);
    round_copy<<<(LLAY * FF * DD + 255) / 256, 256>>>(W1, w1R, LLAY * FF * DD);
    round_copy<<<(LLAY * DD * FF + 255) / 256, 256>>>(W2, w2R, LLAY * DD * FF);
    fill_i<<<(n + 1 + 255) / 256, 256>>>(cnt, 0, n + 1);
    csr_hist<<<(E + 255) / 256, 256>>>(tgtI, cnt, E);
    csr_scan<<<1, 1024>>>(cnt, off, pos, n);
    csr_scatter<<<(E + 255) / 256, 256>>>(srcI, tgtI, pos, esrc, E);

    const float* xinExact = src;   // exact residual input

    for (int l = 0; l < LLAY; l++) {
        const float* W1l = w1R + (size_t)l * FF * DD;
        const float* W2l = w2R + (size_t)l * DD * FF;
        const float* Wol = woR + (size_t)l * DD * DD;

        // fused q|k|v projection, split-routed into qb / kv buffers
        if (l > 0)
            gemm_tf32<false, false><<<gQKV, 256, GEMM_SMEM>>>(
                xr, wqkv + (size_t)l * QKVW * DD, bqkv + l * QKVW, qb, kv,
                n, DD, QKVW, DD);

        // attention over CSR (two-pass, no atomics; rounds agg)
        attn_csr<<<(n * 32 + 255) / 256, 256>>>(qb, kv, off, esrc, p, agg, n);

        // output projection
        gemm_tf32<false, false><<<gD, 256, GEMM_SMEM>>>(agg, Wol, bo + l * DD, tb,
                                                        nullptr, n, DD, DD, 0);

        // batchnorm 1 (residual xinExact + tb) -> x (exact), xr (rounded)
        fill_f<<<(2 * DD + 255) / 256, 256>>>(sums, 0.f, 2 * DD);
        bn_stats<<<256, DD>>>(xinExact, tb, sums, n);
        bn_finalize<<<1, DD>>>(sums, mu, rs, 1.f / (float)n);
        bn_apply<<<nDblocks, 256>>>(xinExact, tb, mu, rs,
                                    g1 + l * DD, be1 + l * DD, x, xr, n);

        // feedforward: FF1 rounds its output (feeds FF2)
        gemm_tf32<true, true  ><<<gF, 256, GEMM_SMEM>>>(xr, W1l, b1 + l * FF, ff,
                                                        nullptr, n, DD, FF, 0);
        gemm_tf32<false, false><<<gD, 256, GEMM_SMEM>>>(ff, W2l, b2 + l * DD, tb,
                                                        nullptr, n, FF, DD, 0);

        // batchnorm 2 (residual x + tb) -> x (exact), xr (rounded)
        fill_f<<<(2 * DD + 255) / 256, 256>>>(sums, 0.f, 2 * DD);
        bn_stats<<<256, DD>>>(x, tb, sums, n);
        bn_finalize<<<1, DD>>>(sums, mu, rs, 1.f / (float)n);
        bn_apply<<<nDblocks, 256>>>(x, tb, mu, rs,
                                    g2 + l * DD, be2 + l * DD, x, xr, n);

        xinExact = x;
    }

    // final layernorm -> output (exact path)
    layernorm_k<<<n, 128>>>(x, lng, lnb, outp);
}

// round 10
// speedup vs baseline: 1.2057x; 1.0265x over previous
#include <cuda_runtime.h>
#include <math.h>
#include <stdint.h>

// Problem constants (fixed by the reference generator)
#define NN   20000
#define DD   512
#define HH   8
#define DHH  64
#define FF   2048
#define LLAY 2
#define EE   320000
#define QKVW 1536   // packed q|k|v projection width

// ---------------------------------------------------------------------------
// Scratch (device globals: alloc-free rule)
// ---------------------------------------------------------------------------
__device__ float g_qb  [NN * DD];        // q rows (read once per node)
__device__ float g_kv  [NN * 2 * DD];    // compact k|v rows (gather working set)
__device__ float g_agg [NN * DD];        // attn output (tf32-rounded)
__device__ float g_t   [NN * DD];
__device__ float g_x   [NN * DD];        // exact activations (residual/LN path)
__device__ float g_xr  [NN * DD];        // tf32-rounded activations (GEMM path)
__device__ float g_srctf[NN * DD];       // tf32-rounded src
__device__ float g_ff  [NN * FF];        // FF1 output (tf32-rounded)
__device__ float g_p   [EE * HH];
__device__ float g_part[256 * 1024];     // BN partial sums [block][sum|sq]
__device__ float g_mu  [DD];
__device__ float g_rs  [DD];
__device__ float g_wqkv[LLAY * QKVW * DD];   // packed+rounded
__device__ float g_bqkv[LLAY * QKVW];
__device__ float g_woR [LLAY * DD * DD];     // rounded weight copies
__device__ float g_w1R [LLAY * FF * DD];
__device__ float g_w2R [LLAY * DD * FF];
__device__ int g_cnt [NN + 1];
__device__ int g_off [NN + 1];
__device__ int g_pos [NN];
__device__ int g_esrc[EE];

// ---------------------------------------------------------------------------
// helpers
// ---------------------------------------------------------------------------
__device__ __forceinline__ uint32_t smem_u32(const void* p) {
    uint32_t a;
    asm("{ .reg .u64 t; cvta.to.shared.u64 t, %1; cvt.u32.u64 %0, t; }"
        : "=r"(a) : "l"(p));
    return a;
}
__device__ __forceinline__ void cp16(uint32_t dst, const void* src, int szbytes) {
    asm volatile("cp.async.cg.shared.global [%0], [%1], 16, %2;"
                 :: "r"(dst), "l"(src), "r"(szbytes) : "memory");
}
#define CP_COMMIT() asm volatile("cp.async.commit_group;" ::: "memory")
#define CP_WAIT(n)  asm volatile("cp.async.wait_group %0;" :: "n"(n) : "memory")

__device__ __forceinline__ float rnd_tf(float x) {
    uint32_t r;
    asm("cvt.rna.tf32.f32 %0, %1;" : "=r"(r) : "f"(x));
    return __uint_as_float(r);
}

// ---------------------------------------------------------------------------
// Utility kernels
// ---------------------------------------------------------------------------
__global__ void fill_i(int* __restrict__ p, int v, int n) {
    int i = blockIdx.x * blockDim.x + threadIdx.x;
    if (i < n) p[i] = v;
}
__global__ void round_copy(const float* __restrict__ in, float* __restrict__ out, int n)
{
    int i = blockIdx.x * blockDim.x + threadIdx.x;
    if (i < n) out[i] = rnd_tf(in[i]);
}

// ---------------------------------------------------------------------------
// Weight packing (rounded): r<512: Wq*0.125 | r<1024: Wk | else Wv
// ---------------------------------------------------------------------------
__global__ void pack_qkv_w(const float* __restrict__ Wq, const float* __restrict__ Wk,
                           const float* __restrict__ Wv, float* __restrict__ wout)
{
    int idx = blockIdx.x * blockDim.x + threadIdx.x;
    const int total = LLAY * QKVW * DD;
    if (idx >= total) return;
    int l = idx / (QKVW * DD);
    int rem = idx % (QKVW * DD);
    int r = rem / DD, c = rem % DD;
    float val;
    if (r < 512)       val = Wq[(size_t)l * DD * DD + (size_t)r * DD + c] * 0.125f;
    else if (r < 1024) val = Wk[(size_t)l * DD * DD + (size_t)(r - 512) * DD + c];
    else               val = Wv[(size_t)l * DD * DD + (size_t)(r - 1024) * DD + c];
    wout[idx] = rnd_tf(val);
}
__global__ void pack_qkv_b(const float* __restrict__ bq, float* __restrict__ bout)
{
    int idx = blockIdx.x * blockDim.x + threadIdx.x;
    if (idx >= LLAY * QKVW) return;
    int l = idx / QKVW, r = idx % QKVW;
    bout[idx] = (r < 512) ? bq[l * DD + r] * 0.125f : 0.f;
}

// ---------------------------------------------------------------------------
// TF32 tensor-core GEMM (mma.sync), cp.async 3-stage pipeline, ONE barrier
// per k-tile (the start-of-iteration barrier already orders compute(kt-1)
// before issue(kt+2), which reuses that stage).
// ALL operands pre-rounded tf32 values in gmem (idempotent rounding).
// ---------------------------------------------------------------------------
#define TILE_F (128 * 36)
#define GEMM_SMEM (6 * TILE_F * (int)sizeof(float))  // 110592 B

template <bool RELU, bool ROUND>
__global__ void __launch_bounds__(256, 2)
gemm_tf32(const float* __restrict__ A, const float* __restrict__ W,
          const float* __restrict__ bias, float* __restrict__ Cq,
          float* __restrict__ Ckv, int M, int K, int Nout, int split)
{
    extern __shared__ float smemf[];
    float* AsB = smemf;                 // [3][128][36]
    float* BsB = smemf + 3 * TILE_F;    // [3][128][36]
    const uint32_t AsAddr = smem_u32(AsB);
    const uint32_t BsAddr = smem_u32(BsB);

    const int tid  = threadIdx.x;
    const int lane = tid & 31;
    const int warp = tid >> 5;
    const int wm   = warp >> 2;     // 0..1
    const int wn   = warp & 3;      // 0..3
    const int g    = lane >> 2;     // 0..7
    const int c    = lane & 3;      // 0..3
    const int rowBase = blockIdx.y * 128;
    const int colBase = blockIdx.x * 128;

    float* Cb;
    int NoutB, colB;
    if (split > 0 && colBase >= split) {
        Cb = Ckv; NoutB = Nout - split; colB = colBase - split;
    } else if (split > 0) {
        Cb = Cq;  NoutB = split;        colB = colBase;
    } else {
        Cb = Cq;  NoutB = Nout;         colB = colBase;
    }

    float acc[4][4][4];
#pragma unroll
    for (int mt = 0; mt < 4; mt++)
#pragma unroll
        for (int nt = 0; nt < 4; nt++)
#pragma unroll
            for (int i = 0; i < 4; i++) acc[mt][nt][i] = 0.f;

    auto issue = [&](int kt) {
        const int k0 = kt << 5;
        const int st = kt % 3;
        const uint32_t Ad = AsAddr + (uint32_t)(st * TILE_F) * 4u;
        const uint32_t Bd = BsAddr + (uint32_t)(st * TILE_F) * 4u;
#pragma unroll
        for (int i = 0; i < 4; i++) {
            int li = tid + i * 256;
            int r  = li >> 3;
            int q  = li & 7;
            int ar = rowBase + r;
            int sz = (ar < M) ? 16 : 0;
            int arc = (ar < M) ? ar : (M - 1);
            cp16(Ad + (uint32_t)(r * 36 + q * 4) * 4u,
                 A + (size_t)arc * K + k0 + q * 4, sz);
            cp16(Bd + (uint32_t)(r * 36 + q * 4) * 4u,
                 W + (size_t)(colBase + r) * K + k0 + q * 4, 16);
        }
        CP_COMMIT();
    };

    const int NT = K >> 5;
    issue(0);
    issue(1);

    for (int kt = 0; kt < NT; kt++) {
        if (kt + 1 < NT) { CP_WAIT(1); } else { CP_WAIT(0); }
        __syncthreads();
        if (kt + 2 < NT) issue(kt + 2);

        const float* As = AsB + (kt % 3) * TILE_F;
        const float* Bs = BsB + (kt % 3) * TILE_F;

#pragma unroll
        for (int ks = 0; ks < 4; ks++) {
            uint32_t af[4][4];
            uint32_t bf[4][2];
#pragma unroll
            for (int mt = 0; mt < 4; mt++) {
                int r0 = wm * 64 + mt * 16 + g;
                af[mt][0] = __float_as_uint(As[(r0    ) * 36 + ks * 8 + c    ]);
                af[mt][1] = __float_as_uint(As[(r0 + 8) * 36 + ks * 8 + c    ]);
                af[mt][2] = __float_as_uint(As[(r0    ) * 36 + ks * 8 + c + 4]);
                af[mt][3] = __float_as_uint(As[(r0 + 8) * 36 + ks * 8 + c + 4]);
            }
#pragma unroll
            for (int nt = 0; nt < 4; nt++) {
                int n0 = wn * 32 + nt * 8 + g;
                bf[nt][0] = __float_as_uint(Bs[n0 * 36 + ks * 8 + c    ]);
                bf[nt][1] = __float_as_uint(Bs[n0 * 36 + ks * 8 + c + 4]);
            }
#pragma unroll
            for (int mt = 0; mt < 4; mt++)
#pragma unroll
                for (int nt = 0; nt < 4; nt++)
                    asm volatile(
                        "mma.sync.aligned.m16n8k8.row.col.f32.tf32.tf32.f32 "
                        "{%0,%1,%2,%3}, {%4,%5,%6,%7}, {%8,%9}, {%0,%1,%2,%3};"
                        : "+f"(acc[mt][nt][0]), "+f"(acc[mt][nt][1]),
                          "+f"(acc[mt][nt][2]), "+f"(acc[mt][nt][3])
                        : "r"(af[mt][0]), "r"(af[mt][1]),
                          "r"(af[mt][2]), "r"(af[mt][3]),
                          "r"(bf[nt][0]), "r"(bf[nt][1]));
        }
        // no trailing barrier: next iteration's barrier protects stage reuse
    }

    // Epilogue: bias, relu, optional tf32 rounding, split-routed stores
#pragma unroll
    for (int mt = 0; mt < 4; mt++) {
        int r0 = rowBase + wm * 64 + mt * 16 + g;
        int r1 = r0 + 8;
#pragma unroll
        for (int nt = 0; nt < 4; nt++) {
            int colRel = wn * 32 + nt * 8 + c * 2;
            float2 bb = *(const float2*)(bias + colBase + colRel);
            float v0 = acc[mt][nt][0] + bb.x;
            float v1 = acc[mt][nt][1] + bb.y;
            float v2 = acc[mt][nt][2] + bb.x;
            float v3 = acc[mt][nt][3] + bb.y;
            if (RELU) {
                v0 = fmaxf(v0, 0.f); v1 = fmaxf(v1, 0.f);
                v2 = fmaxf(v2, 0.f); v3 = fmaxf(v3, 0.f);
            }
            if (ROUND) {
                v0 = rnd_tf(v0); v1 = rnd_tf(v1);
                v2 = rnd_tf(v2); v3 = rnd_tf(v3);
            }
            int col = colB + colRel;
            if (r0 < M) *(float2*)(Cb + (size_t)r0 * NoutB + col) = make_float2(v0, v1);
            if (r1 < M) *(float2*)(Cb + (size_t)r1 * NoutB + col) = make_float2(v2, v3);
        }
    }
}

// ---------------------------------------------------------------------------
// CSR build
// ---------------------------------------------------------------------------
__global__ void csr_hist(const int* __restrict__ tgtI, int* __restrict__ cnt, int E)
{
    int e = blockIdx.x * blockDim.x + threadIdx.x;
    if (e < E) atomicAdd(&cnt[tgtI[e]], 1);
}

__global__ void __launch_bounds__(1024)
csr_scan(const int* __restrict__ cnt, int* __restrict__ off, int* __restrict__ pos, int n)
{
    __shared__ int part[1024];
    const int t = threadIdx.x;
    const int CH = (n + 1023) / 1024;
    int vals[32];
    int base = t * CH;
    int local = 0;
    for (int i = 0; i < CH; i++) {
        int e = base + i;
        int v = (e < n) ? cnt[e] : 0;
        vals[i] = v;
        local += v;
    }
    part[t] = local;
    __syncthreads();
    for (int d = 1; d < 1024; d <<= 1) {
        int v = (t >= d) ? part[t - d] : 0;
        __syncthreads();
        part[t] += v;
        __syncthreads();
    }
    int run = (t > 0) ? part[t - 1] : 0;
    for (int i = 0; i < CH; i++) {
        int e = base + i;
        if (e < n) { off[e] = run; pos[e] = run; run += vals[i]; }
    }
    if (t == 1023) off[n] = part[1023];
}

__global__ void csr_scatter(const int* __restrict__ srcI, const int* __restrict__ tgtI,
                            int* __restrict__ pos, int* __restrict__ esrc, int E)
{
    int e = blockIdx.x * blockDim.x + threadIdx.x;
    if (e >= E) return;
    int slot = atomicAdd(&pos[tgtI[e]], 1);
    esrc[slot] = srcI[e];
}

// ---------------------------------------------------------------------------
// Attention over CSR: one warp per target node, two-pass, no atomics.
// 2-stage software pipeline: edge s+1's row loads issue before edge s's math.
// ---------------------------------------------------------------------------
__global__ void __launch_bounds__(256)
attn_csr(const float* __restrict__ qb, const float* __restrict__ kv,
         const int* __restrict__ off, const int* __restrict__ esrc,
         float* __restrict__ p, float* __restrict__ agg, int n)
{
    int node = (blockIdx.x * blockDim.x + threadIdx.x) >> 5;
    int lane = threadIdx.x & 31;
    if (node >= n) return;
    const int start = off[node];
    const int end   = off[node + 1];
    const int h     = lane >> 2;

    const float4* qr = (const float4*)(qb + (size_t)node * DD) + lane * 4;
    float4 q0 = qr[0], q1 = qr[1], q2 = qr[2], q3 = qr[3];

    float hmax = -INFINITY;
    if (start < end) {
        int sn = esrc[start];
        const float4* kr = (const float4*)(kv + (size_t)sn * 1024) + lane * 4;
        float4 k0 = kr[0], k1 = kr[1], k2 = kr[2], k3 = kr[3];
        for (int s = start; s < end; s++) {
            float4 n0, n1, n2, n3;
            if (s + 1 < end) {
                int sn2 = esrc[s + 1];
                const float4* nr = (const float4*)(kv + (size_t)sn2 * 1024) + lane * 4;
                n0 = nr[0]; n1 = nr[1]; n2 = nr[2]; n3 = nr[3];
            }
            float d = q0.x*k0.x + q0.y*k0.y + q0.z*k0.z + q0.w*k0.w;
            d += q1.x*k1.x + q1.y*k1.y + q1.z*k1.z + q1.w*k1.w;
            d += q2.x*k2.x + q2.y*k2.y + q2.z*k2.z + q2.w*k2.w;
            d += q3.x*k3.x + q3.y*k3.y + q3.z*k3.z + q3.w*k3.w;
            d += __shfl_xor_sync(0xffffffffu, d, 1);
            d += __shfl_xor_sync(0xffffffffu, d, 2);
            if ((lane & 3) == 0) p[(size_t)s * HH + h] = d;
            hmax = fmaxf(hmax, d);
            if (s + 1 < end) { k0 = n0; k1 = n1; k2 = n2; k3 = n3; }
        }
    }

    float acc[16];
#pragma unroll
    for (int i = 0; i < 16; i++) acc[i] = 0.f;
    float hsum = 0.f;

    if (start < end) {
        int sn = esrc[start];
        const float4* vr = (const float4*)(kv + (size_t)sn * 1024 + 512) + lane * 4;
        float4 v0 = vr[0], v1 = vr[1], v2 = vr[2], v3 = vr[3];
        float dcur = p[(size_t)start * HH + h];
        for (int s = start; s < end; s++) {
            float4 n0, n1, n2, n3;
            float dnxt;
            if (s + 1 < end) {
                int sn2 = esrc[s + 1];
                const float4* nr = (const float4*)(kv + (size_t)sn2 * 1024 + 512) + lane * 4;
                n0 = nr[0]; n1 = nr[1]; n2 = nr[2]; n3 = nr[3];
                dnxt = p[(size_t)(s + 1) * HH + h];
            }
            float w = expf(dcur - hmax);
            hsum += w;
            acc[0]  += w * v0.x; acc[1]  += w * v0.y; acc[2]  += w * v0.z; acc[3]  += w * v0.w;
            acc[4]  += w * v1.x; acc[5]  += w * v1.y; acc[6]  += w * v1.z; acc[7]  += w * v1.w;
            acc[8]  += w * v2.x; acc[9]  += w * v2.y; acc[10] += w * v2.z; acc[11] += w * v2.w;
            acc[12] += w * v3.x; acc[13] += w * v3.y; acc[14] += w * v3.z; acc[15] += w * v3.w;
            if (s + 1 < end) {
                v0 = n0; v1 = n1; v2 = n2; v3 = n3; dcur = dnxt;
            }
        }
    }

    float inv = 1.f / (hsum + 1e-16f);
    float4* ag = (float4*)(agg + (size_t)node * DD) + lane * 4;
#pragma unroll
    for (int i = 0; i < 4; i++)
        ag[i] = make_float4(rnd_tf(acc[i*4+0]*inv), rnd_tf(acc[i*4+1]*inv),
                            rnd_tf(acc[i*4+2]*inv), rnd_tf(acc[i*4+3]*inv));
}

// ---------------------------------------------------------------------------
// BatchNorm over node dimension on z = a + b (residual fused); partial sums
// to g_part (no atomics, no fill), reduced in bn_finalize.
// ---------------------------------------------------------------------------
__global__ void bn_stats(const float* __restrict__ a, const float* __restrict__ b,
                         float* __restrict__ part, int n)
{
    int j = threadIdx.x;     // 512 = one per feature
    int blk = blockIdx.x;    // 256 blocks
    float sum = 0.f, sq = 0.f;
    for (int i = blk; i < n; i += 256) {
        float z = a[(size_t)i * DD + j] + b[(size_t)i * DD + j];
        sum += z; sq += z * z;
    }
    part[blk * 1024 + j]       = sum;
    part[blk * 1024 + 512 + j] = sq;
}

__global__ void bn_finalize(const float* __restrict__ part,
                            float* __restrict__ mu, float* __restrict__ rs, float invn)
{
    int j = threadIdx.x;
    float s = 0.f, q = 0.f;
    for (int b = 0; b < 256; b++) {
        s += part[b * 1024 + j];
        q += part[b * 1024 + 512 + j];
    }
    float m = s * invn;
    float var = q * invn - m * m;
    mu[j] = m;
    rs[j] = rsqrtf(var + 1e-5f);
}

// writes exact out (residual/LN path) and tf32-rounded outr (GEMM path)
__global__ void bn_apply(const float* __restrict__ a, const float* __restrict__ b,
                         const float* __restrict__ mu, const float* __restrict__ rs,
                         const float* __restrict__ g, const float* __restrict__ beta,
                         float* __restrict__ out, float* __restrict__ outr, int n)
{
    int idx = blockIdx.x * blockDim.x + threadIdx.x;
    if (idx >= n * DD) return;
    int j = idx & (DD - 1);
    float z = a[idx] + b[idx];
    float o = (z - mu[j]) * rs[j] * g[j] + beta[j];
    out[idx]  = o;
    outr[idx] = rnd_tf(o);
}

// ---------------------------------------------------------------------------
// Final per-row LayerNorm  (128 threads/row, 4 floats each)
// ---------------------------------------------------------------------------
__global__ void layernorm_k(const float* __restrict__ x, const float* __restrict__ g,
                            const float* __restrict__ b, float* __restrict__ out)
{
    int row = blockIdx.x;
    int t = threadIdx.x;
    const float4* xr = (const float4*)(x + (size_t)row * DD);
    float4 v = xr[t];
    float sum = v.x + v.y + v.z + v.w;
    float sq  = v.x * v.x + v.y * v.y + v.z * v.z + v.w * v.w;

#pragma unroll
    for (int o = 16; o > 0; o >>= 1) {
        sum += __shfl_xor_sync(0xffffffffu, sum, o);
        sq  += __shfl_xor_sync(0xffffffffu, sq, o);
    }
    __shared__ float sa[4], sb[4];
    int w = t >> 5, l = t & 31;
    if (l == 0) { sa[w] = sum; sb[w] = sq; }
    __syncthreads();
    sum = sa[0] + sa[1] + sa[2] + sa[3];
    sq  = sb[0] + sb[1] + sb[2] + sb[3];

    float mu = sum * (1.f / DD);
    float var = sq * (1.f / DD) - mu * mu;
    float rs = rsqrtf(var + 1e-5f);

    const float4* g4 = (const float4*)g;
    const float4* b4 = (const float4*)b;
    float4 gg = g4[t], bb = b4[t];
    float4 o;
    o.x = (v.x - mu) * rs * gg.x + bb.x;
    o.y = (v.y - mu) * rs * gg.y + bb.y;
    o.z = (v.z - mu) * rs * gg.z + bb.z;
    o.w = (v.w - mu) * rs * gg.w + bb.w;
    *(float4*)(out + (size_t)row * DD + t * 4) = o;
}

// ---------------------------------------------------------------------------
// Orchestration
// ---------------------------------------------------------------------------
extern "C" void kernel_launch(void* const* d_in, const int* in_sizes, int n_in,
                              void* d_out, int out_size)
{
    const float* src = (const float*)d_in[0];
    const int*   ei  = (const int*)  d_in[1];
    const float* Wq  = (const float*)d_in[2];
    const float* bq  = (const float*)d_in[3];
    const float* Wk  = (const float*)d_in[4];
    const float* Wv  = (const float*)d_in[5];
    const float* Wo  = (const float*)d_in[6];
    const float* bo  = (const float*)d_in[7];
    const float* W1  = (const float*)d_in[8];
    const float* b1  = (const float*)d_in[9];
    const float* W2  = (const float*)d_in[10];
    const float* b2  = (const float*)d_in[11];
    const float* g1  = (const float*)d_in[12];
    const float* be1 = (const float*)d_in[13];
    const float* g2  = (const float*)d_in[14];
    const float* be2 = (const float*)d_in[15];
    const float* lng = (const float*)d_in[16];
    const float* lnb = (const float*)d_in[17];
    float* outp = (float*)d_out;

    const int n = in_sizes[0] / DD;
    const int E = in_sizes[1] / 2;
    const int* srcI = ei;
    const int* tgtI = ei + E;

    float *qb, *kv, *agg, *tb, *x, *xr, *srctf, *ff, *p, *part, *mu, *rs;
    float *wqkv, *bqkv, *woR, *w1R, *w2R;
    int *cnt, *off, *pos, *esrc;
    cudaGetSymbolAddress((void**)&qb,    g_qb);
    cudaGetSymbolAddress((void**)&kv,    g_kv);
    cudaGetSymbolAddress((void**)&agg,   g_agg);
    cudaGetSymbolAddress((void**)&tb,    g_t);
    cudaGetSymbolAddress((void**)&x,     g_x);
    cudaGetSymbolAddress((void**)&xr,    g_xr);
    cudaGetSymbolAddress((void**)&srctf, g_srctf);
    cudaGetSymbolAddress((void**)&ff,    g_ff);
    cudaGetSymbolAddress((void**)&p,     g_p);
    cudaGetSymbolAddress((void**)&part,  g_part);
    cudaGetSymbolAddress((void**)&mu,    g_mu);
    cudaGetSymbolAddress((void**)&rs,    g_rs);
    cudaGetSymbolAddress((void**)&wqkv,  g_wqkv);
    cudaGetSymbolAddress((void**)&bqkv,  g_bqkv);
    cudaGetSymbolAddress((void**)&woR,   g_woR);
    cudaGetSymbolAddress((void**)&w1R,   g_w1R);
    cudaGetSymbolAddress((void**)&w2R,   g_w2R);
    cudaGetSymbolAddress((void**)&cnt,   g_cnt);
    cudaGetSymbolAddress((void**)&off,   g_off);
    cudaGetSymbolAddress((void**)&pos,   g_pos);
    cudaGetSymbolAddress((void**)&esrc,  g_esrc);

    cudaFuncSetAttribute((const void*)gemm_tf32<false, false>,
                         cudaFuncAttributeMaxDynamicSharedMemorySize, GEMM_SMEM);
    cudaFuncSetAttribute((const void*)gemm_tf32<true, true>,
                         cudaFuncAttributeMaxDynamicSharedMemorySize, GEMM_SMEM);

    const dim3 gQKV(QKVW / 128, (n + 127) / 128);
    const dim3 gD(DD / 128, (n + 127) / 128);
    const dim3 gF(FF / 128, (n + 127) / 128);
    const int nDblocks = (n * DD + 255) / 256;

    // launches 0-2: packing + src rounding; launch 3: QKV GEMM (ncu samples #3)
    pack_qkv_w<<<(LLAY * QKVW * DD + 255) / 256, 256>>>(Wq, Wk, Wv, wqkv);
    pack_qkv_b<<<(LLAY * QKVW + 255) / 256, 256>>>(bq, bqkv);
    round_copy<<<nDblocks, 256>>>(src, srctf, n * DD);
    gemm_tf32<false, false><<<gQKV, 256, GEMM_SMEM>>>(srctf, wqkv, bqkv, qb, kv,
                                                      n, DD, QKVW, DD);

    // rounded weight copies + CSR build
    round_copy<<<(LLAY * DD * DD + 255) / 256, 256>>>(Wo, woR, LLAY * DD * DD);
    round_copy<<<(LLAY * FF * DD + 255) / 256, 256>>>(W1, w1R, LLAY * FF * DD);
    round_copy<<<(LLAY * DD * FF + 255) / 256, 256>>>(W2, w2R, LLAY * DD * FF);
    fill_i<<<(n + 1 + 255) / 256, 256>>>(cnt, 0, n + 1);
    csr_hist<<<(E + 255) / 256, 256>>>(tgtI, cnt, E);
    csr_scan<<<1, 1024>>>(cnt, off, pos, n);
    csr_scatter<<<(E + 255) / 256, 256>>>(srcI, tgtI, pos, esrc, E);

    const float* xinExact = src;   // exact residual input

    for (int l = 0; l < LLAY; l++) {
        const float* W1l = w1R + (size_t)l * FF * DD;
        const float* W2l = w2R + (size_t)l * DD * FF;
        const float* Wol = woR + (size_t)l * DD * DD;

        // fused q|k|v projection, split-routed into qb / kv buffers
        if (l > 0)
            gemm_tf32<false, false><<<gQKV, 256, GEMM_SMEM>>>(
                xr, wqkv + (size_t)l * QKVW * DD, bqkv + l * QKVW, qb, kv,
                n, DD, QKVW, DD);

        // attention over CSR (two-pass, pipelined gathers; rounds agg)
        attn_csr<<<(n * 32 + 255) / 256, 256>>>(qb, kv, off, esrc, p, agg, n);

        // output projection
        gemm_tf32<false, false><<<gD, 256, GEMM_SMEM>>>(agg, Wol, bo + l * DD, tb,
                                                        nullptr, n, DD, DD, 0);

        // batchnorm 1 (residual xinExact + tb) -> x (exact), xr (rounded)
        bn_stats<<<256, DD>>>(xinExact, tb, part, n);
        bn_finalize<<<1, DD>>>(part, mu, rs, 1.f / (float)n);
        bn_apply<<<nDblocks, 256>>>(xinExact, tb, mu, rs,
                                    g1 + l * DD, be1 + l * DD, x, xr, n);

        // feedforward: FF1 rounds its output (feeds FF2)
        gemm_tf32<true, true  ><<<gF, 256, GEMM_SMEM>>>(xr, W1l, b1 + l * FF, ff,
                                                        nullptr, n, DD, FF, 0);
        gemm_tf32<false, false><<<gD, 256, GEMM_SMEM>>>(ff, W2l, b2 + l * DD, tb,
                                                        nullptr, n, FF, DD, 0);

        // batchnorm 2 (residual x + tb) -> x (exact), xr (rounded)
        bn_stats<<<256, DD>>>(x, tb, part, n);
        bn_finalize<<<1, DD>>>(part, mu, rs, 1.f / (float)n);
        bn_apply<<<nDblocks, 256>>>(x, tb, mu, rs,
                                    g2 + l * DD, be2 + l * DD, x, xr, n);

        xinExact = x;
    }

    // final layernorm -> output (exact path)
    layernorm_k<<<n, 128>>>(x, lng, lnb, outp);
}

// round 11
// speedup vs baseline: 1.2922x; 1.0718x over previous
#include <cuda_runtime.h>
#include <math.h>
#include <stdint.h>

// Problem constants (fixed by the reference generator)
#define NN   20000
#define DD   512
#define HH   8
#define DHH  64
#define FF   2048
#define LLAY 2
#define EE   320000
#define QKVW 1536   // packed q|k|v projection width

// k-permutation within 8-groups: stored order [k0,k4,k1,k5,k2,k6,k3,k7].
// perm(k)  = position of original k;  iperm(p) = original k at position p.
#define PERM8(k)  ((((k) & 3) << 1) | (((k) >> 2) & 1))
#define IPERM8(p) ((((p) & 1) << 2) | (((p) & 7) >> 1))

// ---------------------------------------------------------------------------
// Scratch (device globals: alloc-free rule)
// ---------------------------------------------------------------------------
__device__ float g_qb  [NN * DD];        // q rows (permuted space)
__device__ float g_kv  [NN * 2 * DD];    // compact k|v rows (permuted space)
__device__ float g_agg [NN * DD];        // attn output (permuted, tf32-rounded)
__device__ float g_t   [NN * DD];        // Wo / FF2 output (original space)
__device__ float g_x   [NN * DD];        // exact activations (original space)
__device__ float g_xr  [NN * DD];        // rounded+permuted activations (GEMM A)
__device__ float g_srctf[NN * DD];       // rounded+permuted src
__device__ float g_ff  [NN * FF];        // FF1 output (rounded+permuted)
__device__ float g_p   [EE * HH];
__device__ float g_part[256 * 1024];     // BN partial sums
__device__ float g_mu  [DD];
__device__ float g_rs  [DD];
__device__ float g_wqkv[LLAY * QKVW * DD];   // packed+rounded+permuted
__device__ float g_bqkv[LLAY * QKVW];
__device__ float g_woR [LLAY * DD * DD];     // rounded+permuted weights
__device__ float g_w1R [LLAY * FF * DD];
__device__ float g_w2R [LLAY * DD * FF];
__device__ int g_cnt [NN + 1];
__device__ int g_off [NN + 1];
__device__ int g_pos [NN];
__device__ int g_esrc[EE];

// ---------------------------------------------------------------------------
// helpers
// ---------------------------------------------------------------------------
__device__ __forceinline__ uint32_t smem_u32(const void* p) {
    uint32_t a;
    asm("{ .reg .u64 t; cvta.to.shared.u64 t, %1; cvt.u32.u64 %0, t; }"
        : "=r"(a) : "l"(p));
    return a;
}
__device__ __forceinline__ void cp16(uint32_t dst, const void* src, int szbytes) {
    asm volatile("cp.async.cg.shared.global [%0], [%1], 16, %2;"
                 :: "r"(dst), "l"(src), "r"(szbytes) : "memory");
}
#define CP_COMMIT() asm volatile("cp.async.commit_group;" ::: "memory")
#define CP_WAIT(n)  asm volatile("cp.async.wait_group %0;" :: "n"(n) : "memory")

__device__ __forceinline__ float rnd_tf(float x) {
    uint32_t r;
    asm("cvt.rna.tf32.f32 %0, %1;" : "=r"(r) : "f"(x));
    return __uint_as_float(r);
}

// ---------------------------------------------------------------------------
// Utility kernels
// ---------------------------------------------------------------------------
__global__ void fill_i(int* __restrict__ p, int v, int n) {
    int i = blockIdx.x * blockDim.x + threadIdx.x;
    if (i < n) p[i] = v;
}
// rounded + k-permuted copy (row widths are multiples of 8, so idx%8 works)
__global__ void round_copy_perm(const float* __restrict__ in, float* __restrict__ out, int n)
{
    int i = blockIdx.x * blockDim.x + threadIdx.x;
    if (i >= n) return;
    int src = (i & ~7) | IPERM8(i & 7);
    out[i] = rnd_tf(in[src]);
}

// ---------------------------------------------------------------------------
// Weight packing (rounded + k-permuted): r<512: Wq*0.125 | <1024: Wk | else Wv
// ---------------------------------------------------------------------------
__global__ void pack_qkv_w(const float* __restrict__ Wq, const float* __restrict__ Wk,
                           const float* __restrict__ Wv, float* __restrict__ wout)
{
    int idx = blockIdx.x * blockDim.x + threadIdx.x;
    const int total = LLAY * QKVW * DD;
    if (idx >= total) return;
    int l = idx / (QKVW * DD);
    int rem = idx % (QKVW * DD);
    int r = rem / DD, cpos = rem % DD;
    int c = (cpos & ~7) | IPERM8(cpos & 7);   // source k for this position
    float val;
    if (r < 512)       val = Wq[(size_t)l * DD * DD + (size_t)r * DD + c] * 0.125f;
    else if (r < 1024) val = Wk[(size_t)l * DD * DD + (size_t)(r - 512) * DD + c];
    else               val = Wv[(size_t)l * DD * DD + (size_t)(r - 1024) * DD + c];
    wout[idx] = rnd_tf(val);
}
__global__ void pack_qkv_b(const float* __restrict__ bq, float* __restrict__ bout)
{
    int idx = blockIdx.x * blockDim.x + threadIdx.x;
    if (idx >= LLAY * QKVW) return;
    int l = idx / QKVW, r = idx % QKVW;
    bout[idx] = (r < 512) ? bq[l * DD + r] * 0.125f : 0.f;
}

// ---------------------------------------------------------------------------
// TF32 tensor-core GEMM (mma.sync), cp.async 3-stage pipeline.
// All operands pre-rounded tf32 values, k-permuted in gmem so each thread's
// fragment pair (k=c, k=c+4) is one contiguous float2 -> LDS.64.
// Smem: 32-float rows + XOR chunk swizzle (chunk ^= (row&3)<<2), conflict-free.
// PERM: outputs are written k-permuted (per-scalar stores) for chained GEMMs.
// ---------------------------------------------------------------------------
#define STAGE_F (128 * 32)
#define GEMM_SMEM (6 * STAGE_F * (int)sizeof(float))  // 98304 B

template <bool RELU, bool ROUND, bool PERM>
__global__ void __launch_bounds__(256, 2)
gemm_tf32(const float* __restrict__ A, const float* __restrict__ W,
          const float* __restrict__ bias, float* __restrict__ Cq,
          float* __restrict__ Ckv, int M, int K, int Nout, int split)
{
    extern __shared__ float smemf[];
    float* AsB = smemf;                 // [3][128][32]
    float* BsB = smemf + 3 * STAGE_F;
    const uint32_t AsAddr = smem_u32(AsB);
    const uint32_t BsAddr = smem_u32(BsB);

    const int tid  = threadIdx.x;
    const int lane = tid & 31;
    const int warp = tid >> 5;
    const int wm   = warp >> 2;     // 0..1
    const int wn   = warp & 3;      // 0..3
    const int g    = lane >> 2;     // 0..7
    const int c    = lane & 3;      // 0..3
    const int rowBase = blockIdx.y * 128;
    const int colBase = blockIdx.x * 128;

    float* Cb;
    int NoutB, colB;
    if (split > 0 && colBase >= split) {
        Cb = Ckv; NoutB = Nout - split; colB = colBase - split;
    } else if (split > 0) {
        Cb = Cq;  NoutB = split;        colB = colBase;
    } else {
        Cb = Cq;  NoutB = Nout;         colB = colBase;
    }

    float acc[4][4][4];
#pragma unroll
    for (int mt = 0; mt < 4; mt++)
#pragma unroll
        for (int nt = 0; nt < 4; nt++)
#pragma unroll
            for (int i = 0; i < 4; i++) acc[mt][nt][i] = 0.f;

    auto issue = [&](int kt) {
        const int k0 = kt << 5;
        const int st = kt % 3;
        const uint32_t Ad = AsAddr + (uint32_t)(st * STAGE_F) * 4u;
        const uint32_t Bd = BsAddr + (uint32_t)(st * STAGE_F) * 4u;
#pragma unroll
        for (int i = 0; i < 4; i++) {
            int li = tid + i * 256;
            int r  = li >> 3;
            int q  = li & 7;
            int qs = q ^ ((r & 3) << 1);   // swizzled quad
            int ar = rowBase + r;
            int sz = (ar < M) ? 16 : 0;
            int arc = (ar < M) ? ar : (M - 1);
            cp16(Ad + (uint32_t)(r * 32 + qs * 4) * 4u,
                 A + (size_t)arc * K + k0 + q * 4, sz);
            cp16(Bd + (uint32_t)(r * 32 + qs * 4) * 4u,
                 W + (size_t)(colBase + r) * K + k0 + q * 4, 16);
        }
        CP_COMMIT();
    };

    const int NT = K >> 5;
    issue(0);
    issue(1);

    const int swz = (g & 3) << 2;   // chunk-xor term (rows r0, r0+8, n0 share g&3)

    for (int kt = 0; kt < NT; kt++) {
        if (kt + 1 < NT) { CP_WAIT(1); } else { CP_WAIT(0); }
        __syncthreads();
        if (kt + 2 < NT) issue(kt + 2);

        const float* As = AsB + (kt % 3) * STAGE_F;
        const float* Bs = BsB + (kt % 3) * STAGE_F;

#pragma unroll
        for (int ks = 0; ks < 4; ks++) {
            const int chunk = (ks * 4 + c) ^ swz;
            uint32_t af[4][4];
            uint32_t bf[4][2];
#pragma unroll
            for (int mt = 0; mt < 4; mt++) {
                int r0 = wm * 64 + mt * 16 + g;
                float2 aLo = *(const float2*)&As[r0 * 32 + chunk * 2];
                float2 aHi = *(const float2*)&As[(r0 + 8) * 32 + chunk * 2];
                af[mt][0] = __float_as_uint(aLo.x);
                af[mt][1] = __float_as_uint(aHi.x);
                af[mt][2] = __float_as_uint(aLo.y);
                af[mt][3] = __float_as_uint(aHi.y);
            }
#pragma unroll
            for (int nt = 0; nt < 4; nt++) {
                int n0 = wn * 32 + nt * 8 + g;
                float2 b = *(const float2*)&Bs[n0 * 32 + chunk * 2];
                bf[nt][0] = __float_as_uint(b.x);
                bf[nt][1] = __float_as_uint(b.y);
            }
#pragma unroll
            for (int mt = 0; mt < 4; mt++)
#pragma unroll
                for (int nt = 0; nt < 4; nt++)
                    asm volatile(
                        "mma.sync.aligned.m16n8k8.row.col.f32.tf32.tf32.f32 "
                        "{%0,%1,%2,%3}, {%4,%5,%6,%7}, {%8,%9}, {%0,%1,%2,%3};"
                        : "+f"(acc[mt][nt][0]), "+f"(acc[mt][nt][1]),
                          "+f"(acc[mt][nt][2]), "+f"(acc[mt][nt][3])
                        : "r"(af[mt][0]), "r"(af[mt][1]),
                          "r"(af[mt][2]), "r"(af[mt][3]),
                          "r"(bf[nt][0]), "r"(bf[nt][1]));
        }
    }

    // Epilogue: bias, relu, optional round, optional permuted scatter stores
#pragma unroll
    for (int mt = 0; mt < 4; mt++) {
        int r0 = rowBase + wm * 64 + mt * 16 + g;
        int r1 = r0 + 8;
#pragma unroll
        for (int nt = 0; nt < 4; nt++) {
            int colRel = wn * 32 + nt * 8 + c * 2;
            float2 bb = *(const float2*)(bias + colBase + colRel);
            float v0 = acc[mt][nt][0] + bb.x;
            float v1 = acc[mt][nt][1] + bb.y;
            float v2 = acc[mt][nt][2] + bb.x;
            float v3 = acc[mt][nt][3] + bb.y;
            if (RELU) {
                v0 = fmaxf(v0, 0.f); v1 = fmaxf(v1, 0.f);
                v2 = fmaxf(v2, 0.f); v3 = fmaxf(v3, 0.f);
            }
            if (ROUND) {
                v0 = rnd_tf(v0); v1 = rnd_tf(v1);
                v2 = rnd_tf(v2); v3 = rnd_tf(v3);
            }
            int col = colB + colRel;
            if (PERM) {
                int p0 = (col & ~7) | PERM8(col & 7);
                int p1 = ((col + 1) & ~7) | PERM8((col + 1) & 7);
                if (r0 < M) {
                    Cb[(size_t)r0 * NoutB + p0] = v0;
                    Cb[(size_t)r0 * NoutB + p1] = v1;
                }
                if (r1 < M) {
                    Cb[(size_t)r1 * NoutB + p0] = v2;
                    Cb[(size_t)r1 * NoutB + p1] = v3;
                }
            } else {
                if (r0 < M) *(float2*)(Cb + (size_t)r0 * NoutB + col) = make_float2(v0, v1);
                if (r1 < M) *(float2*)(Cb + (size_t)r1 * NoutB + col) = make_float2(v2, v3);
            }
        }
    }
}

// ---------------------------------------------------------------------------
// CSR build
// ---------------------------------------------------------------------------
__global__ void csr_hist(const int* __restrict__ tgtI, int* __restrict__ cnt, int E)
{
    int e = blockIdx.x * blockDim.x + threadIdx.x;
    if (e < E) atomicAdd(&cnt[tgtI[e]], 1);
}

__global__ void __launch_bounds__(1024)
csr_scan(const int* __restrict__ cnt, int* __restrict__ off, int* __restrict__ pos, int n)
{
    __shared__ int part[1024];
    const int t = threadIdx.x;
    const int CH = (n + 1023) / 1024;
    int vals[32];
    int base = t * CH;
    int local = 0;
    for (int i = 0; i < CH; i++) {
        int e = base + i;
        int v = (e < n) ? cnt[e] : 0;
        vals[i] = v;
        local += v;
    }
    part[t] = local;
    __syncthreads();
    for (int d = 1; d < 1024; d <<= 1) {
        int v = (t >= d) ? part[t - d] : 0;
        __syncthreads();
        part[t] += v;
        __syncthreads();
    }
    int run = (t > 0) ? part[t - 1] : 0;
    for (int i = 0; i < CH; i++) {
        int e = base + i;
        if (e < n) { off[e] = run; pos[e] = run; run += vals[i]; }
    }
    if (t == 1023) off[n] = part[1023];
}

__global__ void csr_scatter(const int* __restrict__ srcI, const int* __restrict__ tgtI,
                            int* __restrict__ pos, int* __restrict__ esrc, int E)
{
    int e = blockIdx.x * blockDim.x + threadIdx.x;
    if (e >= E) return;
    int slot = atomicAdd(&pos[tgtI[e]], 1);
    esrc[slot] = srcI[e];
}

// ---------------------------------------------------------------------------
// Attention over CSR (permuted dim space — closed under elementwise ops):
// one warp per target node, two-pass, pipelined gathers, no atomics.
// ---------------------------------------------------------------------------
__global__ void __launch_bounds__(256)
attn_csr(const float* __restrict__ qb, const float* __restrict__ kv,
         const int* __restrict__ off, const int* __restrict__ esrc,
         float* __restrict__ p, float* __restrict__ agg, int n)
{
    int node = (blockIdx.x * blockDim.x + threadIdx.x) >> 5;
    int lane = threadIdx.x & 31;
    if (node >= n) return;
    const int start = off[node];
    const int end   = off[node + 1];
    const int h     = lane >> 2;

    const float4* qr = (const float4*)(qb + (size_t)node * DD) + lane * 4;
    float4 q0 = qr[0], q1 = qr[1], q2 = qr[2], q3 = qr[3];

    float hmax = -INFINITY;
    if (start < end) {
        int sn = esrc[start];
        const float4* kr = (const float4*)(kv + (size_t)sn * 1024) + lane * 4;
        float4 k0 = kr[0], k1 = kr[1], k2 = kr[2], k3 = kr[3];
        for (int s = start; s < end; s++) {
            float4 n0, n1, n2, n3;
            if (s + 1 < end) {
                int sn2 = esrc[s + 1];
                const float4* nr = (const float4*)(kv + (size_t)sn2 * 1024) + lane * 4;
                n0 = nr[0]; n1 = nr[1]; n2 = nr[2]; n3 = nr[3];
            }
            float d = q0.x*k0.x + q0.y*k0.y + q0.z*k0.z + q0.w*k0.w;
            d += q1.x*k1.x + q1.y*k1.y + q1.z*k1.z + q1.w*k1.w;
            d += q2.x*k2.x + q2.y*k2.y + q2.z*k2.z + q2.w*k2.w;
            d += q3.x*k3.x + q3.y*k3.y + q3.z*k3.z + q3.w*k3.w;
            d += __shfl_xor_sync(0xffffffffu, d, 1);
            d += __shfl_xor_sync(0xffffffffu, d, 2);
            if ((lane & 3) == 0) p[(size_t)s * HH + h] = d;
            hmax = fmaxf(hmax, d);
            if (s + 1 < end) { k0 = n0; k1 = n1; k2 = n2; k3 = n3; }
        }
    }

    float acc[16];
#pragma unroll
    for (int i = 0; i < 16; i++) acc[i] = 0.f;
    float hsum = 0.f;

    if (start < end) {
        int sn = esrc[start];
        const float4* vr = (const float4*)(kv + (size_t)sn * 1024 + 512) + lane * 4;
        float4 v0 = vr[0], v1 = vr[1], v2 = vr[2], v3 = vr[3];
        float dcur = p[(size_t)start * HH + h];
        for (int s = start; s < end; s++) {
            float4 n0, n1, n2, n3;
            float dnxt;
            if (s + 1 < end) {
                int sn2 = esrc[s + 1];
                const float4* nr = (const float4*)(kv + (size_t)sn2 * 1024 + 512) + lane * 4;
                n0 = nr[0]; n1 = nr[1]; n2 = nr[2]; n3 = nr[3];
                dnxt = p[(size_t)(s + 1) * HH + h];
            }
            float w = expf(dcur - hmax);
            hsum += w;
            acc[0]  += w * v0.x; acc[1]  += w * v0.y; acc[2]  += w * v0.z; acc[3]  += w * v0.w;
            acc[4]  += w * v1.x; acc[5]  += w * v1.y; acc[6]  += w * v1.z; acc[7]  += w * v1.w;
            acc[8]  += w * v2.x; acc[9]  += w * v2.y; acc[10] += w * v2.z; acc[11] += w * v2.w;
            acc[12] += w * v3.x; acc[13] += w * v3.y; acc[14] += w * v3.z; acc[15] += w * v3.w;
            if (s + 1 < end) {
                v0 = n0; v1 = n1; v2 = n2; v3 = n3; dcur = dnxt;
            }
        }
    }

    float inv = 1.f / (hsum + 1e-16f);
    float4* ag = (float4*)(agg + (size_t)node * DD) + lane * 4;
#pragma unroll
    for (int i = 0; i < 4; i++)
        ag[i] = make_float4(rnd_tf(acc[i*4+0]*inv), rnd_tf(acc[i*4+1]*inv),
                            rnd_tf(acc[i*4+2]*inv), rnd_tf(acc[i*4+3]*inv));
}

// ---------------------------------------------------------------------------
// BatchNorm over node dimension on z = a + b (residual fused); partials.
// ---------------------------------------------------------------------------
__global__ void bn_stats(const float* __restrict__ a, const float* __restrict__ b,
                         float* __restrict__ part, int n)
{
    int j = threadIdx.x;     // 512 = one per feature
    int blk = blockIdx.x;    // 256 blocks
    float sum = 0.f, sq = 0.f;
    for (int i = blk; i < n; i += 256) {
        float z = a[(size_t)i * DD + j] + b[(size_t)i * DD + j];
        sum += z; sq += z * z;
    }
    part[blk * 1024 + j]       = sum;
    part[blk * 1024 + 512 + j] = sq;
}

__global__ void bn_finalize(const float* __restrict__ part,
                            float* __restrict__ mu, float* __restrict__ rs, float invn)
{
    int j = threadIdx.x;
    float s = 0.f, q = 0.f;
    for (int b = 0; b < 256; b++) {
        s += part[b * 1024 + j];
        q += part[b * 1024 + 512 + j];
    }
    float m = s * invn;
    float var = q * invn - m * m;
    mu[j] = m;
    rs[j] = rsqrtf(var + 1e-5f);
}

// writes exact out (original space) and rounded+permuted outr (GEMM A path)
__global__ void bn_apply(const float* __restrict__ a, const float* __restrict__ b,
                         const float* __restrict__ mu, const float* __restrict__ rs,
                         const float* __restrict__ g, const float* __restrict__ beta,
                         float* __restrict__ out, float* __restrict__ outr, int n)
{
    int idx = blockIdx.x * blockDim.x + threadIdx.x;
    if (idx >= n * DD) return;
    int j = idx & (DD - 1);
    float z = a[idx] + b[idx];
    float o = (z - mu[j]) * rs[j] * g[j] + beta[j];
    out[idx] = o;
    outr[(idx & ~7) | PERM8(idx & 7)] = rnd_tf(o);
}

// ---------------------------------------------------------------------------
// Final per-row LayerNorm  (128 threads/row, 4 floats each)
// ---------------------------------------------------------------------------
__global__ void layernorm_k(const float* __restrict__ x, const float* __restrict__ g,
                            const float* __restrict__ b, float* __restrict__ out)
{
    int row = blockIdx.x;
    int t = threadIdx.x;
    const float4* xr = (const float4*)(x + (size_t)row * DD);
    float4 v = xr[t];
    float sum = v.x + v.y + v.z + v.w;
    float sq  = v.x * v.x + v.y * v.y + v.z * v.z + v.w * v.w;

#pragma unroll
    for (int o = 16; o > 0; o >>= 1) {
        sum += __shfl_xor_sync(0xffffffffu, sum, o);
        sq  += __shfl_xor_sync(0xffffffffu, sq, o);
    }
    __shared__ float sa[4], sb[4];
    int w = t >> 5, l = t & 31;
    if (l == 0) { sa[w] = sum; sb[w] = sq; }
    __syncthreads();
    sum = sa[0] + sa[1] + sa[2] + sa[3];
    sq  = sb[0] + sb[1] + sb[2] + sb[3];

    float mu = sum * (1.f / DD);
    float var = sq * (1.f / DD) - mu * mu;
    float rs = rsqrtf(var + 1e-5f);

    const float4* g4 = (const float4*)g;
    const float4* b4 = (const float4*)b;
    float4 gg = g4[t], bb = b4[t];
    float4 o;
    o.x = (v.x - mu) * rs * gg.x + bb.x;
    o.y = (v.y - mu) * rs * gg.y + bb.y;
    o.z = (v.z - mu) * rs * gg.z + bb.z;
    o.w = (v.w - mu) * rs * gg.w + bb.w;
    *(float4*)(out + (size_t)row * DD + t * 4) = o;
}

// ---------------------------------------------------------------------------
// Orchestration
// ---------------------------------------------------------------------------
extern "C" void kernel_launch(void* const* d_in, const int* in_sizes, int n_in,
                              void* d_out, int out_size)
{
    const float* src = (const float*)d_in[0];
    const int*   ei  = (const int*)  d_in[1];
    const float* Wq  = (const float*)d_in[2];
    const float* bq  = (const float*)d_in[3];
    const float* Wk  = (const float*)d_in[4];
    const float* Wv  = (const float*)d_in[5];
    const float* Wo  = (const float*)d_in[6];
    const float* bo  = (const float*)d_in[7];
    const float* W1  = (const float*)d_in[8];
    const float* b1  = (const float*)d_in[9];
    const float* W2  = (const float*)d_in[10];
    const float* b2  = (const float*)d_in[11];
    const float* g1  = (const float*)d_in[12];
    const float* be1 = (const float*)d_in[13];
    const float* g2  = (const float*)d_in[14];
    const float* be2 = (const float*)d_in[15];
    const float* lng = (const float*)d_in[16];
    const float* lnb = (const float*)d_in[17];
    float* outp = (float*)d_out;

    const int n = in_sizes[0] / DD;
    const int E = in_sizes[1] / 2;
    const int* srcI = ei;
    const int* tgtI = ei + E;

    float *qb, *kv, *agg, *tb, *x, *xr, *srctf, *ff, *p, *part, *mu, *rs;
    float *wqkv, *bqkv, *woR, *w1R, *w2R;
    int *cnt, *off, *pos, *esrc;
    cudaGetSymbolAddress((void**)&qb,    g_qb);
    cudaGetSymbolAddress((void**)&kv,    g_kv);
    cudaGetSymbolAddress((void**)&agg,   g_agg);
    cudaGetSymbolAddress((void**)&tb,    g_t);
    cudaGetSymbolAddress((void**)&x,     g_x);
    cudaGetSymbolAddress((void**)&xr,    g_xr);
    cudaGetSymbolAddress((void**)&srctf, g_srctf);
    cudaGetSymbolAddress((void**)&ff,    g_ff);
    cudaGetSymbolAddress((void**)&p,     g_p);
    cudaGetSymbolAddress((void**)&part,  g_part);
    cudaGetSymbolAddress((void**)&mu,    g_mu);
    cudaGetSymbolAddress((void**)&rs,    g_rs);
    cudaGetSymbolAddress((void**)&wqkv,  g_wqkv);
    cudaGetSymbolAddress((void**)&bqkv,  g_bqkv);
    cudaGetSymbolAddress((void**)&woR,   g_woR);
    cudaGetSymbolAddress((void**)&w1R,   g_w1R);
    cudaGetSymbolAddress((void**)&w2R,   g_w2R);
    cudaGetSymbolAddress((void**)&cnt,   g_cnt);
    cudaGetSymbolAddress((void**)&off,   g_off);
    cudaGetSymbolAddress((void**)&pos,   g_pos);
    cudaGetSymbolAddress((void**)&esrc,  g_esrc);

    cudaFuncSetAttribute((const void*)gemm_tf32<false, false, true>,
                         cudaFuncAttributeMaxDynamicSharedMemorySize, GEMM_SMEM);
    cudaFuncSetAttribute((const void*)gemm_tf32<false, false, false>,
                         cudaFuncAttributeMaxDynamicSharedMemorySize, GEMM_SMEM);
    cudaFuncSetAttribute((const void*)gemm_tf32<true, true, true>,
                         cudaFuncAttributeMaxDynamicSharedMemorySize, GEMM_SMEM);

    const dim3 gQKV(QKVW / 128, (n + 127) / 128);
    const dim3 gD(DD / 128, (n + 127) / 128);
    const dim3 gF(FF / 128, (n + 127) / 128);
    const int nDblocks = (n * DD + 255) / 256;

    // launches 0-2: packing + src round/perm; launch 3: QKV GEMM (ncu sample)
    pack_qkv_w<<<(LLAY * QKVW * DD + 255) / 256, 256>>>(Wq, Wk, Wv, wqkv);
    pack_qkv_b<<<(LLAY * QKVW + 255) / 256, 256>>>(bq, bqkv);
    round_copy_perm<<<nDblocks, 256>>>(src, srctf, n * DD);
    gemm_tf32<false, false, true><<<gQKV, 256, GEMM_SMEM>>>(srctf, wqkv, bqkv,
                                                            qb, kv, n, DD, QKVW, DD);

    // rounded+permuted weight copies + CSR build
    round_copy_perm<<<(LLAY * DD * DD + 255) / 256, 256>>>(Wo, woR, LLAY * DD * DD);
    round_copy_perm<<<(LLAY * FF * DD + 255) / 256, 256>>>(W1, w1R, LLAY * FF * DD);
    round_copy_perm<<<(LLAY * DD * FF + 255) / 256, 256>>>(W2, w2R, LLAY * DD * FF);
    fill_i<<<(n + 1 + 255) / 256, 256>>>(cnt, 0, n + 1);
    csr_hist<<<(E + 255) / 256, 256>>>(tgtI, cnt, E);
    csr_scan<<<1, 1024>>>(cnt, off, pos, n);
    csr_scatter<<<(E + 255) / 256, 256>>>(srcI, tgtI, pos, esrc, E);

    const float* xinExact = src;   // exact residual input (original space)

    for (int l = 0; l < LLAY; l++) {
        const float* W1l = w1R + (size_t)l * FF * DD;
        const float* W2l = w2R + (size_t)l * DD * FF;
        const float* Wol = woR + (size_t)l * DD * DD;

        // fused q|k|v projection (permuted outputs), split-routed into qb / kv
        if (l > 0)
            gemm_tf32<false, false, true><<<gQKV, 256, GEMM_SMEM>>>(
                xr, wqkv + (size_t)l * QKVW * DD, bqkv + l * QKVW, qb, kv,
                n, DD, QKVW, DD);

        // attention over CSR (permuted space; rounds agg)
        attn_csr<<<(n * 32 + 255) / 256, 256>>>(qb, kv, off, esrc, p, agg, n);

        // output projection (original-space output)
        gemm_tf32<false, false, false><<<gD, 256, GEMM_SMEM>>>(
            agg, Wol, bo + l * DD, tb, nullptr, n, DD, DD, 0);

        // batchnorm 1 (residual xinExact + tb) -> x (exact), xr (rounded+perm)
        bn_stats<<<256, DD>>>(xinExact, tb, part, n);
        bn_finalize<<<1, DD>>>(part, mu, rs, 1.f / (float)n);
        bn_apply<<<nDblocks, 256>>>(xinExact, tb, mu, rs,
                                    g1 + l * DD, be1 + l * DD, x, xr, n);

        // feedforward: FF1 rounds+permutes its output (feeds FF2)
        gemm_tf32<true, true, true><<<gF, 256, GEMM_SMEM>>>(
            xr, W1l, b1 + l * FF, ff, nullptr, n, DD, FF, 0);
        gemm_tf32<false, false, false><<<gD, 256, GEMM_SMEM>>>(
            ff, W2l, b2 + l * DD, tb, nullptr, n, FF, DD, 0);

        // batchnorm 2 (residual x + tb) -> x (exact), xr (rounded+perm)
        bn_stats<<<256, DD>>>(x, tb, part, n);
        bn_finalize<<<1, DD>>>(part, mu, rs, 1.f / (float)n);
        bn_apply<<<nDblocks, 256>>>(x, tb, mu, rs,
                                    g2 + l * DD, be2 + l * DD, x, xr, n);

        xinExact = x;
    }

    // final layernorm -> output (exact path, original space)
    layernorm_k<<<n, 128>>>(x, lng, lnb, outp);
}

// round 12
// speedup vs baseline: 1.3249x; 1.0253x over previous
#include <cuda_runtime.h>
#include <math.h>
#include <stdint.h>

// Problem constants (fixed by the reference generator)
#define NN   20000
#define DD   512
#define HH   8
#define DHH  64
#define FF   2048
#define LLAY 2
#define EE   320000
#define QKVW 1536   // packed q|k|v projection width

// k-permutation within 8-groups: stored order [k0,k4,k1,k5,k2,k6,k3,k7].
#define PERM8(k)  ((((k) & 3) << 1) | (((k) >> 2) & 1))
#define IPERM8(p) ((((p) & 1) << 2) | (((p) & 7) >> 1))

// ---------------------------------------------------------------------------
// Scratch (device globals: alloc-free rule)
// ---------------------------------------------------------------------------
__device__ float g_qb  [NN * DD];        // q rows (permuted space)
__device__ float g_kv  [NN * 2 * DD];    // compact k|v rows (permuted space)
__device__ float g_agg [NN * DD];        // attn output (permuted, tf32-rounded)
__device__ float g_t   [NN * DD];        // Wo / FF2 output (original space)
__device__ float g_x   [NN * DD];        // exact activations (original space)
__device__ float g_xr  [NN * DD];        // rounded+permuted activations (GEMM A)
__device__ float g_srctf[NN * DD];       // rounded+permuted src
__device__ float g_ff  [NN * FF];        // FF1 output (rounded+permuted)
__device__ float g_p   [EE * HH];
__device__ float g_part[256 * 1024];     // BN partial sums
__device__ float g_mu  [DD];
__device__ float g_rs  [DD];
__device__ float g_wqkv[LLAY * QKVW * DD];   // packed+rounded+permuted
__device__ float g_bqkv[LLAY * QKVW];
__device__ float g_woR [LLAY * DD * DD];     // rounded+permuted weights
__device__ float g_w1R [LLAY * FF * DD];
__device__ float g_w2R [LLAY * DD * FF];
__device__ int g_cnt [NN + 1];
__device__ int g_off [NN + 1];
__device__ int g_pos [NN];
__device__ int g_esrc[EE];

// ---------------------------------------------------------------------------
// helpers
// ---------------------------------------------------------------------------
__device__ __forceinline__ uint32_t smem_u32(const void* p) {
    uint32_t a;
    asm("{ .reg .u64 t; cvta.to.shared.u64 t, %1; cvt.u32.u64 %0, t; }"
        : "=r"(a) : "l"(p));
    return a;
}
__device__ __forceinline__ void cp16(uint32_t dst, const void* src, int szbytes) {
    asm volatile("cp.async.cg.shared.global [%0], [%1], 16, %2;"
                 :: "r"(dst), "l"(src), "r"(szbytes) : "memory");
}
#define CP_COMMIT() asm volatile("cp.async.commit_group;" ::: "memory")
#define CP_WAIT(n)  asm volatile("cp.async.wait_group %0;" :: "n"(n) : "memory")

__device__ __forceinline__ float rnd_tf(float x) {
    uint32_t r;
    asm("cvt.rna.tf32.f32 %0, %1;" : "=r"(r) : "f"(x));
    return __uint_as_float(r);
}

// ---------------------------------------------------------------------------
// Utility kernels
// ---------------------------------------------------------------------------
__global__ void fill_i(int* __restrict__ p, int v, int n) {
    int i = blockIdx.x * blockDim.x + threadIdx.x;
    if (i < n) p[i] = v;
}
__global__ void round_copy_perm(const float* __restrict__ in, float* __restrict__ out, int n)
{
    int i = blockIdx.x * blockDim.x + threadIdx.x;
    if (i >= n) return;
    int src = (i & ~7) | IPERM8(i & 7);
    out[i] = rnd_tf(in[src]);
}

// ---------------------------------------------------------------------------
// Weight packing (rounded + k-permuted): r<512: Wq*0.125 | <1024: Wk | else Wv
// ---------------------------------------------------------------------------
__global__ void pack_qkv_w(const float* __restrict__ Wq, const float* __restrict__ Wk,
                           const float* __restrict__ Wv, float* __restrict__ wout)
{
    int idx = blockIdx.x * blockDim.x + threadIdx.x;
    const int total = LLAY * QKVW * DD;
    if (idx >= total) return;
    int l = idx / (QKVW * DD);
    int rem = idx % (QKVW * DD);
    int r = rem / DD, cpos = rem % DD;
    int c = (cpos & ~7) | IPERM8(cpos & 7);
    float val;
    if (r < 512)       val = Wq[(size_t)l * DD * DD + (size_t)r * DD + c] * 0.125f;
    else if (r < 1024) val = Wk[(size_t)l * DD * DD + (size_t)(r - 512) * DD + c];
    else               val = Wv[(size_t)l * DD * DD + (size_t)(r - 1024) * DD + c];
    wout[idx] = rnd_tf(val);
}
__global__ void pack_qkv_b(const float* __restrict__ bq, float* __restrict__ bout)
{
    int idx = blockIdx.x * blockDim.x + threadIdx.x;
    if (idx >= LLAY * QKVW) return;
    int l = idx / QKVW, r = idx % QKVW;
    bout[idx] = (r < 512) ? bq[l * DD + r] * 0.125f : 0.f;
}

// ---------------------------------------------------------------------------
// TF32 tensor-core GEMM (mma.sync), cp.async 3-stage gmem pipeline +
// double-buffered fragment (ks) pipeline: LDS for ks+1 issues before ks MMAs.
// All operands pre-rounded tf32 values, k-permuted (float2 fragment pairs).
// ---------------------------------------------------------------------------
#define STAGE_F (128 * 32)
#define GEMM_SMEM (6 * STAGE_F * (int)sizeof(float))  // 98304 B

template <bool RELU, bool ROUND, bool PERM>
__global__ void __launch_bounds__(256, 2)
gemm_tf32(const float* __restrict__ A, const float* __restrict__ W,
          const float* __restrict__ bias, float* __restrict__ Cq,
          float* __restrict__ Ckv, int M, int K, int Nout, int split)
{
    extern __shared__ float smemf[];
    float* AsB = smemf;                 // [3][128][32]
    float* BsB = smemf + 3 * STAGE_F;
    const uint32_t AsAddr = smem_u32(AsB);
    const uint32_t BsAddr = smem_u32(BsB);

    const int tid  = threadIdx.x;
    const int lane = tid & 31;
    const int warp = tid >> 5;
    const int wm   = warp >> 2;     // 0..1
    const int wn   = warp & 3;      // 0..3
    const int g    = lane >> 2;     // 0..7
    const int c    = lane & 3;      // 0..3
    const int rowBase = blockIdx.y * 128;
    const int colBase = blockIdx.x * 128;

    float* Cb;
    int NoutB, colB;
    if (split > 0 && colBase >= split) {
        Cb = Ckv; NoutB = Nout - split; colB = colBase - split;
    } else if (split > 0) {
        Cb = Cq;  NoutB = split;        colB = colBase;
    } else {
        Cb = Cq;  NoutB = Nout;         colB = colBase;
    }

    float acc[4][4][4];
#pragma unroll
    for (int mt = 0; mt < 4; mt++)
#pragma unroll
        for (int nt = 0; nt < 4; nt++)
#pragma unroll
            for (int i = 0; i < 4; i++) acc[mt][nt][i] = 0.f;

    auto issue = [&](int kt) {
        const int k0 = kt << 5;
        const int st = kt % 3;
        const uint32_t Ad = AsAddr + (uint32_t)(st * STAGE_F) * 4u;
        const uint32_t Bd = BsAddr + (uint32_t)(st * STAGE_F) * 4u;
#pragma unroll
        for (int i = 0; i < 4; i++) {
            int li = tid + i * 256;
            int r  = li >> 3;
            int q  = li & 7;
            int qs = q ^ ((r & 3) << 1);
            int ar = rowBase + r;
            int sz = (ar < M) ? 16 : 0;
            int arc = (ar < M) ? ar : (M - 1);
            cp16(Ad + (uint32_t)(r * 32 + qs * 4) * 4u,
                 A + (size_t)arc * K + k0 + q * 4, sz);
            cp16(Bd + (uint32_t)(r * 32 + qs * 4) * 4u,
                 W + (size_t)(colBase + r) * K + k0 + q * 4, 16);
        }
        CP_COMMIT();
    };

    const int NT = K >> 5;
    issue(0);
    issue(1);

    const int swz = (g & 3) << 2;

    uint32_t afb[2][4][4];
    uint32_t bfb[2][4][2];

    for (int kt = 0; kt < NT; kt++) {
        if (kt + 1 < NT) { CP_WAIT(1); } else { CP_WAIT(0); }
        __syncthreads();
        if (kt + 2 < NT) issue(kt + 2);

        const float* As = AsB + (kt % 3) * STAGE_F;
        const float* Bs = BsB + (kt % 3) * STAGE_F;

        auto loadFrag = [&](int ks, uint32_t af[4][4], uint32_t bf[4][2]) {
            const int chunk = (ks * 4 + c) ^ swz;
#pragma unroll
            for (int mt = 0; mt < 4; mt++) {
                int r0 = wm * 64 + mt * 16 + g;
                float2 aLo = *(const float2*)&As[r0 * 32 + chunk * 2];
                float2 aHi = *(const float2*)&As[(r0 + 8) * 32 + chunk * 2];
                af[mt][0] = __float_as_uint(aLo.x);
                af[mt][1] = __float_as_uint(aHi.x);
                af[mt][2] = __float_as_uint(aLo.y);
                af[mt][3] = __float_as_uint(aHi.y);
            }
#pragma unroll
            for (int nt = 0; nt < 4; nt++) {
                int n0 = wn * 32 + nt * 8 + g;
                float2 b = *(const float2*)&Bs[n0 * 32 + chunk * 2];
                bf[nt][0] = __float_as_uint(b.x);
                bf[nt][1] = __float_as_uint(b.y);
            }
        };

        loadFrag(0, afb[0], bfb[0]);
#pragma unroll
        for (int ks = 0; ks < 4; ks++) {
            const int cur = ks & 1;
            if (ks < 3) loadFrag(ks + 1, afb[cur ^ 1], bfb[cur ^ 1]);
#pragma unroll
            for (int mt = 0; mt < 4; mt++)
#pragma unroll
                for (int nt = 0; nt < 4; nt++)
                    asm volatile(
                        "mma.sync.aligned.m16n8k8.row.col.f32.tf32.tf32.f32 "
                        "{%0,%1,%2,%3}, {%4,%5,%6,%7}, {%8,%9}, {%0,%1,%2,%3};"
                        : "+f"(acc[mt][nt][0]), "+f"(acc[mt][nt][1]),
                          "+f"(acc[mt][nt][2]), "+f"(acc[mt][nt][3])
                        : "r"(afb[cur][mt][0]), "r"(afb[cur][mt][1]),
                          "r"(afb[cur][mt][2]), "r"(afb[cur][mt][3]),
                          "r"(bfb[cur][nt][0]), "r"(bfb[cur][nt][1]));
        }
    }

    // Epilogue: bias, relu, optional round, optional permuted scatter stores
#pragma unroll
    for (int mt = 0; mt < 4; mt++) {
        int r0 = rowBase + wm * 64 + mt * 16 + g;
        int r1 = r0 + 8;
#pragma unroll
        for (int nt = 0; nt < 4; nt++) {
            int colRel = wn * 32 + nt * 8 + c * 2;
            float2 bb = *(const float2*)(bias + colBase + colRel);
            float v0 = acc[mt][nt][0] + bb.x;
            float v1 = acc[mt][nt][1] + bb.y;
            float v2 = acc[mt][nt][2] + bb.x;
            float v3 = acc[mt][nt][3] + bb.y;
            if (RELU) {
                v0 = fmaxf(v0, 0.f); v1 = fmaxf(v1, 0.f);
                v2 = fmaxf(v2, 0.f); v3 = fmaxf(v3, 0.f);
            }
            if (ROUND) {
                v0 = rnd_tf(v0); v1 = rnd_tf(v1);
                v2 = rnd_tf(v2); v3 = rnd_tf(v3);
            }
            int col = colB + colRel;
            if (PERM) {
                int p0 = (col & ~7) | PERM8(col & 7);
                int p1 = ((col + 1) & ~7) | PERM8((col + 1) & 7);
                if (r0 < M) {
                    Cb[(size_t)r0 * NoutB + p0] = v0;
                    Cb[(size_t)r0 * NoutB + p1] = v1;
                }
                if (r1 < M) {
                    Cb[(size_t)r1 * NoutB + p0] = v2;
                    Cb[(size_t)r1 * NoutB + p1] = v3;
                }
            } else {
                if (r0 < M) *(float2*)(Cb + (size_t)r0 * NoutB + col) = make_float2(v0, v1);
                if (r1 < M) *(float2*)(Cb + (size_t)r1 * NoutB + col) = make_float2(v2, v3);
            }
        }
    }
}

// ---------------------------------------------------------------------------
// CSR build
// ---------------------------------------------------------------------------
__global__ void csr_hist(const int* __restrict__ tgtI, int* __restrict__ cnt, int E)
{
    int e = blockIdx.x * blockDim.x + threadIdx.x;
    if (e < E) atomicAdd(&cnt[tgtI[e]], 1);
}

__global__ void __launch_bounds__(1024)
csr_scan(const int* __restrict__ cnt, int* __restrict__ off, int* __restrict__ pos, int n)
{
    __shared__ int part[1024];
    const int t = threadIdx.x;
    const int CH = (n + 1023) / 1024;
    int vals[32];
    int base = t * CH;
    int local = 0;
    for (int i = 0; i < CH; i++) {
        int e = base + i;
        int v = (e < n) ? cnt[e] : 0;
        vals[i] = v;
        local += v;
    }
    part[t] = local;
    __syncthreads();
    for (int d = 1; d < 1024; d <<= 1) {
        int v = (t >= d) ? part[t - d] : 0;
        __syncthreads();
        part[t] += v;
        __syncthreads();
    }
    int run = (t > 0) ? part[t - 1] : 0;
    for (int i = 0; i < CH; i++) {
        int e = base + i;
        if (e < n) { off[e] = run; pos[e] = run; run += vals[i]; }
    }
    if (t == 1023) off[n] = part[1023];
}

__global__ void csr_scatter(const int* __restrict__ srcI, const int* __restrict__ tgtI,
                            int* __restrict__ pos, int* __restrict__ esrc, int E)
{
    int e = blockIdx.x * blockDim.x + threadIdx.x;
    if (e >= E) return;
    int slot = atomicAdd(&pos[tgtI[e]], 1);
    esrc[slot] = srcI[e];
}

// ---------------------------------------------------------------------------
// Attention over CSR (permuted dim space), two-pass, pipelined gathers.
// ---------------------------------------------------------------------------
__global__ void __launch_bounds__(256)
attn_csr(const float* __restrict__ qb, const float* __restrict__ kv,
         const int* __restrict__ off, const int* __restrict__ esrc,
         float* __restrict__ p, float* __restrict__ agg, int n)
{
    int node = (blockIdx.x * blockDim.x + threadIdx.x) >> 5;
    int lane = threadIdx.x & 31;
    if (node >= n) return;
    const int start = off[node];
    const int end   = off[node + 1];
    const int h     = lane >> 2;

    const float4* qr = (const float4*)(qb + (size_t)node * DD) + lane * 4;
    float4 q0 = qr[0], q1 = qr[1], q2 = qr[2], q3 = qr[3];

    float hmax = -INFINITY;
    if (start < end) {
        int sn = esrc[start];
        const float4* kr = (const float4*)(kv + (size_t)sn * 1024) + lane * 4;
        float4 k0 = kr[0], k1 = kr[1], k2 = kr[2], k3 = kr[3];
        for (int s = start; s < end; s++) {
            float4 n0, n1, n2, n3;
            if (s + 1 < end) {
                int sn2 = esrc[s + 1];
                const float4* nr = (const float4*)(kv + (size_t)sn2 * 1024) + lane * 4;
                n0 = nr[0]; n1 = nr[1]; n2 = nr[2]; n3 = nr[3];
            }
            float d = q0.x*k0.x + q0.y*k0.y + q0.z*k0.z + q0.w*k0.w;
            d += q1.x*k1.x + q1.y*k1.y + q1.z*k1.z + q1.w*k1.w;
            d += q2.x*k2.x + q2.y*k2.y + q2.z*k2.z + q2.w*k2.w;
            d += q3.x*k3.x + q3.y*k3.y + q3.z*k3.z + q3.w*k3.w;
            d += __shfl_xor_sync(0xffffffffu, d, 1);
            d += __shfl_xor_sync(0xffffffffu, d, 2);
            if ((lane & 3) == 0) p[(size_t)s * HH + h] = d;
            hmax = fmaxf(hmax, d);
            if (s + 1 < end) { k0 = n0; k1 = n1; k2 = n2; k3 = n3; }
        }
    }

    float acc[16];
#pragma unroll
    for (int i = 0; i < 16; i++) acc[i] = 0.f;
    float hsum = 0.f;

    if (start < end) {
        int sn = esrc[start];
        const float4* vr = (const float4*)(kv + (size_t)sn * 1024 + 512) + lane * 4;
        float4 v0 = vr[0], v1 = vr[1], v2 = vr[2], v3 = vr[3];
        float dcur = p[(size_t)start * HH + h];
        for (int s = start; s < end; s++) {
            float4 n0, n1, n2, n3;
            float dnxt;
            if (s + 1 < end) {
                int sn2 = esrc[s + 1];
                const float4* nr = (const float4*)(kv + (size_t)sn2 * 1024 + 512) + lane * 4;
                n0 = nr[0]; n1 = nr[1]; n2 = nr[2]; n3 = nr[3];
                dnxt = p[(size_t)(s + 1) * HH + h];
            }
            float w = expf(dcur - hmax);
            hsum += w;
            acc[0]  += w * v0.x; acc[1]  += w * v0.y; acc[2]  += w * v0.z; acc[3]  += w * v0.w;
            acc[4]  += w * v1.x; acc[5]  += w * v1.y; acc[6]  += w * v1.z; acc[7]  += w * v1.w;
            acc[8]  += w * v2.x; acc[9]  += w * v2.y; acc[10] += w * v2.z; acc[11] += w * v2.w;
            acc[12] += w * v3.x; acc[13] += w * v3.y; acc[14] += w * v3.z; acc[15] += w * v3.w;
            if (s + 1 < end) {
                v0 = n0; v1 = n1; v2 = n2; v3 = n3; dcur = dnxt;
            }
        }
    }

    float inv = 1.f / (hsum + 1e-16f);
    float4* ag = (float4*)(agg + (size_t)node * DD) + lane * 4;
#pragma unroll
    for (int i = 0; i < 4; i++)
        ag[i] = make_float4(rnd_tf(acc[i*4+0]*inv), rnd_tf(acc[i*4+1]*inv),
                            rnd_tf(acc[i*4+2]*inv), rnd_tf(acc[i*4+3]*inv));
}

// ---------------------------------------------------------------------------
// BatchNorm over node dimension on z = a + b (residual fused); partials.
// ---------------------------------------------------------------------------
__global__ void bn_stats(const float* __restrict__ a, const float* __restrict__ b,
                         float* __restrict__ part, int n)
{
    int j = threadIdx.x;
    int blk = blockIdx.x;
    float sum = 0.f, sq = 0.f;
    for (int i = blk; i < n; i += 256) {
        float z = a[(size_t)i * DD + j] + b[(size_t)i * DD + j];
        sum += z; sq += z * z;
    }
    part[blk * 1024 + j]       = sum;
    part[blk * 1024 + 512 + j] = sq;
}

__global__ void bn_finalize(const float* __restrict__ part,
                            float* __restrict__ mu, float* __restrict__ rs, float invn)
{
    int j = threadIdx.x;
    float s = 0.f, q = 0.f;
    for (int b = 0; b < 256; b++) {
        s += part[b * 1024 + j];
        q += part[b * 1024 + 512 + j];
    }
    float m = s * invn;
    float var = q * invn - m * m;
    mu[j] = m;
    rs[j] = rsqrtf(var + 1e-5f);
}

__global__ void bn_apply(const float* __restrict__ a, const float* __restrict__ b,
                         const float* __restrict__ mu, const float* __restrict__ rs,
                         const float* __restrict__ g, const float* __restrict__ beta,
                         float* __restrict__ out, float* __restrict__ outr, int n)
{
    int idx = blockIdx.x * blockDim.x + threadIdx.x;
    if (idx >= n * DD) return;
    int j = idx & (DD - 1);
    float z = a[idx] + b[idx];
    float o = (z - mu[j]) * rs[j] * g[j] + beta[j];
    out[idx] = o;
    outr[(idx & ~7) | PERM8(idx & 7)] = rnd_tf(o);
}

// ---------------------------------------------------------------------------
// Final per-row LayerNorm  (128 threads/row, 4 floats each)
// ---------------------------------------------------------------------------
__global__ void layernorm_k(const float* __restrict__ x, const float* __restrict__ g,
                            const float* __restrict__ b, float* __restrict__ out)
{
    int row = blockIdx.x;
    int t = threadIdx.x;
    const float4* xr = (const float4*)(x + (size_t)row * DD);
    float4 v = xr[t];
    float sum = v.x + v.y + v.z + v.w;
    float sq  = v.x * v.x + v.y * v.y + v.z * v.z + v.w * v.w;

#pragma unroll
    for (int o = 16; o > 0; o >>= 1) {
        sum += __shfl_xor_sync(0xffffffffu, sum, o);
        sq  += __shfl_xor_sync(0xffffffffu, sq, o);
    }
    __shared__ float sa[4], sb[4];
    int w = t >> 5, l = t & 31;
    if (l == 0) { sa[w] = sum; sb[w] = sq; }
    __syncthreads();
    sum = sa[0] + sa[1] + sa[2] + sa[3];
    sq  = sb[0] + sb[1] + sb[2] + sb[3];

    float mu = sum * (1.f / DD);
    float var = sq * (1.f / DD) - mu * mu;
    float rs = rsqrtf(var + 1e-5f);

    const float4* g4 = (const float4*)g;
    const float4* b4 = (const float4*)b;
    float4 gg = g4[t], bb = b4[t];
    float4 o;
    o.x = (v.x - mu) * rs * gg.x + bb.x;
    o.y = (v.y - mu) * rs * gg.y + bb.y;
    o.z = (v.z - mu) * rs * gg.z + bb.z;
    o.w = (v.w - mu) * rs * gg.w + bb.w;
    *(float4*)(out + (size_t)row * DD + t * 4) = o;
}

// ---------------------------------------------------------------------------
// Orchestration
// ---------------------------------------------------------------------------
extern "C" void kernel_launch(void* const* d_in, const int* in_sizes, int n_in,
                              void* d_out, int out_size)
{
    const float* src = (const float*)d_in[0];
    const int*   ei  = (const int*)  d_in[1];
    const float* Wq  = (const float*)d_in[2];
    const float* bq  = (const float*)d_in[3];
    const float* Wk  = (const float*)d_in[4];
    const float* Wv  = (const float*)d_in[5];
    const float* Wo  = (const float*)d_in[6];
    const float* bo  = (const float*)d_in[7];
    const float* W1  = (const float*)d_in[8];
    const float* b1  = (const float*)d_in[9];
    const float* W2  = (const float*)d_in[10];
    const float* b2  = (const float*)d_in[11];
    const float* g1  = (const float*)d_in[12];
    const float* be1 = (const float*)d_in[13];
    const float* g2  = (const float*)d_in[14];
    const float* be2 = (const float*)d_in[15];
    const float* lng = (const float*)d_in[16];
    const float* lnb = (const float*)d_in[17];
    float* outp = (float*)d_out;

    const int n = in_sizes[0] / DD;
    const int E = in_sizes[1] / 2;
    const int* srcI = ei;
    const int* tgtI = ei + E;

    float *qb, *kv, *agg, *tb, *x, *xr, *srctf, *ff, *p, *part, *mu, *rs;
    float *wqkv, *bqkv, *woR, *w1R, *w2R;
    int *cnt, *off, *pos, *esrc;
    cudaGetSymbolAddress((void**)&qb,    g_qb);
    cudaGetSymbolAddress((void**)&kv,    g_kv);
    cudaGetSymbolAddress((void**)&agg,   g_agg);
    cudaGetSymbolAddress((void**)&tb,    g_t);
    cudaGetSymbolAddress((void**)&x,     g_x);
    cudaGetSymbolAddress((void**)&xr,    g_xr);
    cudaGetSymbolAddress((void**)&srctf, g_srctf);
    cudaGetSymbolAddress((void**)&ff,    g_ff);
    cudaGetSymbolAddress((void**)&p,     g_p);
    cudaGetSymbolAddress((void**)&part,  g_part);
    cudaGetSymbolAddress((void**)&mu,    g_mu);
    cudaGetSymbolAddress((void**)&rs,    g_rs);
    cudaGetSymbolAddress((void**)&wqkv,  g_wqkv);
    cudaGetSymbolAddress((void**)&bqkv,  g_bqkv);
    cudaGetSymbolAddress((void**)&woR,   g_woR);
    cudaGetSymbolAddress((void**)&w1R,   g_w1R);
    cudaGetSymbolAddress((void**)&w2R,   g_w2R);
    cudaGetSymbolAddress((void**)&cnt,   g_cnt);
    cudaGetSymbolAddress((void**)&off,   g_off);
    cudaGetSymbolAddress((void**)&pos,   g_pos);
    cudaGetSymbolAddress((void**)&esrc,  g_esrc);

    cudaFuncSetAttribute((const void*)gemm_tf32<false, false, true>,
                         cudaFuncAttributeMaxDynamicSharedMemorySize, GEMM_SMEM);
    cudaFuncSetAttribute((const void*)gemm_tf32<false, false, false>,
                         cudaFuncAttributeMaxDynamicSharedMemorySize, GEMM_SMEM);
    cudaFuncSetAttribute((const void*)gemm_tf32<true, true, true>,
                         cudaFuncAttributeMaxDynamicSharedMemorySize, GEMM_SMEM);

    const dim3 gQKV(QKVW / 128, (n + 127) / 128);
    const dim3 gD(DD / 128, (n + 127) / 128);
    const dim3 gF(FF / 128, (n + 127) / 128);
    const int nDblocks = (n * DD + 255) / 256;

    // launches 0-2: packing + src round/perm; launch 3: QKV GEMM (ncu sample)
    pack_qkv_w<<<(LLAY * QKVW * DD + 255) / 256, 256>>>(Wq, Wk, Wv, wqkv);
    pack_qkv_b<<<(LLAY * QKVW + 255) / 256, 256>>>(bq, bqkv);
    round_copy_perm<<<nDblocks, 256>>>(src, srctf, n * DD);
    gemm_tf32<false, false, true><<<gQKV, 256, GEMM_SMEM>>>(srctf, wqkv, bqkv,
                                                            qb, kv, n, DD, QKVW, DD);

    // rounded+permuted weight copies + CSR build
    round_copy_perm<<<(LLAY * DD * DD + 255) / 256, 256>>>(Wo, woR, LLAY * DD * DD);
    round_copy_perm<<<(LLAY * FF * DD + 255) / 256, 256>>>(W1, w1R, LLAY * FF * DD);
    round_copy_perm<<<(LLAY * DD * FF + 255) / 256, 256>>>(W2, w2R, LLAY * DD * FF);
    fill_i<<<(n + 1 + 255) / 256, 256>>>(cnt, 0, n + 1);
    csr_hist<<<(E + 255) / 256, 256>>>(tgtI, cnt, E);
    csr_scan<<<1, 1024>>>(cnt, off, pos, n);
    csr_scatter<<<(E + 255) / 256, 256>>>(srcI, tgtI, pos, esrc, E);

    const float* xinExact = src;   // exact residual input (original space)

    for (int l = 0; l < LLAY; l++) {
        const float* W1l = w1R + (size_t)l * FF * DD;
        const float* W2l = w2R + (size_t)l * DD * FF;
        const float* Wol = woR + (size_t)l * DD * DD;

        if (l > 0)
            gemm_tf32<false, false, true><<<gQKV, 256, GEMM_SMEM>>>(
                xr, wqkv + (size_t)l * QKVW * DD, bqkv + l * QKVW, qb, kv,
                n, DD, QKVW, DD);

        attn_csr<<<(n * 32 + 255) / 256, 256>>>(qb, kv, off, esrc, p, agg, n);

        gemm_tf32<false, false, false><<<gD, 256, GEMM_SMEM>>>(
            agg, Wol, bo + l * DD, tb, nullptr, n, DD, DD, 0);

        bn_stats<<<256, DD>>>(xinExact, tb, part, n);
        bn_finalize<<<1, DD>>>(part, mu, rs, 1.f / (float)n);
        bn_apply<<<nDblocks, 256>>>(xinExact, tb, mu, rs,
                                    g1 + l * DD, be1 + l * DD, x, xr, n);

        gemm_tf32<true, true, true><<<gF, 256, GEMM_SMEM>>>(
            xr, W1l, b1 + l * FF, ff, nullptr, n, DD, FF, 0);
        gemm_tf32<false, false, false><<<gD, 256, GEMM_SMEM>>>(
            ff, W2l, b2 + l * DD, tb, nullptr, n, FF, DD, 0);

        bn_stats<<<256, DD>>>(x, tb, part, n);
        bn_finalize<<<1, DD>>>(part, mu, rs, 1.f / (float)n);
        bn_apply<<<nDblocks, 256>>>(x, tb, mu, rs,
                                    g2 + l * DD, be2 + l * DD, x, xr, n);

        xinExact = x;
    }

    layernorm_k<<<n, 128>>>(x, lng, lnb, outp);
}

// round 13
// speedup vs baseline: 2.4630x; 1.8590x over previous
#include <cuda_runtime.h>
#include <cuda_fp16.h>
#include <math.h>
#include <stdint.h>

// Problem constants (fixed by the reference generator)
#define NN   20000
#define DD   512
#define HH   8
#define DHH  64
#define FF   2048
#define LLAY 2
#define EE   320000
#define QKVW 1536   // packed q|k|v projection width

// half2-pair permutation within 8-half2 (16-half) groups:
// stored order [p0,p4,p1,p5,p2,p6,p3,p7] so fragment pair (c, c+4) is contiguous.
#define PERM8(k)  ((((k) & 3) << 1) | (((k) >> 2) & 1))
#define IPERM8(p) ((((p) & 1) << 2) | (((p) & 7) >> 1))

// ---------------------------------------------------------------------------
// Scratch (device globals: alloc-free rule)
// ---------------------------------------------------------------------------
__device__ __half g_qb  [NN * DD];        // q rows (fp16, permuted)
__device__ __half g_kv  [NN * 2 * DD];    // k|v rows (fp16, permuted)
__device__ __half g_agg [NN * DD];        // attn output (fp16, permuted)
__device__ float  g_t   [NN * DD];        // Wo / FF2 output (fp32, original)
__device__ float  g_x   [NN * DD];        // exact activations (fp32, original)
__device__ __half g_xr  [NN * DD];        // fp16+permuted activations (GEMM A)
__device__ __half g_srctf[NN * DD];       // fp16+permuted src
__device__ __half g_ff  [NN * FF];        // FF1 output (fp16, permuted)
__device__ float  g_p   [EE * HH];
__device__ float  g_part[256 * 1024];     // BN partial sums
__device__ float  g_mu  [DD];
__device__ float  g_rs  [DD];
__device__ __half g_wqkv[LLAY * QKVW * DD];   // packed fp16 permuted (Wq*0.125)
__device__ float  g_bqkv[LLAY * QKVW];
__device__ __half g_woR [LLAY * DD * DD];
__device__ __half g_w1R [LLAY * FF * DD];
__device__ __half g_w2R [LLAY * DD * FF];
__device__ int g_cnt [NN + 1];
__device__ int g_off [NN + 1];
__device__ int g_pos [NN];
__device__ int g_esrc[EE];

// ---------------------------------------------------------------------------
// helpers
// ---------------------------------------------------------------------------
__device__ __forceinline__ uint32_t smem_u32(const void* p) {
    uint32_t a;
    asm("{ .reg .u64 t; cvta.to.shared.u64 t, %1; cvt.u32.u64 %0, t; }"
        : "=r"(a) : "l"(p));
    return a;
}
__device__ __forceinline__ void cp16(uint32_t dst, const void* src, int szbytes) {
    asm volatile("cp.async.cg.shared.global [%0], [%1], 16, %2;"
                 :: "r"(dst), "l"(src), "r"(szbytes) : "memory");
}
#define CP_COMMIT() asm volatile("cp.async.commit_group;" ::: "memory")
#define CP_WAIT(n)  asm volatile("cp.async.wait_group %0;" :: "n"(n) : "memory")

// ---------------------------------------------------------------------------
// Utility kernels
// ---------------------------------------------------------------------------
__global__ void fill_i(int* __restrict__ p, int v, int n) {
    int i = blockIdx.x * blockDim.x + threadIdx.x;
    if (i < n) p[i] = v;
}
// fp16 + half2-permuted copy; n2 = element count / 2 (row widths % 16 == 0)
__global__ void round_copy_perm_h(const float* __restrict__ in,
                                  __half2* __restrict__ out, int n2)
{
    int i = blockIdx.x * blockDim.x + threadIdx.x;
    if (i >= n2) return;
    int sp = (i & ~7) | IPERM8(i & 7);
    out[i] = __floats2half2_rn(in[2 * sp], in[2 * sp + 1]);
}

// ---------------------------------------------------------------------------
// Weight packing (fp16 + permuted): r<512: Wq*0.125 | <1024: Wk | else Wv
// ---------------------------------------------------------------------------
__global__ void pack_qkv_w(const float* __restrict__ Wq, const float* __restrict__ Wk,
                           const float* __restrict__ Wv, __half2* __restrict__ wout)
{
    int idx = blockIdx.x * blockDim.x + threadIdx.x;       // half2 index
    const int total2 = LLAY * QKVW * DD / 2;
    if (idx >= total2) return;
    const int row2 = DD / 2;                               // half2 per row
    int l = idx / (QKVW * row2);
    int rem = idx % (QKVW * row2);
    int r = rem / row2, c2 = rem % row2;
    int sp = (c2 & ~7) | IPERM8(c2 & 7);
    int c0 = 2 * sp, c1 = 2 * sp + 1;
    float v0, v1;
    if (r < 512) {
        const float* W = Wq + (size_t)l * DD * DD + (size_t)r * DD;
        v0 = W[c0] * 0.125f; v1 = W[c1] * 0.125f;
    } else if (r < 1024) {
        const float* W = Wk + (size_t)l * DD * DD + (size_t)(r - 512) * DD;
        v0 = W[c0]; v1 = W[c1];
    } else {
        const float* W = Wv + (size_t)l * DD * DD + (size_t)(r - 1024) * DD;
        v0 = W[c0]; v1 = W[c1];
    }
    wout[idx] = __floats2half2_rn(v0, v1);
}
__global__ void pack_qkv_b(const float* __restrict__ bq, float* __restrict__ bout)
{
    int idx = blockIdx.x * blockDim.x + threadIdx.x;
    if (idx >= LLAY * QKVW) return;
    int l = idx / QKVW, r = idx % QKVW;
    bout[idx] = (r < 512) ? bq[l * DD + r] * 0.125f : 0.f;
}

// ---------------------------------------------------------------------------
// FP16 tensor-core GEMM (mma.sync m16n8k16), cp.async 3-stage pipeline +
// double-buffered fragment (ks) pipeline. All operands fp16 (pre-rounded) and
// half2-permuted in gmem. K counted in ELEMENTS (halves); k-tile = 64.
// PERM=1: output written fp16 half2-permuted (Cq/Ckv are __half*).
// PERM=0: output fp32 original layout (Cq is float*).
// ---------------------------------------------------------------------------
#define STAGE_U (128 * 32)                                 // uint32 per stage
#define GEMM_SMEM (6 * STAGE_U * (int)sizeof(uint32_t))    // 98304 B

template <bool RELU, bool PERM>
__global__ void __launch_bounds__(256, 2)
gemm_f16(const __half* __restrict__ A, const __half* __restrict__ W,
         const float* __restrict__ bias, void* __restrict__ CqV,
         void* __restrict__ CkvV, int M, int K, int Nout, int split)
{
    extern __shared__ uint32_t smemu[];
    uint32_t* AsB = smemu;                 // [3][128][32] uint32 (=half2)
    uint32_t* BsB = smemu + 3 * STAGE_U;
    const uint32_t AsAddr = smem_u32(AsB);
    const uint32_t BsAddr = smem_u32(BsB);

    const int tid  = threadIdx.x;
    const int lane = tid & 31;
    const int warp = tid >> 5;
    const int wm   = warp >> 2;
    const int wn   = warp & 3;
    const int g    = lane >> 2;
    const int c    = lane & 3;
    const int rowBase = blockIdx.y * 128;
    const int colBase = blockIdx.x * 128;

    // output routing
    char* Cb;
    int NoutB, colB;
    if (split > 0 && colBase >= split) {
        Cb = (char*)CkvV; NoutB = Nout - split; colB = colBase - split;
    } else if (split > 0) {
        Cb = (char*)CqV;  NoutB = split;        colB = colBase;
    } else {
        Cb = (char*)CqV;  NoutB = Nout;         colB = colBase;
    }

    float acc[4][4][4];
#pragma unroll
    for (int mt = 0; mt < 4; mt++)
#pragma unroll
        for (int nt = 0; nt < 4; nt++)
#pragma unroll
            for (int i = 0; i < 4; i++) acc[mt][nt][i] = 0.f;

    // tile loader: k-tile = 64 halves = 128 B/row; 8 quads of 16B per row
    auto issue = [&](int kt) {
        const int k0 = kt << 6;
        const int st = kt % 3;
        const uint32_t Ad = AsAddr + (uint32_t)(st * STAGE_U) * 4u;
        const uint32_t Bd = BsAddr + (uint32_t)(st * STAGE_U) * 4u;
#pragma unroll
        for (int i = 0; i < 4; i++) {
            int li = tid + i * 256;
            int r  = li >> 3;
            int q  = li & 7;
            int qs = q ^ ((r & 3) << 1);
            int ar = rowBase + r;
            int sz = (ar < M) ? 16 : 0;
            int arc = (ar < M) ? ar : (M - 1);
            cp16(Ad + (uint32_t)(r * 32 + qs * 4) * 4u,
                 A + (size_t)arc * K + k0 + q * 8, sz);
            cp16(Bd + (uint32_t)(r * 32 + qs * 4) * 4u,
                 W + (size_t)(colBase + r) * K + k0 + q * 8, 16);
        }
        CP_COMMIT();
    };

    const int NT = K >> 6;
    issue(0);
    issue(1);

    const int swz = (g & 3) << 2;

    uint32_t afb[2][4][4];
    uint32_t bfb[2][4][2];

    for (int kt = 0; kt < NT; kt++) {
        if (kt + 1 < NT) { CP_WAIT(1); } else { CP_WAIT(0); }
        __syncthreads();
        if (kt + 2 < NT) issue(kt + 2);

        const uint32_t* As = AsB + (kt % 3) * STAGE_U;
        const uint32_t* Bs = BsB + (kt % 3) * STAGE_U;

        auto loadFrag = [&](int ks, uint32_t af[4][4], uint32_t bf[4][2]) {
            const int chunk = (ks * 4 + c) ^ swz;
#pragma unroll
            for (int mt = 0; mt < 4; mt++) {
                int r0 = wm * 64 + mt * 16 + g;
                uint2 aLo = *(const uint2*)&As[r0 * 32 + chunk * 2];
                uint2 aHi = *(const uint2*)&As[(r0 + 8) * 32 + chunk * 2];
                af[mt][0] = aLo.x;   // row g,    k[2c,2c+1]
                af[mt][1] = aHi.x;   // row g+8,  k[2c,2c+1]
                af[mt][2] = aLo.y;   // row g,    k[2c+8,2c+9]
                af[mt][3] = aHi.y;   // row g+8,  k[2c+8,2c+9]
            }
#pragma unroll
            for (int nt = 0; nt < 4; nt++) {
                int n0 = wn * 32 + nt * 8 + g;
                uint2 b = *(const uint2*)&Bs[n0 * 32 + chunk * 2];
                bf[nt][0] = b.x;
                bf[nt][1] = b.y;
            }
        };

        loadFrag(0, afb[0], bfb[0]);
#pragma unroll
        for (int ks = 0; ks < 4; ks++) {
            const int cur = ks & 1;
            if (ks < 3) loadFrag(ks + 1, afb[cur ^ 1], bfb[cur ^ 1]);
#pragma unroll
            for (int mt = 0; mt < 4; mt++)
#pragma unroll
                for (int nt = 0; nt < 4; nt++)
                    asm volatile(
                        "mma.sync.aligned.m16n8k16.row.col.f32.f16.f16.f32 "
                        "{%0,%1,%2,%3}, {%4,%5,%6,%7}, {%8,%9}, {%0,%1,%2,%3};"
                        : "+f"(acc[mt][nt][0]), "+f"(acc[mt][nt][1]),
                          "+f"(acc[mt][nt][2]), "+f"(acc[mt][nt][3])
                        : "r"(afb[cur][mt][0]), "r"(afb[cur][mt][1]),
                          "r"(afb[cur][mt][2]), "r"(afb[cur][mt][3]),
                          "r"(bfb[cur][nt][0]), "r"(bfb[cur][nt][1]));
        }
    }

    // Epilogue
#pragma unroll
    for (int mt = 0; mt < 4; mt++) {
        int r0 = rowBase + wm * 64 + mt * 16 + g;
        int r1 = r0 + 8;
#pragma unroll
        for (int nt = 0; nt < 4; nt++) {
            int colRel = wn * 32 + nt * 8 + c * 2;
            float2 bb = *(const float2*)(bias + colBase + colRel);
            float v0 = acc[mt][nt][0] + bb.x;
            float v1 = acc[mt][nt][1] + bb.y;
            float v2 = acc[mt][nt][2] + bb.x;
            float v3 = acc[mt][nt][3] + bb.y;
            if (RELU) {
                v0 = fmaxf(v0, 0.f); v1 = fmaxf(v1, 0.f);
                v2 = fmaxf(v2, 0.f); v3 = fmaxf(v3, 0.f);
            }
            int col = colB + colRel;
            if (PERM) {
                // fp16 output, half2-permuted: pair (col, col+1) = one half2
                int c2 = col >> 1;
                int p2 = (c2 & ~7) | PERM8(c2 & 7);
                __half2* Ch = (__half2*)Cb;
                int stride2 = NoutB >> 1;
                if (r0 < M) Ch[(size_t)r0 * stride2 + p2] = __floats2half2_rn(v0, v1);
                if (r1 < M) Ch[(size_t)r1 * stride2 + p2] = __floats2half2_rn(v2, v3);
            } else {
                float* Cf = (float*)Cb;
                if (r0 < M) *(float2*)(Cf + (size_t)r0 * NoutB + col) = make_float2(v0, v1);
                if (r1 < M) *(float2*)(Cf + (size_t)r1 * NoutB + col) = make_float2(v2, v3);
            }
        }
    }
}

// ---------------------------------------------------------------------------
// CSR build
// ---------------------------------------------------------------------------
__global__ void csr_hist(const int* __restrict__ tgtI, int* __restrict__ cnt, int E)
{
    int e = blockIdx.x * blockDim.x + threadIdx.x;
    if (e < E) atomicAdd(&cnt[tgtI[e]], 1);
}

__global__ void __launch_bounds__(1024)
csr_scan(const int* __restrict__ cnt, int* __restrict__ off, int* __restrict__ pos, int n)
{
    __shared__ int part[1024];
    const int t = threadIdx.x;
    const int CH = (n + 1023) / 1024;
    int vals[32];
    int base = t * CH;
    int local = 0;
    for (int i = 0; i < CH; i++) {
        int e = base + i;
        int v = (e < n) ? cnt[e] : 0;
        vals[i] = v;
        local += v;
    }
    part[t] = local;
    __syncthreads();
    for (int d = 1; d < 1024; d <<= 1) {
        int v = (t >= d) ? part[t - d] : 0;
        __syncthreads();
        part[t] += v;
        __syncthreads();
    }
    int run = (t > 0) ? part[t - 1] : 0;
    for (int i = 0; i < CH; i++) {
        int e = base + i;
        if (e < n) { off[e] = run; pos[e] = run; run += vals[i]; }
    }
    if (t == 1023) off[n] = part[1023];
}

__global__ void csr_scatter(const int* __restrict__ srcI, const int* __restrict__ tgtI,
                            int* __restrict__ pos, int* __restrict__ esrc, int E)
{
    int e = blockIdx.x * blockDim.x + threadIdx.x;
    if (e >= E) return;
    int slot = atomicAdd(&pos[tgtI[e]], 1);
    esrc[slot] = srcI[e];
}

// ---------------------------------------------------------------------------
// Attention over CSR (fp16 permuted space; permutation stays within heads):
// one warp per target node, two-pass, pipelined gathers, fp32 math.
// Lane owns 16 halves = two uint4 loads per row segment.
// ---------------------------------------------------------------------------
__device__ __forceinline__ void h8_to_f(uint4 u, float* f) {
    float2 a = __half22float2(*(__half2*)&u.x);
    float2 b = __half22float2(*(__half2*)&u.y);
    float2 cc = __half22float2(*(__half2*)&u.z);
    float2 d = __half22float2(*(__half2*)&u.w);
    f[0] = a.x; f[1] = a.y; f[2] = b.x; f[3] = b.y;
    f[4] = cc.x; f[5] = cc.y; f[6] = d.x; f[7] = d.y;
}

__global__ void __launch_bounds__(256)
attn_csr(const __half* __restrict__ qb, const __half* __restrict__ kv,
         const int* __restrict__ off, const int* __restrict__ esrc,
         float* __restrict__ p, __half* __restrict__ agg, int n)
{
    int node = (blockIdx.x * blockDim.x + threadIdx.x) >> 5;
    int lane = threadIdx.x & 31;
    if (node >= n) return;
    const int start = off[node];
    const int end   = off[node + 1];
    const int h     = lane >> 2;

    float qf[16];
    {
        const uint4* qr = (const uint4*)(qb + (size_t)node * DD) + lane * 2;
        h8_to_f(qr[0], qf);
        h8_to_f(qr[1], qf + 8);
    }

    float hmax = -INFINITY;
    if (start < end) {
        uint4 ka, kb;
        {
            const uint4* kr = (const uint4*)(kv + (size_t)esrc[start] * 1024) + lane * 2;
            ka = kr[0]; kb = kr[1];
        }
        for (int s = start; s < end; s++) {
            uint4 na, nb;
            if (s + 1 < end) {
                const uint4* nr = (const uint4*)(kv + (size_t)esrc[s + 1] * 1024) + lane * 2;
                na = nr[0]; nb = nr[1];
            }
            float kf[16];
            h8_to_f(ka, kf);
            h8_to_f(kb, kf + 8);
            float d = 0.f;
#pragma unroll
            for (int i = 0; i < 16; i++) d = fmaf(qf[i], kf[i], d);
            d += __shfl_xor_sync(0xffffffffu, d, 1);
            d += __shfl_xor_sync(0xffffffffu, d, 2);
            if ((lane & 3) == 0) p[(size_t)s * HH + h] = d;
            hmax = fmaxf(hmax, d);
            if (s + 1 < end) { ka = na; kb = nb; }
        }
    }

    float acc[16];
#pragma unroll
    for (int i = 0; i < 16; i++) acc[i] = 0.f;
    float hsum = 0.f;

    if (start < end) {
        uint4 va, vb;
        {
            const uint4* vr = (const uint4*)(kv + (size_t)esrc[start] * 1024 + 512) + lane * 2;
            va = vr[0]; vb = vr[1];
        }
        float dcur = p[(size_t)start * HH + h];
        for (int s = start; s < end; s++) {
            uint4 na, nb;
            float dnxt;
            if (s + 1 < end) {
                const uint4* nr = (const uint4*)(kv + (size_t)esrc[s + 1] * 1024 + 512) + lane * 2;
                na = nr[0]; nb = nr[1];
                dnxt = p[(size_t)(s + 1) * HH + h];
            }
            float vf[16];
            h8_to_f(va, vf);
            h8_to_f(vb, vf + 8);
            float w = expf(dcur - hmax);
            hsum += w;
#pragma unroll
            for (int i = 0; i < 16; i++) acc[i] = fmaf(w, vf[i], acc[i]);
            if (s + 1 < end) { va = na; vb = nb; dcur = dnxt; }
        }
    }

    float inv = 1.f / (hsum + 1e-16f);
    uint4 o[2];
    __half2* oh = (__half2*)o;
#pragma unroll
    for (int i = 0; i < 8; i++)
        oh[i] = __floats2half2_rn(acc[2 * i] * inv, acc[2 * i + 1] * inv);
    uint4* ag = (uint4*)(agg + (size_t)node * DD) + lane * 2;
    ag[0] = o[0];
    ag[1] = o[1];
}

// ---------------------------------------------------------------------------
// BatchNorm over node dimension on z = a + b (residual fused); partials.
// ---------------------------------------------------------------------------
__global__ void bn_stats(const float* __restrict__ a, const float* __restrict__ b,
                         float* __restrict__ part, int n)
{
    int j = threadIdx.x;
    int blk = blockIdx.x;
    float sum = 0.f, sq = 0.f;
    for (int i = blk; i < n; i += 256) {
        float z = a[(size_t)i * DD + j] + b[(size_t)i * DD + j];
        sum += z; sq += z * z;
    }
    part[blk * 1024 + j]       = sum;
    part[blk * 1024 + 512 + j] = sq;
}

__global__ void bn_finalize(const float* __restrict__ part,
                            float* __restrict__ mu, float* __restrict__ rs, float invn)
{
    int j = threadIdx.x;
    float s = 0.f, q = 0.f;
    for (int b = 0; b < 256; b++) {
        s += part[b * 1024 + j];
        q += part[b * 1024 + 512 + j];
    }
    float m = s * invn;
    float var = q * invn - m * m;
    mu[j] = m;
    rs[j] = rsqrtf(var + 1e-5f);
}

// exact fp32 out (original space) + fp16 half2-permuted outr (GEMM A path)
__global__ void bn_apply(const float* __restrict__ a, const float* __restrict__ b,
                         const float* __restrict__ mu, const float* __restrict__ rs,
                         const float* __restrict__ g, const float* __restrict__ beta,
                         float* __restrict__ out, __half* __restrict__ outr, int n)
{
    // one thread per half2 pair: computes 2 adjacent elements
    int i2 = blockIdx.x * blockDim.x + threadIdx.x;
    if (i2 >= n * (DD / 2)) return;
    int row = i2 / (DD / 2);
    int c2  = i2 % (DD / 2);
    int j0 = 2 * c2, j1 = j0 + 1;
    size_t base = (size_t)row * DD;
    float z0 = a[base + j0] + b[base + j0];
    float z1 = a[base + j1] + b[base + j1];
    float o0 = (z0 - mu[j0]) * rs[j0] * g[j0] + beta[j0];
    float o1 = (z1 - mu[j1]) * rs[j1] * g[j1] + beta[j1];
    out[base + j0] = o0;
    out[base + j1] = o1;
    int p2 = (c2 & ~7) | PERM8(c2 & 7);
    *(__half2*)(outr + base + 2 * p2) = __floats2half2_rn(o0, o1);
}

// ---------------------------------------------------------------------------
// Final per-row LayerNorm  (128 threads/row, 4 floats each)
// ---------------------------------------------------------------------------
__global__ void layernorm_k(const float* __restrict__ x, const float* __restrict__ g,
                            const float* __restrict__ b, float* __restrict__ out)
{
    int row = blockIdx.x;
    int t = threadIdx.x;
    const float4* xr = (const float4*)(x + (size_t)row * DD);
    float4 v = xr[t];
    float sum = v.x + v.y + v.z + v.w;
    float sq  = v.x * v.x + v.y * v.y + v.z * v.z + v.w * v.w;

#pragma unroll
    for (int o = 16; o > 0; o >>= 1) {
        sum += __shfl_xor_sync(0xffffffffu, sum, o);
        sq  += __shfl_xor_sync(0xffffffffu, sq, o);
    }
    __shared__ float sa[4], sb[4];
    int w = t >> 5, l = t & 31;
    if (l == 0) { sa[w] = sum; sb[w] = sq; }
    __syncthreads();
    sum = sa[0] + sa[1] + sa[2] + sa[3];
    sq  = sb[0] + sb[1] + sb[2] + sb[3];

    float mu = sum * (1.f / DD);
    float var = sq * (1.f / DD) - mu * mu;
    float rs = rsqrtf(var + 1e-5f);

    const float4* g4 = (const float4*)g;
    const float4* b4 = (const float4*)b;
    float4 gg = g4[t], bb = b4[t];
    float4 o;
    o.x = (v.x - mu) * rs * gg.x + bb.x;
    o.y = (v.y - mu) * rs * gg.y + bb.y;
    o.z = (v.z - mu) * rs * gg.z + bb.z;
    o.w = (v.w - mu) * rs * gg.w + bb.w;
    *(float4*)(out + (size_t)row * DD + t * 4) = o;
}

// ---------------------------------------------------------------------------
// Orchestration
// ---------------------------------------------------------------------------
extern "C" void kernel_launch(void* const* d_in, const int* in_sizes, int n_in,
                              void* d_out, int out_size)
{
    const float* src = (const float*)d_in[0];
    const int*   ei  = (const int*)  d_in[1];
    const float* Wq  = (const float*)d_in[2];
    const float* bq  = (const float*)d_in[3];
    const float* Wk  = (const float*)d_in[4];
    const float* Wv  = (const float*)d_in[5];
    const float* Wo  = (const float*)d_in[6];
    const float* bo  = (const float*)d_in[7];
    const float* W1  = (const float*)d_in[8];
    const float* b1  = (const float*)d_in[9];
    const float* W2  = (const float*)d_in[10];
    const float* b2  = (const float*)d_in[11];
    const float* g1  = (const float*)d_in[12];
    const float* be1 = (const float*)d_in[13];
    const float* g2  = (const float*)d_in[14];
    const float* be2 = (const float*)d_in[15];
    const float* lng = (const float*)d_in[16];
    const float* lnb = (const float*)d_in[17];
    float* outp = (float*)d_out;

    const int n = in_sizes[0] / DD;
    const int E = in_sizes[1] / 2;
    const int* srcI = ei;
    const int* tgtI = ei + E;

    __half *qb, *kv, *agg, *xr, *srctf, *ff, *wqkv, *woR, *w1R, *w2R;
    float *tb, *x, *p, *part, *mu, *rs, *bqkv;
    int *cnt, *off, *pos, *esrc;
    cudaGetSymbolAddress((void**)&qb,    g_qb);
    cudaGetSymbolAddress((void**)&kv,    g_kv);
    cudaGetSymbolAddress((void**)&agg,   g_agg);
    cudaGetSymbolAddress((void**)&tb,    g_t);
    cudaGetSymbolAddress((void**)&x,     g_x);
    cudaGetSymbolAddress((void**)&xr,    g_xr);
    cudaGetSymbolAddress((void**)&srctf, g_srctf);
    cudaGetSymbolAddress((void**)&ff,    g_ff);
    cudaGetSymbolAddress((void**)&p,     g_p);
    cudaGetSymbolAddress((void**)&part,  g_part);
    cudaGetSymbolAddress((void**)&mu,    g_mu);
    cudaGetSymbolAddress((void**)&rs,    g_rs);
    cudaGetSymbolAddress((void**)&wqkv,  g_wqkv);
    cudaGetSymbolAddress((void**)&bqkv,  g_bqkv);
    cudaGetSymbolAddress((void**)&woR,   g_woR);
    cudaGetSymbolAddress((void**)&w1R,   g_w1R);
    cudaGetSymbolAddress((void**)&w2R,   g_w2R);
    cudaGetSymbolAddress((void**)&cnt,   g_cnt);
    cudaGetSymbolAddress((void**)&off,   g_off);
    cudaGetSymbolAddress((void**)&pos,   g_pos);
    cudaGetSymbolAddress((void**)&esrc,  g_esrc);

    cudaFuncSetAttribute((const void*)gemm_f16<false, true>,
                         cudaFuncAttributeMaxDynamicSharedMemorySize, GEMM_SMEM);
    cudaFuncSetAttribute((const void*)gemm_f16<false, false>,
                         cudaFuncAttributeMaxDynamicSharedMemorySize, GEMM_SMEM);
    cudaFuncSetAttribute((const void*)gemm_f16<true, true>,
                         cudaFuncAttributeMaxDynamicSharedMemorySize, GEMM_SMEM);

    const dim3 gQKV(QKVW / 128, (n + 127) / 128);
    const dim3 gD(DD / 128, (n + 127) / 128);
    const dim3 gF(FF / 128, (n + 127) / 128);
    const int nD2blocks = (n * DD / 2 + 255) / 256;

    // launches 0-2: packing + src convert; launch 3: QKV GEMM (ncu sample)
    pack_qkv_w<<<(LLAY * QKVW * DD / 2 + 255) / 256, 256>>>(Wq, Wk, Wv, (__half2*)wqkv);
    pack_qkv_b<<<(LLAY * QKVW + 255) / 256, 256>>>(bq, bqkv);
    round_copy_perm_h<<<nD2blocks, 256>>>(src, (__half2*)srctf, n * DD / 2);
    gemm_f16<false, true><<<gQKV, 256, GEMM_SMEM>>>(srctf, wqkv, bqkv,
                                                    qb, kv, n, DD, QKVW, DD);

    // fp16 weight copies + CSR build
    round_copy_perm_h<<<(LLAY * DD * DD / 2 + 255) / 256, 256>>>(Wo, (__half2*)woR, LLAY * DD * DD / 2);
    round_copy_perm_h<<<(LLAY * FF * DD / 2 + 255) / 256, 256>>>(W1, (__half2*)w1R, LLAY * FF * DD / 2);
    round_copy_perm_h<<<(LLAY * DD * FF / 2 + 255) / 256, 256>>>(W2, (__half2*)w2R, LLAY * DD * FF / 2);
    fill_i<<<(n + 1 + 255) / 256, 256>>>(cnt, 0, n + 1);
    csr_hist<<<(E + 255) / 256, 256>>>(tgtI, cnt, E);
    csr_scan<<<1, 1024>>>(cnt, off, pos, n);
    csr_scatter<<<(E + 255) / 256, 256>>>(srcI, tgtI, pos, esrc, E);

    const float* xinExact = src;

    for (int l = 0; l < LLAY; l++) {
        const __half* W1l = w1R + (size_t)l * FF * DD;
        const __half* W2l = w2R + (size_t)l * DD * FF;
        const __half* Wol = woR + (size_t)l * DD * DD;

        if (l > 0)
            gemm_f16<false, true><<<gQKV, 256, GEMM_SMEM>>>(
                xr, wqkv + (size_t)l * QKVW * DD, bqkv + l * QKVW, qb, kv,
                n, DD, QKVW, DD);

        attn_csr<<<(n * 32 + 255) / 256, 256>>>(qb, kv, off, esrc, p, agg, n);

        gemm_f16<false, false><<<gD, 256, GEMM_SMEM>>>(
            agg, Wol, bo + l * DD, tb, nullptr, n, DD, DD, 0);

        bn_stats<<<256, DD>>>(xinExact, tb, part, n);
        bn_finalize<<<1, DD>>>(part, mu, rs, 1.f / (float)n);
        bn_apply<<<nD2blocks, 256>>>(xinExact, tb, mu, rs,
                                     g1 + l * DD, be1 + l * DD, x, xr, n);

        gemm_f16<true, true><<<gF, 256, GEMM_SMEM>>>(
            xr, W1l, b1 + l * FF, ff, nullptr, n, DD, FF, 0);
        gemm_f16<false, false><<<gD, 256, GEMM_SMEM>>>(
            ff, W2l, b2 + l * DD, tb, nullptr, n, FF, DD, 0);

        bn_stats<<<256, DD>>>(x, tb, part, n);
        bn_finalize<<<1, DD>>>(part, mu, rs, 1.f / (float)n);
        bn_apply<<<nD2blocks, 256>>>(x, tb, mu, rs,
                                     g2 + l * DD, be2 + l * DD, x, xr, n);

        xinExact = x;
    }

    layernorm_k<<<n, 128>>>(x, lng, lnb, outp);
}